// round 1
// baseline (speedup 1.0000x reference)
#include <cuda_runtime.h>

// Shapes: B=16, C=512, H=W=32 -> S=1024, 32 groups (16 ch/group), 8 heads, D=64.
#define BB 16
#define CC 512
#define SS 1024
#define NG 32
#define CPG 16
#define NH 8
#define DK 64
#define QKVC 1536

// Scratch (allocation-free rule: __device__ globals)
static __device__ float g_h[BB * SS * CC];      // [b*S+s][C]   32 MB
static __device__ float g_qkv[BB * SS * QKVC];  // [b*S+s][3C]  96 MB
static __device__ float g_ao[BB * SS * CC];     // [b*S+s][h*64+d] 32 MB

// ---------------------------------------------------------------------------
// Kernel 1: GroupNorm over (16 ch x 1024 spatial) per (b, group), write h
// transposed to [B,S,C].
// ---------------------------------------------------------------------------
__global__ __launch_bounds__(256) void gn_kernel(const float* __restrict__ x,
                                                 const float* __restrict__ w,
                                                 const float* __restrict__ bgn) {
    const int b = blockIdx.x >> 5;
    const int g = blockIdx.x & 31;
    const float* xp = x + (size_t)(b * CC + g * CPG) * SS;
    const int t = threadIdx.x;

    float sum = 0.f, sq = 0.f;
    for (int i = t; i < CPG * SS; i += 256) {
        float v = xp[i];
        sum += v;
        sq = fmaf(v, v, sq);
    }
    __shared__ float s1[256], s2[256];
    s1[t] = sum; s2[t] = sq;
    __syncthreads();
    for (int o = 128; o > 0; o >>= 1) {
        if (t < o) { s1[t] += s1[t + o]; s2[t] += s2[t + o]; }
        __syncthreads();
    }
    __shared__ float mean_s, inv_s;
    if (t == 0) {
        const float n_inv = 1.f / (CPG * SS);
        float mean = s1[0] * n_inv;
        float var = s2[0] * n_inv - mean * mean;
        mean_s = mean;
        inv_s = rsqrtf(var + 1e-5f);
    }
    __syncthreads();
    const float mean = mean_s, inv = inv_s;

    // Write transposed: c_local = t & 15 is constant per thread (256 % 16 == 0)
    const int cl = t & 15;
    const int c = g * CPG + cl;
    const float wc = w[c] * inv;
    const float bc = bgn[c] - mean * wc;
    for (int i = t; i < CPG * SS; i += 256) {
        int s = i >> 4;
        float v = xp[(size_t)cl * SS + s];
        g_h[(size_t)(b * SS + s) * CC + c] = fmaf(v, wc, bc);
    }
}

// ---------------------------------------------------------------------------
// Kernel 2: QKV GEMM  C[M=16384, N=1536] = h @ proj_w^T + proj_b
// 64x64 block tile, 256 threads, 4x4 micro-tile, k-chunk 16 (k-major smem).
// ---------------------------------------------------------------------------
__global__ __launch_bounds__(256) void qkv_gemm_kernel(const float* __restrict__ W,
                                                       const float* __restrict__ bias) {
    __shared__ __align__(16) float As[16][68];
    __shared__ __align__(16) float Bs[16][68];
    const int n0 = blockIdx.x * 64;
    const int m0 = blockIdx.y * 64;
    const int t = threadIdx.x;
    const int tx = t & 15, ty = t >> 4;
    const int lm = t >> 2, lk = (t & 3) * 4;
    const float* Ap = g_h + (size_t)(m0 + lm) * CC + lk;
    const float* Wp = W + (size_t)(n0 + lm) * CC + lk;
    float acc[4][4] = {};

    for (int k0 = 0; k0 < CC; k0 += 16) {
        float4 av = *(const float4*)(Ap + k0);
        float4 bv = *(const float4*)(Wp + k0);
        __syncthreads();
        As[lk + 0][lm] = av.x; As[lk + 1][lm] = av.y;
        As[lk + 2][lm] = av.z; As[lk + 3][lm] = av.w;
        Bs[lk + 0][lm] = bv.x; Bs[lk + 1][lm] = bv.y;
        Bs[lk + 2][lm] = bv.z; Bs[lk + 3][lm] = bv.w;
        __syncthreads();
#pragma unroll
        for (int kk = 0; kk < 16; ++kk) {
            float4 a4 = *(const float4*)&As[kk][ty * 4];
            float4 b4 = *(const float4*)&Bs[kk][tx * 4];
            float am[4] = {a4.x, a4.y, a4.z, a4.w};
            float bn[4] = {b4.x, b4.y, b4.z, b4.w};
#pragma unroll
            for (int i = 0; i < 4; ++i)
#pragma unroll
                for (int j = 0; j < 4; ++j)
                    acc[i][j] = fmaf(am[i], bn[j], acc[i][j]);
        }
    }
    float4 bb = *(const float4*)&bias[n0 + tx * 4];
#pragma unroll
    for (int i = 0; i < 4; ++i) {
        float4 r = make_float4(acc[i][0] + bb.x, acc[i][1] + bb.y,
                               acc[i][2] + bb.z, acc[i][3] + bb.w);
        *(float4*)&g_qkv[(size_t)(m0 + ty * 4 + i) * QKVC + n0 + tx * 4] = r;
    }
}

// ---------------------------------------------------------------------------
// Kernel 3: flash-style attention, fp32.  One block per (64 query rows, b, h).
// S^T layout in smem (key-major) makes softmax column scans and P^T float4
// reads conflict-free.  Both q and k scales folded: S *= 1/8 (applied to Q).
// ---------------------------------------------------------------------------
#define ATT_SMEM_FLOATS (64 * 68 + 64 * 68 + 64 * 64 + 64 * 3 + 256)

__global__ __launch_bounds__(256) void attn_kernel() {
    extern __shared__ __align__(16) float sm[];
    float* Qs = sm;               // [d=64][q, stride 68]
    float* KV = Qs + 64 * 68;     // K: [d][j] (stride 68) then V: [j][d] (stride 68)
    float* Ss = KV + 64 * 68;     // [key=64][query=64]  (S^T, then P^T)
    float* m_s = Ss + 64 * 64;
    float* l_s = m_s + 64;
    float* al_s = l_s + 64;
    float* red = al_s + 64;       // [4][64]

    const int i0 = blockIdx.x * 64;
    const int bh = blockIdx.y;
    const int b = bh >> 3, h = bh & 7;
    const int t = threadIdx.x;
    const int tx = t & 15, ty = t >> 4;
    const int ld_d = t & 63, ld_r = t >> 6;
    const int qq = t & 63, seg = t >> 6;

    const float* qkbase = g_qkv + (size_t)b * SS * QKVC + h * 192;

    // Load Q tile (transposed to d-major), pre-scaled by 1/8
    {
        const float* qp = qkbase + (size_t)(i0 + ld_r) * QKVC + ld_d;
#pragma unroll
        for (int r = 0; r < 16; ++r)
            Qs[ld_d * 68 + (r * 4 + ld_r)] = qp[(size_t)r * 4 * QKVC] * 0.125f;
    }
    if (t < 64) { m_s[t] = -1e30f; l_s[t] = 0.f; }
    float o[4][4] = {};
    __syncthreads();

    for (int j0 = 0; j0 < SS; j0 += 64) {
        // K tile -> KV (d-major, transposed store)
        {
            const float* kp = qkbase + (size_t)(j0 + ld_r) * QKVC + DK + ld_d;
#pragma unroll
            for (int r = 0; r < 16; ++r)
                KV[ld_d * 68 + (r * 4 + ld_r)] = kp[(size_t)r * 4 * QKVC];
        }
        __syncthreads();

        // S^T[key][query] = K Q^T
        float sa[4][4] = {};
#pragma unroll 16
        for (int d = 0; d < 64; ++d) {
            float4 k4 = *(const float4*)&KV[d * 68 + ty * 4];
            float4 q4 = *(const float4*)&Qs[d * 68 + tx * 4];
            float kr[4] = {k4.x, k4.y, k4.z, k4.w};
            float qr[4] = {q4.x, q4.y, q4.z, q4.w};
#pragma unroll
            for (int i = 0; i < 4; ++i)
#pragma unroll
                for (int j = 0; j < 4; ++j)
                    sa[i][j] = fmaf(kr[i], qr[j], sa[i][j]);
        }
#pragma unroll
        for (int i = 0; i < 4; ++i)
#pragma unroll
            for (int j = 0; j < 4; ++j)
                Ss[(ty * 4 + i) * 64 + tx * 4 + j] = sa[i][j];
        __syncthreads();

        // V tile -> KV (j-major, natural store); overlap with max scan
        {
            const float* vp = qkbase + (size_t)(j0 + ld_r) * QKVC + 2 * DK + ld_d;
#pragma unroll
            for (int r = 0; r < 16; ++r)
                KV[(r * 4 + ld_r) * 68 + ld_d] = vp[(size_t)r * 4 * QKVC];
        }
        float lmax = -1e30f;
#pragma unroll
        for (int k = 0; k < 16; ++k)
            lmax = fmaxf(lmax, Ss[(seg * 16 + k) * 64 + qq]);
        red[seg * 64 + qq] = lmax;
        __syncthreads();

        float tmax = fmaxf(fmaxf(red[qq], red[64 + qq]),
                           fmaxf(red[128 + qq], red[192 + qq]));
        float m_old = m_s[qq];
        float m_new = fmaxf(m_old, tmax);
        __syncthreads();
        if (seg == 0) { m_s[qq] = m_new; al_s[qq] = __expf(m_old - m_new); }

        float lsum = 0.f;
#pragma unroll
        for (int k = 0; k < 16; ++k) {
            float p = __expf(Ss[(seg * 16 + k) * 64 + qq] - m_new);
            Ss[(seg * 16 + k) * 64 + qq] = p;
            lsum += p;
        }
        red[seg * 64 + qq] = lsum;
        __syncthreads();
        if (seg == 0)
            l_s[qq] = fmaf(l_s[qq], al_s[qq],
                           red[qq] + red[64 + qq] + red[128 + qq] + red[192 + qq]);

        float ar[4] = {al_s[ty * 4], al_s[ty * 4 + 1],
                       al_s[ty * 4 + 2], al_s[ty * 4 + 3]};
#pragma unroll
        for (int i = 0; i < 4; ++i)
#pragma unroll
            for (int j = 0; j < 4; ++j)
                o[i][j] *= ar[i];

        // O += P^T-rows x V
#pragma unroll 16
        for (int j = 0; j < 64; ++j) {
            float4 p4 = *(const float4*)&Ss[j * 64 + ty * 4];
            float4 v4 = *(const float4*)&KV[j * 68 + tx * 4];
            float pr[4] = {p4.x, p4.y, p4.z, p4.w};
            float vr[4] = {v4.x, v4.y, v4.z, v4.w};
#pragma unroll
            for (int i = 0; i < 4; ++i)
#pragma unroll
                for (int jj = 0; jj < 4; ++jj)
                    o[i][jj] = fmaf(pr[i], vr[jj], o[i][jj]);
        }
        __syncthreads();
    }

#pragma unroll
    for (int i = 0; i < 4; ++i) {
        float inv = 1.f / l_s[ty * 4 + i];
        float4 r = make_float4(o[i][0] * inv, o[i][1] * inv,
                               o[i][2] * inv, o[i][3] * inv);
        *(float4*)&g_ao[(size_t)(b * SS + i0 + ty * 4 + i) * CC + h * DK + tx * 4] = r;
    }
}

// ---------------------------------------------------------------------------
// Kernel 4: out projection + bias + residual + transpose back to [B,C,H,W].
// ---------------------------------------------------------------------------
__global__ __launch_bounds__(256) void out_gemm_kernel(const float* __restrict__ W,
                                                       const float* __restrict__ bias,
                                                       const float* __restrict__ x,
                                                       float* __restrict__ out) {
    __shared__ __align__(16) float As[16][68];
    __shared__ __align__(16) float Bs[16][68];
    __shared__ float Cs[64][65];
    const int n0 = blockIdx.x * 64;
    const int m0 = blockIdx.y * 64;
    const int t = threadIdx.x;
    const int tx = t & 15, ty = t >> 4;
    const int lm = t >> 2, lk = (t & 3) * 4;
    const float* Ap = g_ao + (size_t)(m0 + lm) * CC + lk;
    const float* Wp = W + (size_t)(n0 + lm) * CC + lk;
    float acc[4][4] = {};

    for (int k0 = 0; k0 < CC; k0 += 16) {
        float4 av = *(const float4*)(Ap + k0);
        float4 bv = *(const float4*)(Wp + k0);
        __syncthreads();
        As[lk + 0][lm] = av.x; As[lk + 1][lm] = av.y;
        As[lk + 2][lm] = av.z; As[lk + 3][lm] = av.w;
        Bs[lk + 0][lm] = bv.x; Bs[lk + 1][lm] = bv.y;
        Bs[lk + 2][lm] = bv.z; Bs[lk + 3][lm] = bv.w;
        __syncthreads();
#pragma unroll
        for (int kk = 0; kk < 16; ++kk) {
            float4 a4 = *(const float4*)&As[kk][ty * 4];
            float4 b4 = *(const float4*)&Bs[kk][tx * 4];
            float am[4] = {a4.x, a4.y, a4.z, a4.w};
            float bn[4] = {b4.x, b4.y, b4.z, b4.w};
#pragma unroll
            for (int i = 0; i < 4; ++i)
#pragma unroll
                for (int j = 0; j < 4; ++j)
                    acc[i][j] = fmaf(am[i], bn[j], acc[i][j]);
        }
    }

    // Stage tile in smem transposed, then write coalesced along s + residual
#pragma unroll
    for (int i = 0; i < 4; ++i)
#pragma unroll
        for (int j = 0; j < 4; ++j)
            Cs[tx * 4 + j][ty * 4 + i] = acc[i][j];
    __syncthreads();

    const int b = m0 >> 10;
    const int s0 = m0 & 1023;
#pragma unroll
    for (int it = 0; it < 16; ++it) {
        int idx = it * 256 + t;
        int nl = idx >> 6, sl = idx & 63;
        int c = n0 + nl;
        size_t gi = (size_t)(b * CC + c) * SS + s0 + sl;
        out[gi] = Cs[nl][sl] + bias[c] + x[gi];
    }
}

// ---------------------------------------------------------------------------
extern "C" void kernel_launch(void* const* d_in, const int* in_sizes, int n_in,
                              void* d_out, int out_size) {
    const float* x = (const float*)d_in[0];
    const float* gn_w = (const float*)d_in[1];
    const float* gn_b = (const float*)d_in[2];
    const float* proj_w = (const float*)d_in[3];
    const float* proj_b = (const float*)d_in[4];
    const float* out_w = (const float*)d_in[5];
    const float* out_b = (const float*)d_in[6];
    float* out = (float*)d_out;

    gn_kernel<<<BB * NG, 256>>>(x, gn_w, gn_b);
    qkv_gemm_kernel<<<dim3(QKVC / 64, BB * SS / 64), 256>>>(proj_w, proj_b);

    cudaFuncSetAttribute(attn_kernel, cudaFuncAttributeMaxDynamicSharedMemorySize,
                         ATT_SMEM_FLOATS * (int)sizeof(float));
    attn_kernel<<<dim3(SS / 64, BB * NH), 256, ATT_SMEM_FLOATS * sizeof(float)>>>();

    out_gemm_kernel<<<dim3(CC / 64, BB * SS / 64), 256>>>(out_w, out_b, x, out);
}

// round 4
// speedup vs baseline: 1.7508x; 1.7508x over previous
#include <cuda_runtime.h>
#include <cuda_bf16.h>
#include <cstdint>

// Shapes: B=16, C=512, H=W=32 -> S=1024, 32 groups (16 ch/group), 8 heads, D=64.
#define BB 16
#define CC 512
#define SS 1024
#define NG 32
#define CPG 16
#define NH 8
#define DK 64
#define QKVC 1536

static __device__ float g_h[BB * SS * CC];      // [b*S+s][C]
static __device__ float g_qkv[BB * SS * QKVC];  // [b*S+s][3C]
static __device__ float g_ao[BB * SS * CC];     // [b*S+s][h*64+d]

// ============================================================================
// mma.sync / ldmatrix helpers (legacy tensor path, works on compute_103)
// ============================================================================
__device__ __forceinline__ uint32_t smem_u32(const void* p) {
    uint32_t a;
    asm("{ .reg .u64 t; cvta.to.shared.u64 t, %1; cvt.u32.u64 %0, t; }"
        : "=r"(a) : "l"(p));
    return a;
}

__device__ __forceinline__ void ldm_x4(uint32_t* r, uint32_t addr) {
    asm volatile("ldmatrix.sync.aligned.m8n8.x4.shared.b16 {%0,%1,%2,%3}, [%4];"
                 : "=r"(r[0]), "=r"(r[1]), "=r"(r[2]), "=r"(r[3]) : "r"(addr));
}

__device__ __forceinline__ void mma_bf16(float* c, const uint32_t* a, const uint32_t* b) {
    asm volatile(
        "mma.sync.aligned.m16n8k16.row.col.f32.bf16.bf16.f32 "
        "{%0,%1,%2,%3}, {%4,%5,%6,%7}, {%8,%9}, {%0,%1,%2,%3};"
        : "+f"(c[0]), "+f"(c[1]), "+f"(c[2]), "+f"(c[3])
        : "r"(a[0]), "r"(a[1]), "r"(a[2]), "r"(a[3]), "r"(b[0]), "r"(b[1]));
}

__device__ __forceinline__ uint32_t pack_bf2(__nv_bfloat16 a, __nv_bfloat16 b) {
    __nv_bfloat162 v = __halves2bfloat162(a, b);
    return *reinterpret_cast<uint32_t*>(&v);
}

// fp32x4 -> bf16 hi/lo split, 8B store each to hi/lo buffers at byte offset
__device__ __forceinline__ void cvt_st4(char* hi, char* lo, int off, float4 v) {
    __nv_bfloat16 hx = __float2bfloat16_rn(v.x);
    __nv_bfloat16 hy = __float2bfloat16_rn(v.y);
    __nv_bfloat16 hz = __float2bfloat16_rn(v.z);
    __nv_bfloat16 hw = __float2bfloat16_rn(v.w);
    __nv_bfloat16 lx = __float2bfloat16_rn(v.x - __bfloat162float(hx));
    __nv_bfloat16 ly = __float2bfloat16_rn(v.y - __bfloat162float(hy));
    __nv_bfloat16 lz = __float2bfloat16_rn(v.z - __bfloat162float(hz));
    __nv_bfloat16 lw = __float2bfloat16_rn(v.w - __bfloat162float(hw));
    *reinterpret_cast<uint2*>(hi + off) = make_uint2(pack_bf2(hx, hy), pack_bf2(hz, hw));
    *reinterpret_cast<uint2*>(lo + off) = make_uint2(pack_bf2(lx, ly), pack_bf2(lz, lw));
}

// ---------------------------------------------------------------------------
// Kernel 1: GroupNorm, write transposed to [B,S,C]
// ---------------------------------------------------------------------------
__global__ __launch_bounds__(256) void gn_kernel(const float* __restrict__ x,
                                                 const float* __restrict__ w,
                                                 const float* __restrict__ bgn) {
    const int b = blockIdx.x >> 5;
    const int g = blockIdx.x & 31;
    const float* xp = x + (size_t)(b * CC + g * CPG) * SS;
    const int t = threadIdx.x;

    float sum = 0.f, sq = 0.f;
    for (int i = t; i < CPG * SS; i += 256) {
        float v = xp[i];
        sum += v;
        sq = fmaf(v, v, sq);
    }
    __shared__ float s1[256], s2[256];
    s1[t] = sum; s2[t] = sq;
    __syncthreads();
    for (int o = 128; o > 0; o >>= 1) {
        if (t < o) { s1[t] += s1[t + o]; s2[t] += s2[t + o]; }
        __syncthreads();
    }
    __shared__ float mean_s, inv_s;
    if (t == 0) {
        const float n_inv = 1.f / (CPG * SS);
        float mean = s1[0] * n_inv;
        float var = s2[0] * n_inv - mean * mean;
        mean_s = mean;
        inv_s = rsqrtf(var + 1e-5f);
    }
    __syncthreads();
    const float mean = mean_s, inv = inv_s;

    const int cl = t & 15;
    const int c = g * CPG + cl;
    const float wc = w[c] * inv;
    const float bc = bgn[c] - mean * wc;
    for (int i = t; i < CPG * SS; i += 256) {
        int s = i >> 4;
        float v = xp[(size_t)cl * SS + s];
        g_h[(size_t)(b * SS + s) * CC + c] = fmaf(v, wc, bc);
    }
}

// ---------------------------------------------------------------------------
// Kernel 2: mma.sync GEMM (2x-bf16 split, 3-pass).  C[M,Ntot] = A @ W^T + epi
// CTA tile 128(M) x 64(N), 8 warps (4M x 2N, 32x32 each), K-chunk 32.
// MODE 0: +bias, row-major store.  MODE 1: +bias +residual, channel-major.
// ---------------------------------------------------------------------------
#define GP 40  // bf16 smem pitch for 32-wide K-chunks (80B rows)
#define G_AH 0
#define G_AL 10240
#define G_BH 20480
#define G_BL 25600
#define GEMM_SMEM 34816  // fp32 stage 128*68*4 overlaps all of the above

template <int MODE>
__global__ __launch_bounds__(256, 2) void mma_gemm(const float* __restrict__ A,
                                                   const float* __restrict__ W,
                                                   const float* __restrict__ bias,
                                                   const float* __restrict__ xres,
                                                   float* __restrict__ out,
                                                   int Ntot) {
    extern __shared__ __align__(16) char sm[];
    const uint32_t sb = smem_u32(sm);
    const int t = threadIdx.x, w = t >> 5, L = t & 31;
    const int n0 = blockIdx.x * 64;
    const int m0 = blockIdx.y * 128;
    const int wm = w >> 1, wn = w & 1;

    const int arow = L & 15, aseg = L >> 4;
    const int brow = ((L >> 4) << 3) + (L & 7), bcol = ((L >> 3) & 1) * 8;
    const int crow = L >> 2, ccol = (L & 3) * 2;

    const float* Ap = A + (size_t)m0 * CC;
    const float* Wp = W + (size_t)n0 * CC;
    float acc[2][4][4] = {};

    for (int kc = 0; kc < 16; ++kc) {
        const int k0 = kc * 32;
        __syncthreads();
#pragma unroll
        for (int i = 0; i < 4; ++i) {   // A: 128x32 fp32
            int f = t + 256 * i;
            int row = f >> 3, c4 = f & 7;
            float4 v = *(const float4*)(Ap + (size_t)row * CC + k0 + c4 * 4);
            cvt_st4(sm + G_AH, sm + G_AL, row * (GP * 2) + c4 * 8, v);
        }
#pragma unroll
        for (int i = 0; i < 2; ++i) {   // B: 64x32 fp32
            int f = t + 256 * i;
            int row = f >> 3, c4 = f & 7;
            float4 v = *(const float4*)(Wp + (size_t)row * CC + k0 + c4 * 4);
            cvt_st4(sm + G_BH, sm + G_BL, row * (GP * 2) + c4 * 8, v);
        }
        __syncthreads();

#pragma unroll
        for (int ks = 0; ks < 2; ++ks) {
            uint32_t ah[2][4], al[2][4], bh[2][4], bl[2][4];
#pragma unroll
            for (int mt = 0; mt < 2; ++mt) {
                uint32_t off = (uint32_t)(((wm * 32 + mt * 16 + arow) * GP +
                                           ks * 16 + aseg * 8) * 2);
                ldm_x4(ah[mt], sb + G_AH + off);
                ldm_x4(al[mt], sb + G_AL + off);
            }
#pragma unroll
            for (int nt = 0; nt < 2; ++nt) {
                uint32_t off = (uint32_t)(((wn * 32 + nt * 16 + brow) * GP +
                                           ks * 16 + bcol) * 2);
                ldm_x4(bh[nt], sb + G_BH + off);
                ldm_x4(bl[nt], sb + G_BL + off);
            }
#pragma unroll
            for (int mt = 0; mt < 2; ++mt)
#pragma unroll
                for (int n8 = 0; n8 < 4; ++n8) {
                    const uint32_t* bhp = &bh[n8 >> 1][(n8 & 1) * 2];
                    const uint32_t* blp = &bl[n8 >> 1][(n8 & 1) * 2];
                    mma_bf16(acc[mt][n8], ah[mt], bhp);
                    mma_bf16(acc[mt][n8], ah[mt], blp);
                    mma_bf16(acc[mt][n8], al[mt], bhp);
                }
        }
    }

    __syncthreads();
    float* stage = reinterpret_cast<float*>(sm);
    const int PITCH = (MODE == 0) ? 68 : 65;
#pragma unroll
    for (int mt = 0; mt < 2; ++mt)
#pragma unroll
        for (int n8 = 0; n8 < 4; ++n8) {
            int r = wm * 32 + mt * 16 + crow;
            int c = wn * 32 + n8 * 8 + ccol;
            stage[r * PITCH + c]           = acc[mt][n8][0];
            stage[r * PITCH + c + 1]       = acc[mt][n8][1];
            stage[(r + 8) * PITCH + c]     = acc[mt][n8][2];
            stage[(r + 8) * PITCH + c + 1] = acc[mt][n8][3];
        }
    __syncthreads();

    if (MODE == 0) {
#pragma unroll
        for (int i = 0; i < 8; ++i) {
            int f = t + 256 * i;
            int row = f >> 4, c4 = f & 15;
            float4 v = *(const float4*)&stage[row * 68 + c4 * 4];
            float4 bb = *(const float4*)&bias[n0 + c4 * 4];
            v.x += bb.x; v.y += bb.y; v.z += bb.z; v.w += bb.w;
            *(float4*)&out[(size_t)(m0 + row) * Ntot + n0 + c4 * 4] = v;
        }
    } else {
        const int b = m0 >> 10;
        const int s0 = m0 & 1023;
#pragma unroll
        for (int i = 0; i < 32; ++i) {
            int idx = i * 256 + t;
            int c = idx >> 7, srow = idx & 127;
            size_t gi = (size_t)(b * CC + n0 + c) * SS + s0 + srow;
            out[gi] = stage[srow * 65 + c] + bias[n0 + c] + xres[gi];
        }
    }
}

// ---------------------------------------------------------------------------
// Kernel 3: flash attention with mma.sync (3-pass bf16 for QK^T and PV).
// 64 queries per CTA, 8 warps (4 q-tiles x 2 key/d halves).
// Attention tiles are 64 wide -> pitch AP=72 bf16 (144B rows, 16B-aligned,
// conflict-free ldmatrix).
// ---------------------------------------------------------------------------
#define AP 72
#define ATILE (64 * AP * 2)       // 9216 bytes per 64x64 bf16 tile
#define A_QH 0
#define A_QL (1 * ATILE)
#define A_KH (2 * ATILE)
#define A_KL (3 * ATILE)
#define A_VH (4 * ATILE)
#define A_VL (5 * ATILE)
#define A_PH (6 * ATILE)
#define A_PL (7 * ATILE)
#define A_SS (8 * ATILE)          // fp32 [64][65] = 16640
#define A_ST (A_SS + 16640)       // m_s(64f) l_s(64f) al_s(64f) red(256f) = 1792
#define ATT_SMEM (A_ST + 1792)    // 92160

__global__ __launch_bounds__(256, 2) void attn_mma() {
    extern __shared__ __align__(16) char sm[];
    const uint32_t sb = smem_u32(sm);
    float* Ss = reinterpret_cast<float*>(sm + A_SS);
    float* m_s = reinterpret_cast<float*>(sm + A_ST);
    float* l_s = m_s + 64;
    float* al_s = l_s + 64;
    float* red = al_s + 64;

    const int i0 = blockIdx.x * 64;
    const int bh = blockIdx.y;
    const int b = bh >> 3, h = bh & 7;
    const int t = threadIdx.x, w = t >> 5, L = t & 31;
    const int wm = w >> 1, wn = w & 1;
    const int qq = t & 63, seg = t >> 6;

    const int arow = L & 15, aseg = L >> 4;
    const int brow = ((L >> 4) << 3) + (L & 7), bcol = ((L >> 3) & 1) * 8;
    const int crow = L >> 2, ccol = (L & 3) * 2;

    const float* qkb = g_qkv + (size_t)b * SS * QKVC + h * 192;

    // Q -> bf16 hi/lo, pre-scaled by 1/8 (both q and k scales folded)
#pragma unroll
    for (int i = 0; i < 4; ++i) {
        int f = t + 256 * i;
        int row = f >> 4, c4 = f & 15;
        float4 v = *(const float4*)(qkb + (size_t)(i0 + row) * QKVC + c4 * 4);
        v.x *= 0.125f; v.y *= 0.125f; v.z *= 0.125f; v.w *= 0.125f;
        cvt_st4(sm + A_QH, sm + A_QL, row * (AP * 2) + c4 * 8, v);
    }
    if (t < 64) { m_s[t] = -1e30f; l_s[t] = 0.f; }
    float o[4][4] = {};
    __syncthreads();

    for (int j0 = 0; j0 < SS; j0 += 64) {
        // K tile -> bf16 hi/lo, [key][d]
#pragma unroll
        for (int i = 0; i < 4; ++i) {
            int f = t + 256 * i;
            int row = f >> 4, c4 = f & 15;
            float4 v = *(const float4*)(qkb + (size_t)(j0 + row) * QKVC + DK + c4 * 4);
            cvt_st4(sm + A_KH, sm + A_KL, row * (AP * 2) + c4 * 8, v);
        }
        __syncthreads();

        // S = Q K^T (warp: 16q x 32key)
        float sc[4][4] = {};
#pragma unroll
        for (int ks = 0; ks < 4; ++ks) {
            uint32_t aoff = (uint32_t)(((wm * 16 + arow) * AP + ks * 16 + aseg * 8) * 2);
            uint32_t ah[4], al_[4];
            ldm_x4(ah, sb + A_QH + aoff);
            ldm_x4(al_, sb + A_QL + aoff);
            uint32_t bh_[2][4], bl_[2][4];
#pragma unroll
            for (int nt = 0; nt < 2; ++nt) {
                uint32_t boff = (uint32_t)(((wn * 32 + nt * 16 + brow) * AP +
                                            ks * 16 + bcol) * 2);
                ldm_x4(bh_[nt], sb + A_KH + boff);
                ldm_x4(bl_[nt], sb + A_KL + boff);
            }
#pragma unroll
            for (int n8 = 0; n8 < 4; ++n8) {
                const uint32_t* bhp = &bh_[n8 >> 1][(n8 & 1) * 2];
                const uint32_t* blp = &bl_[n8 >> 1][(n8 & 1) * 2];
                mma_bf16(sc[n8], ah, bhp);
                mma_bf16(sc[n8], ah, blp);
                mma_bf16(sc[n8], al_, bhp);
            }
        }
#pragma unroll
        for (int n8 = 0; n8 < 4; ++n8) {
            int r = wm * 16 + crow, c = wn * 32 + n8 * 8 + ccol;
            Ss[r * 65 + c]           = sc[n8][0];
            Ss[r * 65 + c + 1]       = sc[n8][1];
            Ss[(r + 8) * 65 + c]     = sc[n8][2];
            Ss[(r + 8) * 65 + c + 1] = sc[n8][3];
        }

        // V tile -> bf16 hi/lo transposed [d][key]
#pragma unroll
        for (int i = 0; i < 4; ++i) {
            int f = t + 256 * i;
            int key = f >> 4, c4 = f & 15;
            float4 v = *(const float4*)(qkb + (size_t)(j0 + key) * QKVC + 2 * DK + c4 * 4);
            float vv[4] = {v.x, v.y, v.z, v.w};
            int d0 = c4 * 4;
#pragma unroll
            for (int j = 0; j < 4; ++j) {
                __nv_bfloat16 hv = __float2bfloat16_rn(vv[j]);
                __nv_bfloat16 lv = __float2bfloat16_rn(vv[j] - __bfloat162float(hv));
                *reinterpret_cast<__nv_bfloat16*>(sm + A_VH + ((d0 + j) * AP + key) * 2) = hv;
                *reinterpret_cast<__nv_bfloat16*>(sm + A_VL + ((d0 + j) * AP + key) * 2) = lv;
            }
        }
        __syncthreads();

        // online softmax on Ss rows, write P to bf16 hi/lo
        float lmax = -1e30f;
#pragma unroll
        for (int i = 0; i < 16; ++i)
            lmax = fmaxf(lmax, Ss[qq * 65 + seg * 16 + i]);
        red[seg * 64 + qq] = lmax;
        __syncthreads();
        float tmax = fmaxf(fmaxf(red[qq], red[64 + qq]),
                           fmaxf(red[128 + qq], red[192 + qq]));
        float m_old = m_s[qq];
        float m_new = fmaxf(m_old, tmax);
        __syncthreads();
        if (seg == 0) { m_s[qq] = m_new; al_s[qq] = __expf(m_old - m_new); }

        float lsum = 0.f;
#pragma unroll
        for (int i = 0; i < 16; i += 2) {
            float p0 = __expf(Ss[qq * 65 + seg * 16 + i] - m_new);
            float p1 = __expf(Ss[qq * 65 + seg * 16 + i + 1] - m_new);
            lsum += p0 + p1;
            __nv_bfloat16 h0 = __float2bfloat16_rn(p0);
            __nv_bfloat16 h1 = __float2bfloat16_rn(p1);
            __nv_bfloat16 e0 = __float2bfloat16_rn(p0 - __bfloat162float(h0));
            __nv_bfloat16 e1 = __float2bfloat16_rn(p1 - __bfloat162float(h1));
            int off = (qq * AP + seg * 16 + i) * 2;
            *reinterpret_cast<uint32_t*>(sm + A_PH + off) = pack_bf2(h0, h1);
            *reinterpret_cast<uint32_t*>(sm + A_PL + off) = pack_bf2(e0, e1);
        }
        red[seg * 64 + qq] = lsum;
        __syncthreads();
        if (seg == 0)
            l_s[qq] = fmaf(l_s[qq], al_s[qq],
                           red[qq] + red[64 + qq] + red[128 + qq] + red[192 + qq]);

        // rescale O, then O += P V
        float ar0 = al_s[wm * 16 + crow];
        float ar1 = al_s[wm * 16 + crow + 8];
#pragma unroll
        for (int n8 = 0; n8 < 4; ++n8) {
            o[n8][0] *= ar0; o[n8][1] *= ar0;
            o[n8][2] *= ar1; o[n8][3] *= ar1;
        }
#pragma unroll
        for (int ks = 0; ks < 4; ++ks) {
            uint32_t aoff = (uint32_t)(((wm * 16 + arow) * AP + ks * 16 + aseg * 8) * 2);
            uint32_t ph[4], pl[4];
            ldm_x4(ph, sb + A_PH + aoff);
            ldm_x4(pl, sb + A_PL + aoff);
            uint32_t vh[2][4], vl[2][4];
#pragma unroll
            for (int nt = 0; nt < 2; ++nt) {
                uint32_t boff = (uint32_t)(((wn * 32 + nt * 16 + brow) * AP +
                                            ks * 16 + bcol) * 2);
                ldm_x4(vh[nt], sb + A_VH + boff);
                ldm_x4(vl[nt], sb + A_VL + boff);
            }
#pragma unroll
            for (int n8 = 0; n8 < 4; ++n8) {
                const uint32_t* bhp = &vh[n8 >> 1][(n8 & 1) * 2];
                const uint32_t* blp = &vl[n8 >> 1][(n8 & 1) * 2];
                mma_bf16(o[n8], ph, bhp);
                mma_bf16(o[n8], ph, blp);
                mma_bf16(o[n8], pl, bhp);
            }
        }
        __syncthreads();
    }

    const int q0 = wm * 16 + crow;
    const float inv0 = 1.f / l_s[q0];
    const float inv1 = 1.f / l_s[q0 + 8];
#pragma unroll
    for (int n8 = 0; n8 < 4; ++n8) {
        int d = wn * 32 + n8 * 8 + ccol;
        float2 v0 = make_float2(o[n8][0] * inv0, o[n8][1] * inv0);
        float2 v1 = make_float2(o[n8][2] * inv1, o[n8][3] * inv1);
        *(float2*)&g_ao[(size_t)(b * SS + i0 + q0) * CC + h * DK + d] = v0;
        *(float2*)&g_ao[(size_t)(b * SS + i0 + q0 + 8) * CC + h * DK + d] = v1;
    }
}

// ---------------------------------------------------------------------------
extern "C" void kernel_launch(void* const* d_in, const int* in_sizes, int n_in,
                              void* d_out, int out_size) {
    const float* x = (const float*)d_in[0];
    const float* gn_w = (const float*)d_in[1];
    const float* gn_b = (const float*)d_in[2];
    const float* proj_w = (const float*)d_in[3];
    const float* proj_b = (const float*)d_in[4];
    const float* out_w = (const float*)d_in[5];
    const float* out_b = (const float*)d_in[6];
    float* out = (float*)d_out;

    float* d_h;   cudaGetSymbolAddress((void**)&d_h, g_h);
    float* d_qkv; cudaGetSymbolAddress((void**)&d_qkv, g_qkv);
    float* d_ao;  cudaGetSymbolAddress((void**)&d_ao, g_ao);

    cudaFuncSetAttribute(mma_gemm<0>, cudaFuncAttributeMaxDynamicSharedMemorySize, GEMM_SMEM);
    cudaFuncSetAttribute(mma_gemm<1>, cudaFuncAttributeMaxDynamicSharedMemorySize, GEMM_SMEM);
    cudaFuncSetAttribute(attn_mma, cudaFuncAttributeMaxDynamicSharedMemorySize, ATT_SMEM);

    gn_kernel<<<BB * NG, 256>>>(x, gn_w, gn_b);

    mma_gemm<0><<<dim3(QKVC / 64, BB * SS / 128), 256, GEMM_SMEM>>>(
        d_h, proj_w, proj_b, nullptr, d_qkv, QKVC);

    attn_mma<<<dim3(SS / 64, BB * NH), 256, ATT_SMEM>>>();

    mma_gemm<1><<<dim3(CC / 64, BB * SS / 128), 256, GEMM_SMEM>>>(
        d_ao, out_w, out_b, x, out, CC);
}

// round 5
// speedup vs baseline: 2.2960x; 1.3114x over previous
#include <cuda_runtime.h>
#include <cuda_bf16.h>
#include <cstdint>

// Shapes: B=16, C=512, H=W=32 -> S=1024, 32 groups (16 ch/group), 8 heads, D=64.
#define BB 16
#define CC 512
#define SS 1024
#define NG 32
#define CPG 16
#define NH 8
#define DK 64
#define QKVC 1536

// hi/lo bf16 split storage for every mma operand (allocation-free rule)
static __device__ __nv_bfloat16 g_h_h[BB * SS * CC];
static __device__ __nv_bfloat16 g_h_l[BB * SS * CC];
static __device__ __nv_bfloat16 g_qkv_h[BB * SS * QKVC];
static __device__ __nv_bfloat16 g_qkv_l[BB * SS * QKVC];
static __device__ __nv_bfloat16 g_ao_h[BB * SS * CC];
static __device__ __nv_bfloat16 g_ao_l[BB * SS * CC];
static __device__ __nv_bfloat16 g_pw_h[QKVC * CC];
static __device__ __nv_bfloat16 g_pw_l[QKVC * CC];
static __device__ __nv_bfloat16 g_ow_h[CC * CC];
static __device__ __nv_bfloat16 g_ow_l[CC * CC];

// ============================================================================
// helpers
// ============================================================================
__device__ __forceinline__ uint32_t smem_u32(const void* p) {
    uint32_t a;
    asm("{ .reg .u64 t; cvta.to.shared.u64 t, %1; cvt.u32.u64 %0, t; }"
        : "=r"(a) : "l"(p));
    return a;
}

__device__ __forceinline__ void ldm_x4(uint32_t* r, uint32_t addr) {
    asm volatile("ldmatrix.sync.aligned.m8n8.x4.shared.b16 {%0,%1,%2,%3}, [%4];"
                 : "=r"(r[0]), "=r"(r[1]), "=r"(r[2]), "=r"(r[3]) : "r"(addr));
}
__device__ __forceinline__ void ldm_x4_t(uint32_t* r, uint32_t addr) {
    asm volatile("ldmatrix.sync.aligned.m8n8.x4.trans.shared.b16 {%0,%1,%2,%3}, [%4];"
                 : "=r"(r[0]), "=r"(r[1]), "=r"(r[2]), "=r"(r[3]) : "r"(addr));
}

__device__ __forceinline__ void mma_bf16(float* c, const uint32_t* a, const uint32_t* b) {
    asm volatile(
        "mma.sync.aligned.m16n8k16.row.col.f32.bf16.bf16.f32 "
        "{%0,%1,%2,%3}, {%4,%5,%6,%7}, {%8,%9}, {%0,%1,%2,%3};"
        : "+f"(c[0]), "+f"(c[1]), "+f"(c[2]), "+f"(c[3])
        : "r"(a[0]), "r"(a[1]), "r"(a[2]), "r"(a[3]), "r"(b[0]), "r"(b[1]));
}

#define CP_A16(dst, src) \
    asm volatile("cp.async.cg.shared.global [%0], [%1], 16;" :: "r"(dst), "l"(src))
#define CP_COMMIT() asm volatile("cp.async.commit_group;" ::: "memory")
#define CP_WAIT0()  asm volatile("cp.async.wait_group 0;" ::: "memory")
#define CP_WAIT1()  asm volatile("cp.async.wait_group 1;" ::: "memory")

__device__ __forceinline__ uint32_t pack_bf2(__nv_bfloat16 a, __nv_bfloat16 b) {
    __nv_bfloat162 v = __halves2bfloat162(a, b);
    return *reinterpret_cast<uint32_t*>(&v);
}

__device__ __forceinline__ void split2(float a, float b, uint32_t& h, uint32_t& l) {
    __nv_bfloat16 ha = __float2bfloat16_rn(a), hb = __float2bfloat16_rn(b);
    h = pack_bf2(ha, hb);
    l = pack_bf2(__float2bfloat16_rn(a - __bfloat162float(ha)),
                 __float2bfloat16_rn(b - __bfloat162float(hb)));
}

__device__ __forceinline__ void split4(float4 v, uint2& hv, uint2& lv) {
    split2(v.x, v.y, hv.x, lv.x);
    split2(v.z, v.w, hv.y, lv.y);
}

// ---------------------------------------------------------------------------
// Kernel 0: one-time weight split fp32 -> bf16 hi/lo
// ---------------------------------------------------------------------------
__global__ __launch_bounds__(256) void cvt_w(const float* __restrict__ w,
                                             __nv_bfloat16* __restrict__ hi,
                                             __nv_bfloat16* __restrict__ lo, int n4) {
    int i = blockIdx.x * 256 + threadIdx.x;
    if (i < n4) {
        float4 v = reinterpret_cast<const float4*>(w)[i];
        uint2 hv, lv;
        split4(v, hv, lv);
        reinterpret_cast<uint2*>(hi)[i] = hv;
        reinterpret_cast<uint2*>(lo)[i] = lv;
    }
}

// ---------------------------------------------------------------------------
// Kernel 1: GroupNorm, write transposed hi/lo bf16 to [B,S,C]
// ---------------------------------------------------------------------------
__global__ __launch_bounds__(256) void gn_kernel(const float* __restrict__ x,
                                                 const float* __restrict__ w,
                                                 const float* __restrict__ bgn) {
    const int b = blockIdx.x >> 5;
    const int g = blockIdx.x & 31;
    const float* xp = x + (size_t)(b * CC + g * CPG) * SS;
    const int t = threadIdx.x;

    float sum = 0.f, sq = 0.f;
    for (int i = t; i < CPG * SS; i += 256) {
        float v = xp[i];
        sum += v;
        sq = fmaf(v, v, sq);
    }
    __shared__ float s1[256], s2[256];
    s1[t] = sum; s2[t] = sq;
    __syncthreads();
    for (int o = 128; o > 0; o >>= 1) {
        if (t < o) { s1[t] += s1[t + o]; s2[t] += s2[t + o]; }
        __syncthreads();
    }
    __shared__ float mean_s, inv_s;
    if (t == 0) {
        const float n_inv = 1.f / (CPG * SS);
        float mean = s1[0] * n_inv;
        float var = s2[0] * n_inv - mean * mean;
        mean_s = mean;
        inv_s = rsqrtf(var + 1e-5f);
    }
    __syncthreads();
    const float mean = mean_s, inv = inv_s;

    const int cl = t & 15;
    const int c = g * CPG + cl;
    const float wc = w[c] * inv;
    const float bc = bgn[c] - mean * wc;
    for (int i = t; i < CPG * SS; i += 256) {
        int s = i >> 4;
        float v = xp[(size_t)cl * SS + s];
        float val = fmaf(v, wc, bc);
        __nv_bfloat16 hv = __float2bfloat16_rn(val);
        __nv_bfloat16 lv = __float2bfloat16_rn(val - __bfloat162float(hv));
        size_t idx = (size_t)(b * SS + s) * CC + c;
        g_h_h[idx] = hv;
        g_h_l[idx] = lv;
    }
}

// ---------------------------------------------------------------------------
// Kernel 2: convert-free mma GEMM, cp.async double-buffered.
// C[M,Ntot] = A @ W^T.  CTA tile 128x64, 8 warps (4Mx2N), K-chunk 32.
// MODE 0: +bias, write hi/lo bf16 row-major.  MODE 1: +bias+residual fp32 CM.
// ---------------------------------------------------------------------------
#define GP 40                 // bf16 smem pitch (80B rows)
#define GBUF 30720            // per-buffer bytes: Ah 10240 Al 10240 Bh 5120 Bl 5120
#define GEMM_SMEM (2 * GBUF)  // 61440; fp32 stage (<=34816) aliases buffers

template <int MODE>
__global__ __launch_bounds__(256, 2) void mma_gemm(
    const __nv_bfloat16* __restrict__ Ah, const __nv_bfloat16* __restrict__ Al,
    const __nv_bfloat16* __restrict__ Wh, const __nv_bfloat16* __restrict__ Wl,
    const float* __restrict__ bias, const float* __restrict__ xres,
    float* __restrict__ outf, __nv_bfloat16* __restrict__ oh,
    __nv_bfloat16* __restrict__ ol, int Ntot) {
    extern __shared__ __align__(16) char sm[];
    const uint32_t sb = smem_u32(sm);
    const int t = threadIdx.x, w = t >> 5, L = t & 31;
    const int n0 = blockIdx.x * 64;
    const int m0 = blockIdx.y * 128;
    const int wm = w >> 1, wn = w & 1;

    const int arow = L & 15, aseg = L >> 4;
    const int brow = ((L >> 4) << 3) + (L & 7), bcol = ((L >> 3) & 1) * 8;
    const int crow = L >> 2, ccol = (L & 3) * 2;

    float acc[2][4][4] = {};

    auto load_chunk = [&](int kc, int bb) {
        const int k0 = kc * 32;
        const uint32_t base = sb + bb * GBUF;
#pragma unroll
        for (int rep = 0; rep < 2; ++rep) {
            int c = t + rep * 256;
            int row = c >> 2, ch = c & 3;
            size_t so = (size_t)(m0 + row) * CC + k0 + ch * 8;
            CP_A16(base + row * 80 + ch * 16, Ah + so);
            CP_A16(base + 10240 + row * 80 + ch * 16, Al + so);
        }
        {
            int row = t >> 2, ch = t & 3;
            size_t so = (size_t)(n0 + row) * CC + k0 + ch * 8;
            CP_A16(base + 20480 + row * 80 + ch * 16, Wh + so);
            CP_A16(base + 25600 + row * 80 + ch * 16, Wl + so);
        }
    };

    auto compute = [&](int bb) {
        const uint32_t base = sb + bb * GBUF;
#pragma unroll
        for (int ks = 0; ks < 2; ++ks) {
            uint32_t ah[2][4], al2[2][4], bh[2][4], bl[2][4];
#pragma unroll
            for (int mt = 0; mt < 2; ++mt) {
                uint32_t off = (uint32_t)(((wm * 32 + mt * 16 + arow) * GP +
                                           ks * 16 + aseg * 8) * 2);
                ldm_x4(ah[mt], base + off);
                ldm_x4(al2[mt], base + 10240 + off);
            }
#pragma unroll
            for (int nt = 0; nt < 2; ++nt) {
                uint32_t off = (uint32_t)(((wn * 32 + nt * 16 + brow) * GP +
                                           ks * 16 + bcol) * 2);
                ldm_x4(bh[nt], base + 20480 + off);
                ldm_x4(bl[nt], base + 25600 + off);
            }
#pragma unroll
            for (int mt = 0; mt < 2; ++mt)
#pragma unroll
                for (int n8 = 0; n8 < 4; ++n8) {
                    const uint32_t* bhp = &bh[n8 >> 1][(n8 & 1) * 2];
                    const uint32_t* blp = &bl[n8 >> 1][(n8 & 1) * 2];
                    mma_bf16(acc[mt][n8], ah[mt], bhp);
                    mma_bf16(acc[mt][n8], ah[mt], blp);
                    mma_bf16(acc[mt][n8], al2[mt], bhp);
                }
        }
    };

    load_chunk(0, 0);
    CP_COMMIT();
    for (int kc = 0; kc < 16; ++kc) {
        if (kc < 15) {
            load_chunk(kc + 1, (kc + 1) & 1);
            CP_COMMIT();
            CP_WAIT1();
        } else {
            CP_WAIT0();
        }
        __syncthreads();
        compute(kc & 1);
        __syncthreads();
    }

    float* stage = reinterpret_cast<float*>(sm);
    const int PITCH = (MODE == 0) ? 68 : 65;
#pragma unroll
    for (int mt = 0; mt < 2; ++mt)
#pragma unroll
        for (int n8 = 0; n8 < 4; ++n8) {
            int r = wm * 32 + mt * 16 + crow;
            int c = wn * 32 + n8 * 8 + ccol;
            stage[r * PITCH + c]           = acc[mt][n8][0];
            stage[r * PITCH + c + 1]       = acc[mt][n8][1];
            stage[(r + 8) * PITCH + c]     = acc[mt][n8][2];
            stage[(r + 8) * PITCH + c + 1] = acc[mt][n8][3];
        }
    __syncthreads();

    if (MODE == 0) {
#pragma unroll
        for (int i = 0; i < 8; ++i) {
            int f = t + 256 * i;
            int row = f >> 4, c4 = f & 15;
            float4 v = *(const float4*)&stage[row * 68 + c4 * 4];
            float4 bb = *(const float4*)&bias[n0 + c4 * 4];
            v.x += bb.x; v.y += bb.y; v.z += bb.z; v.w += bb.w;
            uint2 hv, lv;
            split4(v, hv, lv);
            size_t go = (size_t)(m0 + row) * Ntot + n0 + c4 * 4;
            *reinterpret_cast<uint2*>(oh + go) = hv;
            *reinterpret_cast<uint2*>(ol + go) = lv;
        }
    } else {
        const int b = m0 >> 10;
        const int s0 = m0 & 1023;
#pragma unroll
        for (int i = 0; i < 32; ++i) {
            int idx = i * 256 + t;
            int c = idx >> 7, srow = idx & 127;
            size_t gi = (size_t)(b * CC + n0 + c) * SS + s0 + srow;
            outf[gi] = stage[srow * 65 + c] + bias[n0 + c] + xres[gi];
        }
    }
}

// ---------------------------------------------------------------------------
// Kernel 3: flash attention, convert-free tiles (hi/lo bf16 in gmem),
// cp.async pipelined K/V, ldmatrix.trans for V.  Scale 0.125 folded into S.
// ---------------------------------------------------------------------------
#define AP 72
#define ATILE (64 * AP * 2)       // 9216 B per 64x64 bf16 tile
#define A_QH 0
#define A_QL (1 * ATILE)
#define A_KH (2 * ATILE)
#define A_KL (3 * ATILE)
#define A_VH (4 * ATILE)
#define A_VL (5 * ATILE)
#define A_PH (6 * ATILE)
#define A_PL (7 * ATILE)
#define A_SS (8 * ATILE)          // fp32 [64][65] = 16640
#define A_ST (A_SS + 16640)       // m,l,al (64f each) + red (256f) = 1792
#define ATT_SMEM (A_ST + 1792)    // 92160

__global__ __launch_bounds__(256, 2) void attn_mma() {
    extern __shared__ __align__(16) char sm[];
    const uint32_t sb = smem_u32(sm);
    float* Ss = reinterpret_cast<float*>(sm + A_SS);
    float* m_s = reinterpret_cast<float*>(sm + A_ST);
    float* l_s = m_s + 64;
    float* al_s = l_s + 64;
    float* red = al_s + 64;

    const int i0 = blockIdx.x * 64;
    const int bh = blockIdx.y;
    const int b = bh >> 3, h = bh & 7;
    const int t = threadIdx.x, w = t >> 5, L = t & 31;
    const int wm = w >> 1, wn = w & 1;
    const int qq = t & 63, seg = t >> 6;

    const int arow = L & 15, aseg = L >> 4;
    const int brow = ((L >> 4) << 3) + (L & 7), bcol = ((L >> 3) & 1) * 8;
    const int crow = L >> 2, ccol = (L & 3) * 2;

    const __nv_bfloat16* qkh = g_qkv_h + (size_t)b * SS * QKVC + h * 192;
    const __nv_bfloat16* qkl = g_qkv_l + (size_t)b * SS * QKVC + h * 192;

    auto cp_tile = [&](uint32_t dh, uint32_t dl, const __nv_bfloat16* srh,
                       const __nv_bfloat16* srl) {
#pragma unroll
        for (int rep = 0; rep < 2; ++rep) {
            int c = t + rep * 256;
            int row = c >> 3, ch = c & 7;
            size_t so = (size_t)row * QKVC + ch * 8;
            CP_A16(dh + row * 144 + ch * 16, srh + so);
            CP_A16(dl + row * 144 + ch * 16, srl + so);
        }
    };

    // prologue: Q + K(0) in group 0, V(0) in group 1
    cp_tile(sb + A_QH, sb + A_QL, qkh + (size_t)i0 * QKVC, qkl + (size_t)i0 * QKVC);
    cp_tile(sb + A_KH, sb + A_KL, qkh + 64, qkl + 64);
    CP_COMMIT();
    cp_tile(sb + A_VH, sb + A_VL, qkh + 128, qkl + 128);
    CP_COMMIT();

    if (t < 64) { m_s[t] = -1e30f; l_s[t] = 0.f; }
    float o[4][4] = {};

    for (int j = 0; j < 16; ++j) {
        CP_WAIT1();           // Q + K(j) arrived
        __syncthreads();

        // S = Q K^T (warp: 16q x 32key), scale 0.125 folded in
        float sc[4][4] = {};
#pragma unroll
        for (int ks = 0; ks < 4; ++ks) {
            uint32_t aoff = (uint32_t)(((wm * 16 + arow) * AP + ks * 16 + aseg * 8) * 2);
            uint32_t ah[4], al_[4];
            ldm_x4(ah, sb + A_QH + aoff);
            ldm_x4(al_, sb + A_QL + aoff);
            uint32_t bh_[2][4], bl_[2][4];
#pragma unroll
            for (int nt = 0; nt < 2; ++nt) {
                uint32_t boff = (uint32_t)(((wn * 32 + nt * 16 + brow) * AP +
                                            ks * 16 + bcol) * 2);
                ldm_x4(bh_[nt], sb + A_KH + boff);
                ldm_x4(bl_[nt], sb + A_KL + boff);
            }
#pragma unroll
            for (int n8 = 0; n8 < 4; ++n8) {
                const uint32_t* bhp = &bh_[n8 >> 1][(n8 & 1) * 2];
                const uint32_t* blp = &bl_[n8 >> 1][(n8 & 1) * 2];
                mma_bf16(sc[n8], ah, bhp);
                mma_bf16(sc[n8], ah, blp);
                mma_bf16(sc[n8], al_, bhp);
            }
        }
#pragma unroll
        for (int n8 = 0; n8 < 4; ++n8) {
            int r = wm * 16 + crow, c = wn * 32 + n8 * 8 + ccol;
            Ss[r * 65 + c]           = sc[n8][0] * 0.125f;
            Ss[r * 65 + c + 1]       = sc[n8][1] * 0.125f;
            Ss[(r + 8) * 65 + c]     = sc[n8][2] * 0.125f;
            Ss[(r + 8) * 65 + c + 1] = sc[n8][3] * 0.125f;
        }
        __syncthreads();      // Ss visible; K smem free

        if (j < 15) {         // prefetch K(j+1), hidden behind softmax + PV
            size_t nb = (size_t)(j + 1) * 64 * QKVC;
            cp_tile(sb + A_KH, sb + A_KL, qkh + nb + 64, qkl + nb + 64);
            CP_COMMIT();
        }

        // online softmax
        float lmax = -1e30f;
#pragma unroll
        for (int i = 0; i < 16; ++i)
            lmax = fmaxf(lmax, Ss[qq * 65 + seg * 16 + i]);
        red[seg * 64 + qq] = lmax;
        __syncthreads();
        float tmax = fmaxf(fmaxf(red[qq], red[64 + qq]),
                           fmaxf(red[128 + qq], red[192 + qq]));
        float m_old = m_s[qq];
        float m_new = fmaxf(m_old, tmax);
        __syncthreads();
        if (seg == 0) { m_s[qq] = m_new; al_s[qq] = __expf(m_old - m_new); }

        float lsum = 0.f;
#pragma unroll
        for (int i = 0; i < 16; i += 2) {
            float p0 = __expf(Ss[qq * 65 + seg * 16 + i] - m_new);
            float p1 = __expf(Ss[qq * 65 + seg * 16 + i + 1] - m_new);
            lsum += p0 + p1;
            uint32_t hp, lp;
            split2(p0, p1, hp, lp);
            int off = (qq * AP + seg * 16 + i) * 2;
            *reinterpret_cast<uint32_t*>(sm + A_PH + off) = hp;
            *reinterpret_cast<uint32_t*>(sm + A_PL + off) = lp;
        }
        red[seg * 64 + qq] = lsum;

        if (j < 15) CP_WAIT1(); else CP_WAIT0();   // V(j) arrived
        __syncthreads();                           // P, lsum, V visible

        if (seg == 0)
            l_s[qq] = fmaf(l_s[qq], al_s[qq],
                           red[qq] + red[64 + qq] + red[128 + qq] + red[192 + qq]);

        float ar0 = al_s[wm * 16 + crow];
        float ar1 = al_s[wm * 16 + crow + 8];
#pragma unroll
        for (int n8 = 0; n8 < 4; ++n8) {
            o[n8][0] *= ar0; o[n8][1] *= ar0;
            o[n8][2] *= ar1; o[n8][3] *= ar1;
        }

        // O += P V  (V natural [key][d], trans ldmatrix)
#pragma unroll
        for (int ks = 0; ks < 4; ++ks) {
            uint32_t aoff = (uint32_t)(((wm * 16 + arow) * AP + ks * 16 + aseg * 8) * 2);
            uint32_t ph[4], pl[4];
            ldm_x4(ph, sb + A_PH + aoff);
            ldm_x4(pl, sb + A_PL + aoff);
            uint32_t vh[2][4], vl[2][4];
            int krow = ks * 16 + ((L >> 3) & 1) * 8 + (L & 7);
#pragma unroll
            for (int nt = 0; nt < 2; ++nt) {
                int dcol = wn * 32 + nt * 16 + (L >> 4) * 8;
                uint32_t boff = (uint32_t)((krow * AP + dcol) * 2);
                ldm_x4_t(vh[nt], sb + A_VH + boff);
                ldm_x4_t(vl[nt], sb + A_VL + boff);
            }
#pragma unroll
            for (int n8 = 0; n8 < 4; ++n8) {
                const uint32_t* bhp = &vh[n8 >> 1][(n8 & 1) * 2];
                const uint32_t* blp = &vl[n8 >> 1][(n8 & 1) * 2];
                mma_bf16(o[n8], ph, bhp);
                mma_bf16(o[n8], ph, blp);
                mma_bf16(o[n8], pl, bhp);
            }
        }
        __syncthreads();      // V, P consumed

        if (j < 15) {         // prefetch V(j+1), overlaps next QK
            size_t nb = (size_t)(j + 1) * 64 * QKVC;
            cp_tile(sb + A_VH, sb + A_VL, qkh + nb + 128, qkl + nb + 128);
            CP_COMMIT();
        }
    }

    const int q0 = wm * 16 + crow;
    const float inv0 = 1.f / l_s[q0];
    const float inv1 = 1.f / l_s[q0 + 8];
#pragma unroll
    for (int n8 = 0; n8 < 4; ++n8) {
        int d = wn * 32 + n8 * 8 + ccol;
        uint32_t h0, l0, h1, l1;
        split2(o[n8][0] * inv0, o[n8][1] * inv0, h0, l0);
        split2(o[n8][2] * inv1, o[n8][3] * inv1, h1, l1);
        size_t g0 = (size_t)(b * SS + i0 + q0) * CC + h * DK + d;
        size_t g1 = (size_t)(b * SS + i0 + q0 + 8) * CC + h * DK + d;
        *reinterpret_cast<uint32_t*>(g_ao_h + g0) = h0;
        *reinterpret_cast<uint32_t*>(g_ao_l + g0) = l0;
        *reinterpret_cast<uint32_t*>(g_ao_h + g1) = h1;
        *reinterpret_cast<uint32_t*>(g_ao_l + g1) = l1;
    }
}

// ---------------------------------------------------------------------------
extern "C" void kernel_launch(void* const* d_in, const int* in_sizes, int n_in,
                              void* d_out, int out_size) {
    const float* x = (const float*)d_in[0];
    const float* gn_w = (const float*)d_in[1];
    const float* gn_b = (const float*)d_in[2];
    const float* proj_w = (const float*)d_in[3];
    const float* proj_b = (const float*)d_in[4];
    const float* out_w = (const float*)d_in[5];
    const float* out_b = (const float*)d_in[6];
    float* out = (float*)d_out;

    __nv_bfloat16 *d_hh, *d_hl, *d_qh, *d_ql, *d_aoh, *d_aol;
    __nv_bfloat16 *d_pwh, *d_pwl, *d_owh, *d_owl;
    cudaGetSymbolAddress((void**)&d_hh, g_h_h);
    cudaGetSymbolAddress((void**)&d_hl, g_h_l);
    cudaGetSymbolAddress((void**)&d_qh, g_qkv_h);
    cudaGetSymbolAddress((void**)&d_ql, g_qkv_l);
    cudaGetSymbolAddress((void**)&d_aoh, g_ao_h);
    cudaGetSymbolAddress((void**)&d_aol, g_ao_l);
    cudaGetSymbolAddress((void**)&d_pwh, g_pw_h);
    cudaGetSymbolAddress((void**)&d_pwl, g_pw_l);
    cudaGetSymbolAddress((void**)&d_owh, g_ow_h);
    cudaGetSymbolAddress((void**)&d_owl, g_ow_l);

    cudaFuncSetAttribute(mma_gemm<0>, cudaFuncAttributeMaxDynamicSharedMemorySize, GEMM_SMEM);
    cudaFuncSetAttribute(mma_gemm<1>, cudaFuncAttributeMaxDynamicSharedMemorySize, GEMM_SMEM);
    cudaFuncSetAttribute(attn_mma, cudaFuncAttributeMaxDynamicSharedMemorySize, ATT_SMEM);

    cvt_w<<<(QKVC * CC / 4 + 255) / 256, 256>>>(proj_w, d_pwh, d_pwl, QKVC * CC / 4);
    cvt_w<<<(CC * CC / 4 + 255) / 256, 256>>>(out_w, d_owh, d_owl, CC * CC / 4);
    gn_kernel<<<BB * NG, 256>>>(x, gn_w, gn_b);

    mma_gemm<0><<<dim3(QKVC / 64, BB * SS / 128), 256, GEMM_SMEM>>>(
        d_hh, d_hl, d_pwh, d_pwl, proj_b, nullptr, nullptr, d_qh, d_ql, QKVC);

    attn_mma<<<dim3(SS / 64, BB * NH), 256, ATT_SMEM>>>();

    mma_gemm<1><<<dim3(CC / 64, BB * SS / 128), 256, GEMM_SMEM>>>(
        d_aoh, d_aol, d_owh, d_owl, out_b, x, out, nullptr, nullptr, CC);
}

// round 6
// speedup vs baseline: 2.7354x; 1.1914x over previous
#include <cuda_runtime.h>
#include <cuda_bf16.h>
#include <cstdint>

// Shapes: B=16, C=512, H=W=32 -> S=1024, 32 groups (16 ch/group), 8 heads, D=64.
#define BB 16
#define CC 512
#define SS 1024
#define NG 32
#define CPG 16
#define NH 8
#define DK 64
#define QKVC 1536

// hi/lo bf16 split storage for every mma operand (allocation-free rule)
static __device__ __nv_bfloat16 g_h_h[BB * SS * CC];
static __device__ __nv_bfloat16 g_h_l[BB * SS * CC];
static __device__ __nv_bfloat16 g_qkv_h[BB * SS * QKVC];
static __device__ __nv_bfloat16 g_qkv_l[BB * SS * QKVC];
static __device__ __nv_bfloat16 g_ao_h[BB * SS * CC];
static __device__ __nv_bfloat16 g_ao_l[BB * SS * CC];
static __device__ __nv_bfloat16 g_pw_h[QKVC * CC];
static __device__ __nv_bfloat16 g_pw_l[QKVC * CC];
static __device__ __nv_bfloat16 g_ow_h[CC * CC];
static __device__ __nv_bfloat16 g_ow_l[CC * CC];

// ============================================================================
// helpers
// ============================================================================
__device__ __forceinline__ uint32_t smem_u32(const void* p) {
    uint32_t a;
    asm("{ .reg .u64 t; cvta.to.shared.u64 t, %1; cvt.u32.u64 %0, t; }"
        : "=r"(a) : "l"(p));
    return a;
}

__device__ __forceinline__ void ldm_x4(uint32_t* r, uint32_t addr) {
    asm volatile("ldmatrix.sync.aligned.m8n8.x4.shared.b16 {%0,%1,%2,%3}, [%4];"
                 : "=r"(r[0]), "=r"(r[1]), "=r"(r[2]), "=r"(r[3]) : "r"(addr));
}
__device__ __forceinline__ void ldm_x4_t(uint32_t* r, uint32_t addr) {
    asm volatile("ldmatrix.sync.aligned.m8n8.x4.trans.shared.b16 {%0,%1,%2,%3}, [%4];"
                 : "=r"(r[0]), "=r"(r[1]), "=r"(r[2]), "=r"(r[3]) : "r"(addr));
}

__device__ __forceinline__ void mma_bf16(float* c, const uint32_t* a, const uint32_t* b) {
    asm volatile(
        "mma.sync.aligned.m16n8k16.row.col.f32.bf16.bf16.f32 "
        "{%0,%1,%2,%3}, {%4,%5,%6,%7}, {%8,%9}, {%0,%1,%2,%3};"
        : "+f"(c[0]), "+f"(c[1]), "+f"(c[2]), "+f"(c[3])
        : "r"(a[0]), "r"(a[1]), "r"(a[2]), "r"(a[3]), "r"(b[0]), "r"(b[1]));
}

#define CP_A16(dst, src) \
    asm volatile("cp.async.cg.shared.global [%0], [%1], 16;" :: "r"(dst), "l"(src))
#define CP_COMMIT() asm volatile("cp.async.commit_group;" ::: "memory")
#define CP_WAIT0()  asm volatile("cp.async.wait_group 0;" ::: "memory")
#define CP_WAIT1()  asm volatile("cp.async.wait_group 1;" ::: "memory")

__device__ __forceinline__ uint32_t pack_bf2(__nv_bfloat16 a, __nv_bfloat16 b) {
    __nv_bfloat162 v = __halves2bfloat162(a, b);
    return *reinterpret_cast<uint32_t*>(&v);
}

__device__ __forceinline__ void split2(float a, float b, uint32_t& h, uint32_t& l) {
    __nv_bfloat16 ha = __float2bfloat16_rn(a), hb = __float2bfloat16_rn(b);
    h = pack_bf2(ha, hb);
    l = pack_bf2(__float2bfloat16_rn(a - __bfloat162float(ha)),
                 __float2bfloat16_rn(b - __bfloat162float(hb)));
}

__device__ __forceinline__ void split4(float4 v, uint2& hv, uint2& lv) {
    split2(v.x, v.y, hv.x, lv.x);
    split2(v.z, v.w, hv.y, lv.y);
}

// ---------------------------------------------------------------------------
// Kernel 0: one-time weight split fp32 -> bf16 hi/lo
// ---------------------------------------------------------------------------
__global__ __launch_bounds__(256) void cvt_w(const float* __restrict__ w,
                                             __nv_bfloat16* __restrict__ hi,
                                             __nv_bfloat16* __restrict__ lo, int n4) {
    int i = blockIdx.x * 256 + threadIdx.x;
    if (i < n4) {
        float4 v = reinterpret_cast<const float4*>(w)[i];
        uint2 hv, lv;
        split4(v, hv, lv);
        reinterpret_cast<uint2*>(hi)[i] = hv;
        reinterpret_cast<uint2*>(lo)[i] = lv;
    }
}

// ---------------------------------------------------------------------------
// Kernel 1: GroupNorm, write transposed hi/lo bf16 to [B,S,C]
// ---------------------------------------------------------------------------
__global__ __launch_bounds__(256) void gn_kernel(const float* __restrict__ x,
                                                 const float* __restrict__ w,
                                                 const float* __restrict__ bgn) {
    const int b = blockIdx.x >> 5;
    const int g = blockIdx.x & 31;
    const float* xp = x + (size_t)(b * CC + g * CPG) * SS;
    const int t = threadIdx.x;

    float sum = 0.f, sq = 0.f;
    for (int i = t; i < CPG * SS; i += 256) {
        float v = xp[i];
        sum += v;
        sq = fmaf(v, v, sq);
    }
    __shared__ float s1[256], s2[256];
    s1[t] = sum; s2[t] = sq;
    __syncthreads();
    for (int o = 128; o > 0; o >>= 1) {
        if (t < o) { s1[t] += s1[t + o]; s2[t] += s2[t + o]; }
        __syncthreads();
    }
    __shared__ float mean_s, inv_s;
    if (t == 0) {
        const float n_inv = 1.f / (CPG * SS);
        float mean = s1[0] * n_inv;
        float var = s2[0] * n_inv - mean * mean;
        mean_s = mean;
        inv_s = rsqrtf(var + 1e-5f);
    }
    __syncthreads();
    const float mean = mean_s, inv = inv_s;

    const int cl = t & 15;
    const int c = g * CPG + cl;
    const float wc = w[c] * inv;
    const float bc = bgn[c] - mean * wc;
    for (int i = t; i < CPG * SS; i += 256) {
        int s = i >> 4;
        float v = xp[(size_t)cl * SS + s];
        float val = fmaf(v, wc, bc);
        __nv_bfloat16 hv = __float2bfloat16_rn(val);
        __nv_bfloat16 lv = __float2bfloat16_rn(val - __bfloat162float(hv));
        size_t idx = (size_t)(b * SS + s) * CC + c;
        g_h_h[idx] = hv;
        g_h_l[idx] = lv;
    }
}

// ---------------------------------------------------------------------------
// Kernel 2: convert-free mma GEMM, cp.async double-buffered, 3 CTAs/SM.
// ---------------------------------------------------------------------------
#define GP 40                 // bf16 smem pitch (80B rows)
#define GBUF 30720            // per-buffer: Ah 10240 Al 10240 Bh 5120 Bl 5120
#define GEMM_SMEM (2 * GBUF)

template <int MODE>
__global__ __launch_bounds__(256, 3) void mma_gemm(
    const __nv_bfloat16* __restrict__ Ah, const __nv_bfloat16* __restrict__ Al,
    const __nv_bfloat16* __restrict__ Wh, const __nv_bfloat16* __restrict__ Wl,
    const float* __restrict__ bias, const float* __restrict__ xres,
    float* __restrict__ outf, __nv_bfloat16* __restrict__ oh,
    __nv_bfloat16* __restrict__ ol, int Ntot) {
    extern __shared__ __align__(16) char sm[];
    const uint32_t sb = smem_u32(sm);
    const int t = threadIdx.x, w = t >> 5, L = t & 31;
    const int n0 = blockIdx.x * 64;
    const int m0 = blockIdx.y * 128;
    const int wm = w >> 1, wn = w & 1;

    const int arow = L & 15, aseg = L >> 4;
    const int brow = ((L >> 4) << 3) + (L & 7), bcol = ((L >> 3) & 1) * 8;
    const int crow = L >> 2, ccol = (L & 3) * 2;

    float acc[2][4][4] = {};

    auto load_chunk = [&](int kc, int bb) {
        const int k0 = kc * 32;
        const uint32_t base = sb + bb * GBUF;
#pragma unroll
        for (int rep = 0; rep < 2; ++rep) {
            int c = t + rep * 256;
            int row = c >> 2, ch = c & 3;
            size_t so = (size_t)(m0 + row) * CC + k0 + ch * 8;
            CP_A16(base + row * 80 + ch * 16, Ah + so);
            CP_A16(base + 10240 + row * 80 + ch * 16, Al + so);
        }
        {
            int row = t >> 2, ch = t & 3;
            size_t so = (size_t)(n0 + row) * CC + k0 + ch * 8;
            CP_A16(base + 20480 + row * 80 + ch * 16, Wh + so);
            CP_A16(base + 25600 + row * 80 + ch * 16, Wl + so);
        }
    };

    auto compute = [&](int bb) {
        const uint32_t base = sb + bb * GBUF;
#pragma unroll
        for (int ks = 0; ks < 2; ++ks) {
            uint32_t ah[2][4], al2[2][4], bh[2][4], bl[2][4];
#pragma unroll
            for (int mt = 0; mt < 2; ++mt) {
                uint32_t off = (uint32_t)(((wm * 32 + mt * 16 + arow) * GP +
                                           ks * 16 + aseg * 8) * 2);
                ldm_x4(ah[mt], base + off);
                ldm_x4(al2[mt], base + 10240 + off);
            }
#pragma unroll
            for (int nt = 0; nt < 2; ++nt) {
                uint32_t off = (uint32_t)(((wn * 32 + nt * 16 + brow) * GP +
                                           ks * 16 + bcol) * 2);
                ldm_x4(bh[nt], base + 20480 + off);
                ldm_x4(bl[nt], base + 25600 + off);
            }
#pragma unroll
            for (int mt = 0; mt < 2; ++mt)
#pragma unroll
                for (int n8 = 0; n8 < 4; ++n8) {
                    const uint32_t* bhp = &bh[n8 >> 1][(n8 & 1) * 2];
                    const uint32_t* blp = &bl[n8 >> 1][(n8 & 1) * 2];
                    mma_bf16(acc[mt][n8], ah[mt], bhp);
                    mma_bf16(acc[mt][n8], ah[mt], blp);
                    mma_bf16(acc[mt][n8], al2[mt], bhp);
                }
        }
    };

    load_chunk(0, 0);
    CP_COMMIT();
    for (int kc = 0; kc < 16; ++kc) {
        if (kc < 15) {
            load_chunk(kc + 1, (kc + 1) & 1);
            CP_COMMIT();
            CP_WAIT1();
        } else {
            CP_WAIT0();
        }
        __syncthreads();
        compute(kc & 1);
        __syncthreads();
    }

    float* stage = reinterpret_cast<float*>(sm);
    const int PITCH = (MODE == 0) ? 68 : 65;
#pragma unroll
    for (int mt = 0; mt < 2; ++mt)
#pragma unroll
        for (int n8 = 0; n8 < 4; ++n8) {
            int r = wm * 32 + mt * 16 + crow;
            int c = wn * 32 + n8 * 8 + ccol;
            stage[r * PITCH + c]           = acc[mt][n8][0];
            stage[r * PITCH + c + 1]       = acc[mt][n8][1];
            stage[(r + 8) * PITCH + c]     = acc[mt][n8][2];
            stage[(r + 8) * PITCH + c + 1] = acc[mt][n8][3];
        }
    __syncthreads();

    if (MODE == 0) {
#pragma unroll
        for (int i = 0; i < 8; ++i) {
            int f = t + 256 * i;
            int row = f >> 4, c4 = f & 15;
            float4 v = *(const float4*)&stage[row * 68 + c4 * 4];
            float4 bb = *(const float4*)&bias[n0 + c4 * 4];
            v.x += bb.x; v.y += bb.y; v.z += bb.z; v.w += bb.w;
            uint2 hv, lv;
            split4(v, hv, lv);
            size_t go = (size_t)(m0 + row) * Ntot + n0 + c4 * 4;
            *reinterpret_cast<uint2*>(oh + go) = hv;
            *reinterpret_cast<uint2*>(ol + go) = lv;
        }
    } else {
        const int b = m0 >> 10;
        const int s0 = m0 & 1023;
#pragma unroll
        for (int i = 0; i < 32; ++i) {
            int idx = i * 256 + t;
            int c = idx >> 7, srow = idx & 127;
            size_t gi = (size_t)(b * CC + n0 + c) * SS + s0 + srow;
            outf[gi] = stage[srow * 65 + c] + bias[n0 + c] + xres[gi];
        }
    }
}

// ---------------------------------------------------------------------------
// Kernel 3: flash attention, register-resident softmax + P fragments.
// Each warp: 16q x 32keys for QK; partial PV over its 32 keys into full
// 16q x 64d accumulator; halves merged once at the end.
// ---------------------------------------------------------------------------
#define AP 72
#define ATILE (64 * AP * 2)       // 9216 B per 64x64 bf16 tile
#define A_QH 0
#define A_QL (1 * ATILE)
#define A_KH (2 * ATILE)
#define A_KL (3 * ATILE)
#define A_VH (4 * ATILE)
#define A_VL (5 * ATILE)
#define A_RED (6 * ATILE)         // redm 128f + reds 128f = 1024B
#define A_MRG (A_RED + 1024)      // 64 x 66 fp32 = 16896
#define ATT_SMEM (A_MRG + 16896)  // 73216

__global__ __launch_bounds__(256, 2) void attn_mma() {
    extern __shared__ __align__(16) char sm[];
    const uint32_t sb = smem_u32(sm);
    float* redm = reinterpret_cast<float*>(sm + A_RED);
    float* reds = redm + 128;
    float* mrg = reinterpret_cast<float*>(sm + A_MRG);

    const int i0 = blockIdx.x * 64;
    const int bh = blockIdx.y;
    const int b = bh >> 3, h = bh & 7;
    const int t = threadIdx.x, w = t >> 5, L = t & 31;
    const int wm = w >> 1, wn = w & 1;

    const int arow = L & 15, aseg = L >> 4;
    const int brow = ((L >> 4) << 3) + (L & 7), bcol = ((L >> 3) & 1) * 8;
    const int crow = L >> 2, ccol = (L & 3) * 2;
    const int r0 = wm * 16 + crow;           // this thread's rows: r0, r0+8

    const __nv_bfloat16* qkh = g_qkv_h + (size_t)b * SS * QKVC + h * 192;
    const __nv_bfloat16* qkl = g_qkv_l + (size_t)b * SS * QKVC + h * 192;

    auto cp_tile = [&](uint32_t dh, uint32_t dl, const __nv_bfloat16* srh,
                       const __nv_bfloat16* srl) {
#pragma unroll
        for (int rep = 0; rep < 2; ++rep) {
            int c = t + rep * 256;
            int row = c >> 3, ch = c & 7;
            size_t so = (size_t)row * QKVC + ch * 8;
            CP_A16(dh + row * 144 + ch * 16, srh + so);
            CP_A16(dl + row * 144 + ch * 16, srl + so);
        }
    };

    cp_tile(sb + A_QH, sb + A_QL, qkh + (size_t)i0 * QKVC, qkl + (size_t)i0 * QKVC);
    cp_tile(sb + A_KH, sb + A_KL, qkh + 64, qkl + 64);
    CP_COMMIT();
    cp_tile(sb + A_VH, sb + A_VL, qkh + 128, qkl + 128);
    CP_COMMIT();

    float m0 = -1e30f, m1 = -1e30f, l0 = 0.f, l1 = 0.f;
    float o[8][4] = {};

    for (int j = 0; j < 16; ++j) {
        CP_WAIT1();               // Q + K(j) ready; V(j) in flight
        __syncthreads();

        // ---- S = Q K^T on this warp's 16q x 32key quadrant ----
        float sc[4][4] = {};
#pragma unroll
        for (int ks = 0; ks < 4; ++ks) {
            uint32_t aoff = (uint32_t)(((wm * 16 + arow) * AP + ks * 16 + aseg * 8) * 2);
            uint32_t ah[4], al_[4];
            ldm_x4(ah, sb + A_QH + aoff);
            ldm_x4(al_, sb + A_QL + aoff);
            uint32_t bh_[2][4], bl_[2][4];
#pragma unroll
            for (int nt = 0; nt < 2; ++nt) {
                uint32_t boff = (uint32_t)(((wn * 32 + nt * 16 + brow) * AP +
                                            ks * 16 + bcol) * 2);
                ldm_x4(bh_[nt], sb + A_KH + boff);
                ldm_x4(bl_[nt], sb + A_KL + boff);
            }
#pragma unroll
            for (int n8 = 0; n8 < 4; ++n8) {
                const uint32_t* bhp = &bh_[n8 >> 1][(n8 & 1) * 2];
                const uint32_t* blp = &bl_[n8 >> 1][(n8 & 1) * 2];
                mma_bf16(sc[n8], ah, bhp);
                mma_bf16(sc[n8], ah, blp);
                mma_bf16(sc[n8], al_, bhp);
            }
        }

        // ---- register softmax: scale + row max ----
        float mx0 = -1e30f, mx1 = -1e30f;
#pragma unroll
        for (int n8 = 0; n8 < 4; ++n8) {
            sc[n8][0] *= 0.125f; sc[n8][1] *= 0.125f;
            sc[n8][2] *= 0.125f; sc[n8][3] *= 0.125f;
            mx0 = fmaxf(mx0, fmaxf(sc[n8][0], sc[n8][1]));
            mx1 = fmaxf(mx1, fmaxf(sc[n8][2], sc[n8][3]));
        }
        mx0 = fmaxf(mx0, __shfl_xor_sync(0xffffffff, mx0, 1));
        mx0 = fmaxf(mx0, __shfl_xor_sync(0xffffffff, mx0, 2));
        mx1 = fmaxf(mx1, __shfl_xor_sync(0xffffffff, mx1, 1));
        mx1 = fmaxf(mx1, __shfl_xor_sync(0xffffffff, mx1, 2));
        if ((L & 3) == 0) {
            redm[r0 * 2 + wn] = mx0;
            redm[(r0 + 8) * 2 + wn] = mx1;
        }
        __syncthreads();          // K consumed + redm visible

        if (j < 15) {             // prefetch K(j+1) behind softmax + PV
            size_t nb = (size_t)(j + 1) * 64 * QKVC;
            cp_tile(sb + A_KH, sb + A_KL, qkh + nb + 64, qkl + nb + 64);
            CP_COMMIT();
        }

        float mn0 = fmaxf(m0, fmaxf(mx0, redm[r0 * 2 + (wn ^ 1)]));
        float mn1 = fmaxf(m1, fmaxf(mx1, redm[(r0 + 8) * 2 + (wn ^ 1)]));
        float a0 = __expf(m0 - mn0), a1 = __expf(m1 - mn1);
        m0 = mn0; m1 = mn1;

        // exp in registers, pack P fragments (hi/lo)
        uint32_t ph[2][4], pl[2][4];
        float s0 = 0.f, s1 = 0.f;
#pragma unroll
        for (int g = 0; g < 2; ++g)
#pragma unroll
            for (int hf = 0; hf < 2; ++hf) {
                int tile = g * 2 + hf;
                float p00 = __expf(sc[tile][0] - mn0);
                float p01 = __expf(sc[tile][1] - mn0);
                float p10 = __expf(sc[tile][2] - mn1);
                float p11 = __expf(sc[tile][3] - mn1);
                s0 += p00 + p01; s1 += p10 + p11;
                split2(p00, p01, ph[g][hf * 2], pl[g][hf * 2]);
                split2(p10, p11, ph[g][hf * 2 + 1], pl[g][hf * 2 + 1]);
            }
        s0 += __shfl_xor_sync(0xffffffff, s0, 1);
        s0 += __shfl_xor_sync(0xffffffff, s0, 2);
        s1 += __shfl_xor_sync(0xffffffff, s1, 1);
        s1 += __shfl_xor_sync(0xffffffff, s1, 2);
        if ((L & 3) == 0) {
            reds[r0 * 2 + wn] = s0;
            reds[(r0 + 8) * 2 + wn] = s1;
        }

        // rescale O (independent of exchange)
#pragma unroll
        for (int n8 = 0; n8 < 8; ++n8) {
            o[n8][0] *= a0; o[n8][1] *= a0;
            o[n8][2] *= a1; o[n8][3] *= a1;
        }

        if (j < 15) CP_WAIT1(); else CP_WAIT0();   // V(j) ready
        __syncthreads();                           // reds visible + V ready

        l0 = fmaf(l0, a0, s0 + reds[r0 * 2 + (wn ^ 1)]);
        l1 = fmaf(l1, a1, s1 + reds[(r0 + 8) * 2 + (wn ^ 1)]);

        // ---- O += P V over this warp's 32 keys, full 64 d ----
#pragma unroll
        for (int g = 0; g < 2; ++g) {
            int krow = wn * 32 + g * 16 + ((L >> 3) & 1) * 8 + (L & 7);
            uint32_t vh[4][4], vl[4][4];
#pragma unroll
            for (int nt = 0; nt < 4; ++nt) {
                int dcol = nt * 16 + (L >> 4) * 8;
                uint32_t boff = (uint32_t)((krow * AP + dcol) * 2);
                ldm_x4_t(vh[nt], sb + A_VH + boff);
                ldm_x4_t(vl[nt], sb + A_VL + boff);
            }
#pragma unroll
            for (int n8 = 0; n8 < 8; ++n8) {
                const uint32_t* bhp = &vh[n8 >> 1][(n8 & 1) * 2];
                const uint32_t* blp = &vl[n8 >> 1][(n8 & 1) * 2];
                mma_bf16(o[n8], ph[g], bhp);
                mma_bf16(o[n8], ph[g], blp);
                mma_bf16(o[n8], pl[g], bhp);
            }
        }
        __syncthreads();          // V consumed

        if (j < 15) {             // prefetch V(j+1), overlaps next QK
            size_t nb = (size_t)(j + 1) * 64 * QKVC;
            cp_tile(sb + A_VH, sb + A_VL, qkh + nb + 128, qkl + nb + 128);
            CP_COMMIT();
        }
    }

    // ---- merge warp-pair halves, normalize, store hi/lo bf16 ----
    if (wn == 1) {
#pragma unroll
        for (int n8 = 0; n8 < 8; ++n8) {
            int c = n8 * 8 + ccol;
            *(float2*)&mrg[(wm * 16 + crow) * 66 + c] = make_float2(o[n8][0], o[n8][1]);
            *(float2*)&mrg[(wm * 16 + crow + 8) * 66 + c] = make_float2(o[n8][2], o[n8][3]);
        }
    }
    __syncthreads();
    if (wn == 0) {
        float inv0 = 1.f / l0, inv1 = 1.f / l1;
#pragma unroll
        for (int n8 = 0; n8 < 8; ++n8) {
            int d = n8 * 8 + ccol;
            float2 u0 = *(float2*)&mrg[(wm * 16 + crow) * 66 + d];
            float2 u1 = *(float2*)&mrg[(wm * 16 + crow + 8) * 66 + d];
            float v00 = (o[n8][0] + u0.x) * inv0;
            float v01 = (o[n8][1] + u0.y) * inv0;
            float v10 = (o[n8][2] + u1.x) * inv1;
            float v11 = (o[n8][3] + u1.y) * inv1;
            uint32_t h0, lo0, h1, lo1;
            split2(v00, v01, h0, lo0);
            split2(v10, v11, h1, lo1);
            size_t g0 = (size_t)(b * SS + i0 + wm * 16 + crow) * CC + h * DK + d;
            size_t g1 = g0 + (size_t)8 * CC;
            *reinterpret_cast<uint32_t*>(g_ao_h + g0) = h0;
            *reinterpret_cast<uint32_t*>(g_ao_l + g0) = lo0;
            *reinterpret_cast<uint32_t*>(g_ao_h + g1) = h1;
            *reinterpret_cast<uint32_t*>(g_ao_l + g1) = lo1;
        }
    }
}

// ---------------------------------------------------------------------------
extern "C" void kernel_launch(void* const* d_in, const int* in_sizes, int n_in,
                              void* d_out, int out_size) {
    const float* x = (const float*)d_in[0];
    const float* gn_w = (const float*)d_in[1];
    const float* gn_b = (const float*)d_in[2];
    const float* proj_w = (const float*)d_in[3];
    const float* proj_b = (const float*)d_in[4];
    const float* out_w = (const float*)d_in[5];
    const float* out_b = (const float*)d_in[6];
    float* out = (float*)d_out;

    __nv_bfloat16 *d_hh, *d_hl, *d_qh, *d_ql, *d_aoh, *d_aol;
    __nv_bfloat16 *d_pwh, *d_pwl, *d_owh, *d_owl;
    cudaGetSymbolAddress((void**)&d_hh, g_h_h);
    cudaGetSymbolAddress((void**)&d_hl, g_h_l);
    cudaGetSymbolAddress((void**)&d_qh, g_qkv_h);
    cudaGetSymbolAddress((void**)&d_ql, g_qkv_l);
    cudaGetSymbolAddress((void**)&d_aoh, g_ao_h);
    cudaGetSymbolAddress((void**)&d_aol, g_ao_l);
    cudaGetSymbolAddress((void**)&d_pwh, g_pw_h);
    cudaGetSymbolAddress((void**)&d_pwl, g_pw_l);
    cudaGetSymbolAddress((void**)&d_owh, g_ow_h);
    cudaGetSymbolAddress((void**)&d_owl, g_ow_l);

    cudaFuncSetAttribute(mma_gemm<0>, cudaFuncAttributeMaxDynamicSharedMemorySize, GEMM_SMEM);
    cudaFuncSetAttribute(mma_gemm<1>, cudaFuncAttributeMaxDynamicSharedMemorySize, GEMM_SMEM);
    cudaFuncSetAttribute(attn_mma, cudaFuncAttributeMaxDynamicSharedMemorySize, ATT_SMEM);

    cvt_w<<<(QKVC * CC / 4 + 255) / 256, 256>>>(proj_w, d_pwh, d_pwl, QKVC * CC / 4);
    cvt_w<<<(CC * CC / 4 + 255) / 256, 256>>>(out_w, d_owh, d_owl, CC * CC / 4);
    gn_kernel<<<BB * NG, 256>>>(x, gn_w, gn_b);

    mma_gemm<0><<<dim3(QKVC / 64, BB * SS / 128), 256, GEMM_SMEM>>>(
        d_hh, d_hl, d_pwh, d_pwl, proj_b, nullptr, nullptr, d_qh, d_ql, QKVC);

    attn_mma<<<dim3(SS / 64, BB * NH), 256, ATT_SMEM>>>();

    mma_gemm<1><<<dim3(CC / 64, BB * SS / 128), 256, GEMM_SMEM>>>(
        d_aoh, d_aol, d_owh, d_owl, out_b, x, out, nullptr, nullptr, CC);
}

// round 7
// speedup vs baseline: 2.9046x; 1.0619x over previous
#include <cuda_runtime.h>
#include <cuda_bf16.h>
#include <cstdint>

// Shapes: B=16, C=512, H=W=32 -> S=1024, 32 groups (16 ch/group), 8 heads, D=64.
#define BB 16
#define CC 512
#define SS 1024
#define NG 32
#define CPG 16
#define NH 8
#define DK 64
#define QKVC 1536

// hi/lo bf16 split storage for every mma operand (allocation-free rule)
static __device__ __nv_bfloat16 g_h_h[BB * SS * CC];
static __device__ __nv_bfloat16 g_h_l[BB * SS * CC];
static __device__ __nv_bfloat16 g_qkv_h[BB * SS * QKVC];
static __device__ __nv_bfloat16 g_qkv_l[BB * SS * QKVC];
static __device__ __nv_bfloat16 g_ao_h[BB * SS * CC];
static __device__ __nv_bfloat16 g_ao_l[BB * SS * CC];
static __device__ __nv_bfloat16 g_pw_h[QKVC * CC];
static __device__ __nv_bfloat16 g_pw_l[QKVC * CC];
static __device__ __nv_bfloat16 g_ow_h[CC * CC];
static __device__ __nv_bfloat16 g_ow_l[CC * CC];

// ============================================================================
// helpers
// ============================================================================
__device__ __forceinline__ uint32_t smem_u32(const void* p) {
    uint32_t a;
    asm("{ .reg .u64 t; cvta.to.shared.u64 t, %1; cvt.u32.u64 %0, t; }"
        : "=r"(a) : "l"(p));
    return a;
}

__device__ __forceinline__ void ldm_x4(uint32_t* r, uint32_t addr) {
    asm volatile("ldmatrix.sync.aligned.m8n8.x4.shared.b16 {%0,%1,%2,%3}, [%4];"
                 : "=r"(r[0]), "=r"(r[1]), "=r"(r[2]), "=r"(r[3]) : "r"(addr));
}
__device__ __forceinline__ void ldm_x4_t(uint32_t* r, uint32_t addr) {
    asm volatile("ldmatrix.sync.aligned.m8n8.x4.trans.shared.b16 {%0,%1,%2,%3}, [%4];"
                 : "=r"(r[0]), "=r"(r[1]), "=r"(r[2]), "=r"(r[3]) : "r"(addr));
}

__device__ __forceinline__ void mma_bf16(float* c, const uint32_t* a, const uint32_t* b) {
    asm volatile(
        "mma.sync.aligned.m16n8k16.row.col.f32.bf16.bf16.f32 "
        "{%0,%1,%2,%3}, {%4,%5,%6,%7}, {%8,%9}, {%0,%1,%2,%3};"
        : "+f"(c[0]), "+f"(c[1]), "+f"(c[2]), "+f"(c[3])
        : "r"(a[0]), "r"(a[1]), "r"(a[2]), "r"(a[3]), "r"(b[0]), "r"(b[1]));
}

#define CP_A16(dst, src) \
    asm volatile("cp.async.cg.shared.global [%0], [%1], 16;" :: "r"(dst), "l"(src))
#define CP_COMMIT() asm volatile("cp.async.commit_group;" ::: "memory")
#define CP_WAIT0()  asm volatile("cp.async.wait_group 0;" ::: "memory")
#define CP_WAIT1()  asm volatile("cp.async.wait_group 1;" ::: "memory")

__device__ __forceinline__ uint32_t pack_bf2(__nv_bfloat16 a, __nv_bfloat16 b) {
    __nv_bfloat162 v = __halves2bfloat162(a, b);
    return *reinterpret_cast<uint32_t*>(&v);
}

__device__ __forceinline__ void split2(float a, float b, uint32_t& h, uint32_t& l) {
    __nv_bfloat16 ha = __float2bfloat16_rn(a), hb = __float2bfloat16_rn(b);
    h = pack_bf2(ha, hb);
    l = pack_bf2(__float2bfloat16_rn(a - __bfloat162float(ha)),
                 __float2bfloat16_rn(b - __bfloat162float(hb)));
}

__device__ __forceinline__ void split4(float4 v, uint2& hv, uint2& lv) {
    split2(v.x, v.y, hv.x, lv.x);
    split2(v.z, v.w, hv.y, lv.y);
}

// ---------------------------------------------------------------------------
// Kernel 0: one-time weight split fp32 -> bf16 hi/lo
// ---------------------------------------------------------------------------
__global__ __launch_bounds__(256) void cvt_w(const float* __restrict__ w,
                                             __nv_bfloat16* __restrict__ hi,
                                             __nv_bfloat16* __restrict__ lo, int n4) {
    int i = blockIdx.x * 256 + threadIdx.x;
    if (i < n4) {
        float4 v = reinterpret_cast<const float4*>(w)[i];
        uint2 hv, lv;
        split4(v, hv, lv);
        reinterpret_cast<uint2*>(hi)[i] = hv;
        reinterpret_cast<uint2*>(lo)[i] = lv;
    }
}

// ---------------------------------------------------------------------------
// Kernel 1: GroupNorm, write transposed hi/lo bf16 to [B,S,C]
// ---------------------------------------------------------------------------
__global__ __launch_bounds__(256) void gn_kernel(const float* __restrict__ x,
                                                 const float* __restrict__ w,
                                                 const float* __restrict__ bgn) {
    const int b = blockIdx.x >> 5;
    const int g = blockIdx.x & 31;
    const float* xp = x + (size_t)(b * CC + g * CPG) * SS;
    const int t = threadIdx.x;

    float sum = 0.f, sq = 0.f;
    for (int i = t; i < CPG * SS; i += 256) {
        float v = xp[i];
        sum += v;
        sq = fmaf(v, v, sq);
    }
    __shared__ float s1[256], s2[256];
    s1[t] = sum; s2[t] = sq;
    __syncthreads();
    for (int o = 128; o > 0; o >>= 1) {
        if (t < o) { s1[t] += s1[t + o]; s2[t] += s2[t + o]; }
        __syncthreads();
    }
    __shared__ float mean_s, inv_s;
    if (t == 0) {
        const float n_inv = 1.f / (CPG * SS);
        float mean = s1[0] * n_inv;
        float var = s2[0] * n_inv - mean * mean;
        mean_s = mean;
        inv_s = rsqrtf(var + 1e-5f);
    }
    __syncthreads();
    const float mean = mean_s, inv = inv_s;

    const int cl = t & 15;
    const int c = g * CPG + cl;
    const float wc = w[c] * inv;
    const float bc = bgn[c] - mean * wc;
    for (int i = t; i < CPG * SS; i += 256) {
        int s = i >> 4;
        float v = xp[(size_t)cl * SS + s];
        float val = fmaf(v, wc, bc);
        __nv_bfloat16 hv = __float2bfloat16_rn(val);
        __nv_bfloat16 lv = __float2bfloat16_rn(val - __bfloat162float(hv));
        size_t idx = (size_t)(b * SS + s) * CC + c;
        g_h_h[idx] = hv;
        g_h_l[idx] = lv;
    }
}

// ---------------------------------------------------------------------------
// Kernel 2: convert-free mma GEMM, 128x128 CTA tile, warp tile 32x64,
// cp.async double-buffered.
// ---------------------------------------------------------------------------
#define GP 40                 // bf16 smem pitch (80B rows)
#define GBUF 40960            // Ah 10240 | Al 10240 | Bh 10240 | Bl 10240
#define GEMM_SMEM (2 * GBUF)  // 81920 (fp32 stage aliases: <=67584)

template <int MODE>
__global__ __launch_bounds__(256, 2) void mma_gemm(
    const __nv_bfloat16* __restrict__ Ah, const __nv_bfloat16* __restrict__ Al,
    const __nv_bfloat16* __restrict__ Wh, const __nv_bfloat16* __restrict__ Wl,
    const float* __restrict__ bias, const float* __restrict__ xres,
    float* __restrict__ outf, __nv_bfloat16* __restrict__ oh,
    __nv_bfloat16* __restrict__ ol, int Ntot) {
    extern __shared__ __align__(16) char sm[];
    const uint32_t sb = smem_u32(sm);
    const int t = threadIdx.x, w = t >> 5, L = t & 31;
    const int n0 = blockIdx.x * 128;
    const int m0 = blockIdx.y * 128;
    const int wm = w >> 1, wn = w & 1;

    const int arow = L & 15, aseg = L >> 4;
    const int brow = ((L >> 4) << 3) + (L & 7), bcol = ((L >> 3) & 1) * 8;
    const int crow = L >> 2, ccol = (L & 3) * 2;

    float acc[2][8][4] = {};

    auto load_chunk = [&](int kc, int bb) {
        const int k0 = kc * 32;
        const uint32_t base = sb + bb * GBUF;
#pragma unroll
        for (int rep = 0; rep < 2; ++rep) {
            int c = t + rep * 256;
            int row = c >> 2, ch = c & 3;
            size_t so = (size_t)(m0 + row) * CC + k0 + ch * 8;
            CP_A16(base + row * 80 + ch * 16, Ah + so);
            CP_A16(base + 10240 + row * 80 + ch * 16, Al + so);
        }
#pragma unroll
        for (int rep = 0; rep < 2; ++rep) {
            int c = t + rep * 256;
            int row = c >> 2, ch = c & 3;
            size_t so = (size_t)(n0 + row) * CC + k0 + ch * 8;
            CP_A16(base + 20480 + row * 80 + ch * 16, Wh + so);
            CP_A16(base + 30720 + row * 80 + ch * 16, Wl + so);
        }
    };

    auto compute = [&](int bb) {
        const uint32_t base = sb + bb * GBUF;
#pragma unroll
        for (int ks = 0; ks < 2; ++ks) {
            uint32_t ah[2][4], al2[2][4], bh[4][4], bl[4][4];
#pragma unroll
            for (int mt = 0; mt < 2; ++mt) {
                uint32_t off = (uint32_t)(((wm * 32 + mt * 16 + arow) * GP +
                                           ks * 16 + aseg * 8) * 2);
                ldm_x4(ah[mt], base + off);
                ldm_x4(al2[mt], base + 10240 + off);
            }
#pragma unroll
            for (int nt = 0; nt < 4; ++nt) {
                uint32_t off = (uint32_t)(((wn * 64 + nt * 16 + brow) * GP +
                                           ks * 16 + bcol) * 2);
                ldm_x4(bh[nt], base + 20480 + off);
                ldm_x4(bl[nt], base + 30720 + off);
            }
#pragma unroll
            for (int mt = 0; mt < 2; ++mt)
#pragma unroll
                for (int n8 = 0; n8 < 8; ++n8) {
                    const uint32_t* bhp = &bh[n8 >> 1][(n8 & 1) * 2];
                    const uint32_t* blp = &bl[n8 >> 1][(n8 & 1) * 2];
                    mma_bf16(acc[mt][n8], ah[mt], bhp);
                    mma_bf16(acc[mt][n8], ah[mt], blp);
                    mma_bf16(acc[mt][n8], al2[mt], bhp);
                }
        }
    };

    load_chunk(0, 0);
    CP_COMMIT();
    for (int kc = 0; kc < 16; ++kc) {
        if (kc < 15) {
            load_chunk(kc + 1, (kc + 1) & 1);
            CP_COMMIT();
            CP_WAIT1();
        } else {
            CP_WAIT0();
        }
        __syncthreads();
        compute(kc & 1);
        __syncthreads();
    }

    float* stage = reinterpret_cast<float*>(sm);
    const int PITCH = (MODE == 0) ? 132 : 129;
#pragma unroll
    for (int mt = 0; mt < 2; ++mt)
#pragma unroll
        for (int n8 = 0; n8 < 8; ++n8) {
            int r = wm * 32 + mt * 16 + crow;
            int c = wn * 64 + n8 * 8 + ccol;
            stage[r * PITCH + c]           = acc[mt][n8][0];
            stage[r * PITCH + c + 1]       = acc[mt][n8][1];
            stage[(r + 8) * PITCH + c]     = acc[mt][n8][2];
            stage[(r + 8) * PITCH + c + 1] = acc[mt][n8][3];
        }
    __syncthreads();

    if (MODE == 0) {
#pragma unroll
        for (int i = 0; i < 16; ++i) {
            int f = t + 256 * i;
            int row = f >> 5, c4 = f & 31;
            float4 v = *(const float4*)&stage[row * 132 + c4 * 4];
            float4 bb = *(const float4*)&bias[n0 + c4 * 4];
            v.x += bb.x; v.y += bb.y; v.z += bb.z; v.w += bb.w;
            uint2 hv, lv;
            split4(v, hv, lv);
            size_t go = (size_t)(m0 + row) * Ntot + n0 + c4 * 4;
            *reinterpret_cast<uint2*>(oh + go) = hv;
            *reinterpret_cast<uint2*>(ol + go) = lv;
        }
    } else {
        const int b = m0 >> 10;
        const int s0 = m0 & 1023;
#pragma unroll
        for (int i = 0; i < 64; ++i) {
            int idx = i * 256 + t;
            int c = idx >> 7, srow = idx & 127;
            size_t gi = (size_t)(b * CC + n0 + c) * SS + s0 + srow;
            outf[gi] = stage[srow * 129 + c] + bias[n0 + c] + xres[gi];
        }
    }
}

// ---------------------------------------------------------------------------
// Kernel 3: flash attention, 128 queries/CTA, each warp owns 16 full rows.
// Softmax entirely register+shfl (no smem reductions, no merge pass).
// ---------------------------------------------------------------------------
#define AP 72
#define A_QH 0
#define A_QL 18432                // Q: 128 x 144B
#define A_KH 36864                // K: 64 x 144B
#define A_KL 46080
#define A_VH 55296
#define A_VL 64512
#define ATT_SMEM 73728

__global__ __launch_bounds__(256, 2) void attn_mma() {
    extern __shared__ __align__(16) char sm[];
    const uint32_t sb = smem_u32(sm);

    const int i0 = blockIdx.x * 128;
    const int bh = blockIdx.y;
    const int b = bh >> 3, h = bh & 7;
    const int t = threadIdx.x, w = t >> 5, L = t & 31;

    const int arow = L & 15, aseg = L >> 4;
    const int brow = ((L >> 4) << 3) + (L & 7), bcol = ((L >> 3) & 1) * 8;
    const int crow = L >> 2, ccol = (L & 3) * 2;

    const __nv_bfloat16* qkh = g_qkv_h + (size_t)b * SS * QKVC + h * 192;
    const __nv_bfloat16* qkl = g_qkv_l + (size_t)b * SS * QKVC + h * 192;

    // K/V tile loads: 64 rows x 64 cols
    auto cp_kv = [&](uint32_t dh, uint32_t dl, const __nv_bfloat16* srh,
                     const __nv_bfloat16* srl) {
#pragma unroll
        for (int rep = 0; rep < 2; ++rep) {
            int c = t + rep * 256;
            int row = c >> 3, ch = c & 7;
            size_t so = (size_t)row * QKVC + ch * 8;
            CP_A16(dh + row * 144 + ch * 16, srh + so);
            CP_A16(dl + row * 144 + ch * 16, srl + so);
        }
    };

    // Q: 128 rows x 64 cols
    {
        const __nv_bfloat16* sqh = qkh + (size_t)i0 * QKVC;
        const __nv_bfloat16* sql = qkl + (size_t)i0 * QKVC;
#pragma unroll
        for (int rep = 0; rep < 4; ++rep) {
            int c = t + rep * 256;
            int row = c >> 3, ch = c & 7;
            size_t so = (size_t)row * QKVC + ch * 8;
            CP_A16(sb + A_QH + row * 144 + ch * 16, sqh + so);
            CP_A16(sb + A_QL + row * 144 + ch * 16, sql + so);
        }
    }
    cp_kv(sb + A_KH, sb + A_KL, qkh + 64, qkl + 64);
    CP_COMMIT();
    cp_kv(sb + A_VH, sb + A_VL, qkh + 128, qkl + 128);
    CP_COMMIT();

    float m0 = -1e30f, m1 = -1e30f, l0 = 0.f, l1 = 0.f;
    float o[8][4] = {};

    for (int j = 0; j < 16; ++j) {
        CP_WAIT1();               // Q + K(j) ready; V(j) in flight
        __syncthreads();

        // ---- S = Q K^T : warp's 16 rows x all 64 keys ----
        float sc[8][4] = {};
#pragma unroll
        for (int ks = 0; ks < 4; ++ks) {
            uint32_t aoff = (uint32_t)(((w * 16 + arow) * AP + ks * 16 + aseg * 8) * 2);
            uint32_t ah[4], al_[4];
            ldm_x4(ah, sb + A_QH + aoff);
            ldm_x4(al_, sb + A_QL + aoff);
            uint32_t bh_[4][4], bl_[4][4];
#pragma unroll
            for (int nt = 0; nt < 4; ++nt) {
                uint32_t boff = (uint32_t)(((nt * 16 + brow) * AP +
                                            ks * 16 + bcol) * 2);
                ldm_x4(bh_[nt], sb + A_KH + boff);
                ldm_x4(bl_[nt], sb + A_KL + boff);
            }
#pragma unroll
            for (int n8 = 0; n8 < 8; ++n8) {
                const uint32_t* bhp = &bh_[n8 >> 1][(n8 & 1) * 2];
                const uint32_t* blp = &bl_[n8 >> 1][(n8 & 1) * 2];
                mma_bf16(sc[n8], ah, bhp);
                mma_bf16(sc[n8], ah, blp);
                mma_bf16(sc[n8], al_, bhp);
            }
        }
        __syncthreads();          // all warps done reading K(j)

        if (j < 15) {             // prefetch K(j+1) behind softmax + PV
            size_t nb = (size_t)(j + 1) * 64 * QKVC;
            cp_kv(sb + A_KH, sb + A_KL, qkh + nb + 64, qkl + nb + 64);
            CP_COMMIT();
        }

        // ---- register softmax over the full row (in-warp only) ----
        float mx0 = -1e30f, mx1 = -1e30f;
#pragma unroll
        for (int n8 = 0; n8 < 8; ++n8) {
            sc[n8][0] *= 0.125f; sc[n8][1] *= 0.125f;
            sc[n8][2] *= 0.125f; sc[n8][3] *= 0.125f;
            mx0 = fmaxf(mx0, fmaxf(sc[n8][0], sc[n8][1]));
            mx1 = fmaxf(mx1, fmaxf(sc[n8][2], sc[n8][3]));
        }
        mx0 = fmaxf(mx0, __shfl_xor_sync(0xffffffff, mx0, 1));
        mx0 = fmaxf(mx0, __shfl_xor_sync(0xffffffff, mx0, 2));
        mx1 = fmaxf(mx1, __shfl_xor_sync(0xffffffff, mx1, 1));
        mx1 = fmaxf(mx1, __shfl_xor_sync(0xffffffff, mx1, 2));

        float mn0 = fmaxf(m0, mx0), mn1 = fmaxf(m1, mx1);
        float a0 = __expf(m0 - mn0), a1 = __expf(m1 - mn1);
        m0 = mn0; m1 = mn1;

        uint32_t ph[4][4], pl[4][4];
        float s0 = 0.f, s1 = 0.f;
#pragma unroll
        for (int g = 0; g < 4; ++g)
#pragma unroll
            for (int hf = 0; hf < 2; ++hf) {
                int tile = g * 2 + hf;
                float p00 = __expf(sc[tile][0] - mn0);
                float p01 = __expf(sc[tile][1] - mn0);
                float p10 = __expf(sc[tile][2] - mn1);
                float p11 = __expf(sc[tile][3] - mn1);
                s0 += p00 + p01; s1 += p10 + p11;
                split2(p00, p01, ph[g][hf * 2], pl[g][hf * 2]);
                split2(p10, p11, ph[g][hf * 2 + 1], pl[g][hf * 2 + 1]);
            }
        s0 += __shfl_xor_sync(0xffffffff, s0, 1);
        s0 += __shfl_xor_sync(0xffffffff, s0, 2);
        s1 += __shfl_xor_sync(0xffffffff, s1, 1);
        s1 += __shfl_xor_sync(0xffffffff, s1, 2);
        l0 = fmaf(l0, a0, s0);
        l1 = fmaf(l1, a1, s1);

#pragma unroll
        for (int n8 = 0; n8 < 8; ++n8) {
            o[n8][0] *= a0; o[n8][1] *= a0;
            o[n8][2] *= a1; o[n8][3] *= a1;
        }

        if (j < 15) CP_WAIT1(); else CP_WAIT0();   // V(j) ready
        __syncthreads();

        // ---- O += P V over all 64 keys ----
#pragma unroll
        for (int g = 0; g < 4; ++g) {
            int krow = g * 16 + ((L >> 3) & 1) * 8 + (L & 7);
            uint32_t vh[4][4], vl[4][4];
#pragma unroll
            for (int nt = 0; nt < 4; ++nt) {
                int dcol = nt * 16 + (L >> 4) * 8;
                uint32_t boff = (uint32_t)((krow * AP + dcol) * 2);
                ldm_x4_t(vh[nt], sb + A_VH + boff);
                ldm_x4_t(vl[nt], sb + A_VL + boff);
            }
#pragma unroll
            for (int n8 = 0; n8 < 8; ++n8) {
                const uint32_t* bhp = &vh[n8 >> 1][(n8 & 1) * 2];
                const uint32_t* blp = &vl[n8 >> 1][(n8 & 1) * 2];
                mma_bf16(o[n8], ph[g], bhp);
                mma_bf16(o[n8], ph[g], blp);
                mma_bf16(o[n8], pl[g], bhp);
            }
        }
        __syncthreads();          // V consumed

        if (j < 15) {             // prefetch V(j+1), overlaps next QK
            size_t nb = (size_t)(j + 1) * 64 * QKVC;
            cp_kv(sb + A_VH, sb + A_VL, qkh + nb + 128, qkl + nb + 128);
            CP_COMMIT();
        }
    }

    // ---- normalize + store hi/lo bf16 (warp owns full rows; no merge) ----
    float inv0 = 1.f / l0, inv1 = 1.f / l1;
#pragma unroll
    for (int n8 = 0; n8 < 8; ++n8) {
        int d = n8 * 8 + ccol;
        uint32_t h0, lo0, h1, lo1;
        split2(o[n8][0] * inv0, o[n8][1] * inv0, h0, lo0);
        split2(o[n8][2] * inv1, o[n8][3] * inv1, h1, lo1);
        size_t g0 = (size_t)(b * SS + i0 + w * 16 + crow) * CC + h * DK + d;
        size_t g1 = g0 + (size_t)8 * CC;
        *reinterpret_cast<uint32_t*>(g_ao_h + g0) = h0;
        *reinterpret_cast<uint32_t*>(g_ao_l + g0) = lo0;
        *reinterpret_cast<uint32_t*>(g_ao_h + g1) = h1;
        *reinterpret_cast<uint32_t*>(g_ao_l + g1) = lo1;
    }
}

// ---------------------------------------------------------------------------
extern "C" void kernel_launch(void* const* d_in, const int* in_sizes, int n_in,
                              void* d_out, int out_size) {
    const float* x = (const float*)d_in[0];
    const float* gn_w = (const float*)d_in[1];
    const float* gn_b = (const float*)d_in[2];
    const float* proj_w = (const float*)d_in[3];
    const float* proj_b = (const float*)d_in[4];
    const float* out_w = (const float*)d_in[5];
    const float* out_b = (const float*)d_in[6];
    float* out = (float*)d_out;

    __nv_bfloat16 *d_hh, *d_hl, *d_qh, *d_ql, *d_aoh, *d_aol;
    __nv_bfloat16 *d_pwh, *d_pwl, *d_owh, *d_owl;
    cudaGetSymbolAddress((void**)&d_hh, g_h_h);
    cudaGetSymbolAddress((void**)&d_hl, g_h_l);
    cudaGetSymbolAddress((void**)&d_qh, g_qkv_h);
    cudaGetSymbolAddress((void**)&d_ql, g_qkv_l);
    cudaGetSymbolAddress((void**)&d_aoh, g_ao_h);
    cudaGetSymbolAddress((void**)&d_aol, g_ao_l);
    cudaGetSymbolAddress((void**)&d_pwh, g_pw_h);
    cudaGetSymbolAddress((void**)&d_pwl, g_pw_l);
    cudaGetSymbolAddress((void**)&d_owh, g_ow_h);
    cudaGetSymbolAddress((void**)&d_owl, g_ow_l);

    cudaFuncSetAttribute(mma_gemm<0>, cudaFuncAttributeMaxDynamicSharedMemorySize, GEMM_SMEM);
    cudaFuncSetAttribute(mma_gemm<1>, cudaFuncAttributeMaxDynamicSharedMemorySize, GEMM_SMEM);
    cudaFuncSetAttribute(attn_mma, cudaFuncAttributeMaxDynamicSharedMemorySize, ATT_SMEM);

    cvt_w<<<(QKVC * CC / 4 + 255) / 256, 256>>>(proj_w, d_pwh, d_pwl, QKVC * CC / 4);
    cvt_w<<<(CC * CC / 4 + 255) / 256, 256>>>(out_w, d_owh, d_owl, CC * CC / 4);
    gn_kernel<<<BB * NG, 256>>>(x, gn_w, gn_b);

    mma_gemm<0><<<dim3(QKVC / 128, BB * SS / 128), 256, GEMM_SMEM>>>(
        d_hh, d_hl, d_pwh, d_pwl, proj_b, nullptr, nullptr, d_qh, d_ql, QKVC);

    attn_mma<<<dim3(SS / 128, BB * NH), 256, ATT_SMEM>>>();

    mma_gemm<1><<<dim3(CC / 128, BB * SS / 128), 256, GEMM_SMEM>>>(
        d_aoh, d_aol, d_owh, d_owl, out_b, x, out, nullptr, nullptr, CC);
}

// round 8
// speedup vs baseline: 3.0539x; 1.0514x over previous
#include <cuda_runtime.h>
#include <cuda_bf16.h>
#include <cstdint>

// Shapes: B=16, C=512, H=W=32 -> S=1024, 32 groups (16 ch/group), 8 heads, D=64.
#define BB 16
#define CC 512
#define SS 1024
#define NG 32
#define CPG 16
#define NH 8
#define DK 64
#define QKVC 1536

// hi/lo bf16 split storage for every mma operand (allocation-free rule)
static __device__ __nv_bfloat16 g_h_h[BB * SS * CC];
static __device__ __nv_bfloat16 g_h_l[BB * SS * CC];
static __device__ __nv_bfloat16 g_qkv_h[BB * SS * QKVC];
static __device__ __nv_bfloat16 g_qkv_l[BB * SS * QKVC];
static __device__ __nv_bfloat16 g_ao_h[BB * SS * CC];
static __device__ __nv_bfloat16 g_ao_l[BB * SS * CC];
static __device__ __nv_bfloat16 g_pw_h[QKVC * CC];
static __device__ __nv_bfloat16 g_pw_l[QKVC * CC];
static __device__ __nv_bfloat16 g_ow_h[CC * CC];
static __device__ __nv_bfloat16 g_ow_l[CC * CC];

// ============================================================================
// helpers
// ============================================================================
__device__ __forceinline__ uint32_t smem_u32(const void* p) {
    uint32_t a;
    asm("{ .reg .u64 t; cvta.to.shared.u64 t, %1; cvt.u32.u64 %0, t; }"
        : "=r"(a) : "l"(p));
    return a;
}

__device__ __forceinline__ void ldm_x4(uint32_t* r, uint32_t addr) {
    asm volatile("ldmatrix.sync.aligned.m8n8.x4.shared.b16 {%0,%1,%2,%3}, [%4];"
                 : "=r"(r[0]), "=r"(r[1]), "=r"(r[2]), "=r"(r[3]) : "r"(addr));
}
__device__ __forceinline__ void ldm_x4_t(uint32_t* r, uint32_t addr) {
    asm volatile("ldmatrix.sync.aligned.m8n8.x4.trans.shared.b16 {%0,%1,%2,%3}, [%4];"
                 : "=r"(r[0]), "=r"(r[1]), "=r"(r[2]), "=r"(r[3]) : "r"(addr));
}

__device__ __forceinline__ void mma_bf16(float* c, const uint32_t* a, const uint32_t* b) {
    asm volatile(
        "mma.sync.aligned.m16n8k16.row.col.f32.bf16.bf16.f32 "
        "{%0,%1,%2,%3}, {%4,%5,%6,%7}, {%8,%9}, {%0,%1,%2,%3};"
        : "+f"(c[0]), "+f"(c[1]), "+f"(c[2]), "+f"(c[3])
        : "r"(a[0]), "r"(a[1]), "r"(a[2]), "r"(a[3]), "r"(b[0]), "r"(b[1]));
}

#define CP_A16(dst, src) \
    asm volatile("cp.async.cg.shared.global [%0], [%1], 16;" :: "r"(dst), "l"(src))
#define CP_COMMIT() asm volatile("cp.async.commit_group;" ::: "memory")
#define CP_WAIT0()  asm volatile("cp.async.wait_group 0;" ::: "memory")
#define CP_WAIT1()  asm volatile("cp.async.wait_group 1;" ::: "memory")
#define CP_WAIT2()  asm volatile("cp.async.wait_group 2;" ::: "memory")

__device__ __forceinline__ uint32_t pack_bf2(__nv_bfloat16 a, __nv_bfloat16 b) {
    __nv_bfloat162 v = __halves2bfloat162(a, b);
    return *reinterpret_cast<uint32_t*>(&v);
}

__device__ __forceinline__ void split2(float a, float b, uint32_t& h, uint32_t& l) {
    __nv_bfloat16 ha = __float2bfloat16_rn(a), hb = __float2bfloat16_rn(b);
    h = pack_bf2(ha, hb);
    l = pack_bf2(__float2bfloat16_rn(a - __bfloat162float(ha)),
                 __float2bfloat16_rn(b - __bfloat162float(hb)));
}

__device__ __forceinline__ void split4(float4 v, uint2& hv, uint2& lv) {
    split2(v.x, v.y, hv.x, lv.x);
    split2(v.z, v.w, hv.y, lv.y);
}

// ---------------------------------------------------------------------------
// Kernel 0: one-time weight split fp32 -> bf16 hi/lo
// ---------------------------------------------------------------------------
__global__ __launch_bounds__(256) void cvt_w(const float* __restrict__ w,
                                             __nv_bfloat16* __restrict__ hi,
                                             __nv_bfloat16* __restrict__ lo, int n4) {
    int i = blockIdx.x * 256 + threadIdx.x;
    if (i < n4) {
        float4 v = reinterpret_cast<const float4*>(w)[i];
        uint2 hv, lv;
        split4(v, hv, lv);
        reinterpret_cast<uint2*>(hi)[i] = hv;
        reinterpret_cast<uint2*>(lo)[i] = lv;
    }
}

// ---------------------------------------------------------------------------
// Kernel 1: GroupNorm, write transposed hi/lo bf16 to [B,S,C]
// ---------------------------------------------------------------------------
__global__ __launch_bounds__(256) void gn_kernel(const float* __restrict__ x,
                                                 const float* __restrict__ w,
                                                 const float* __restrict__ bgn) {
    const int b = blockIdx.x >> 5;
    const int g = blockIdx.x & 31;
    const float* xp = x + (size_t)(b * CC + g * CPG) * SS;
    const int t = threadIdx.x;

    float sum = 0.f, sq = 0.f;
    for (int i = t; i < CPG * SS; i += 256) {
        float v = xp[i];
        sum += v;
        sq = fmaf(v, v, sq);
    }
    __shared__ float s1[256], s2[256];
    s1[t] = sum; s2[t] = sq;
    __syncthreads();
    for (int o = 128; o > 0; o >>= 1) {
        if (t < o) { s1[t] += s1[t + o]; s2[t] += s2[t + o]; }
        __syncthreads();
    }
    __shared__ float mean_s, inv_s;
    if (t == 0) {
        const float n_inv = 1.f / (CPG * SS);
        float mean = s1[0] * n_inv;
        float var = s2[0] * n_inv - mean * mean;
        mean_s = mean;
        inv_s = rsqrtf(var + 1e-5f);
    }
    __syncthreads();
    const float mean = mean_s, inv = inv_s;

    const int cl = t & 15;
    const int c = g * CPG + cl;
    const float wc = w[c] * inv;
    const float bc = bgn[c] - mean * wc;
    for (int i = t; i < CPG * SS; i += 256) {
        int s = i >> 4;
        float v = xp[(size_t)cl * SS + s];
        float val = fmaf(v, wc, bc);
        __nv_bfloat16 hv = __float2bfloat16_rn(val);
        __nv_bfloat16 lv = __float2bfloat16_rn(val - __bfloat162float(hv));
        size_t idx = (size_t)(b * SS + s) * CC + c;
        g_h_h[idx] = hv;
        g_h_l[idx] = lv;
    }
}

// ---------------------------------------------------------------------------
// Kernel 2: convert-free mma GEMM, 128x64 CTA tile, 3-stage cp.async ring,
// ONE __syncthreads per k-chunk.
// ---------------------------------------------------------------------------
#define GP 40                 // bf16 smem pitch (80B rows)
#define GBUF 30720            // Ah 10240 | Al 10240 | Bh 5120 | Bl 5120
#define GEMM_SMEM (3 * GBUF)  // 92160; fp32 stage (<=34816) aliases

template <int MODE>
__global__ __launch_bounds__(256, 2) void mma_gemm(
    const __nv_bfloat16* __restrict__ Ah, const __nv_bfloat16* __restrict__ Al,
    const __nv_bfloat16* __restrict__ Wh, const __nv_bfloat16* __restrict__ Wl,
    const float* __restrict__ bias, const float* __restrict__ xres,
    float* __restrict__ outf, __nv_bfloat16* __restrict__ oh,
    __nv_bfloat16* __restrict__ ol, int Ntot) {
    extern __shared__ __align__(16) char sm[];
    const uint32_t sb = smem_u32(sm);
    const int t = threadIdx.x, w = t >> 5, L = t & 31;
    const int n0 = blockIdx.x * 64;
    const int m0 = blockIdx.y * 128;
    const int wm = w >> 1, wn = w & 1;

    const int arow = L & 15, aseg = L >> 4;
    const int brow = ((L >> 4) << 3) + (L & 7), bcol = ((L >> 3) & 1) * 8;
    const int crow = L >> 2, ccol = (L & 3) * 2;

    float acc[2][4][4] = {};

    auto load_chunk = [&](int kc, int st) {
        const int k0 = kc * 32;
        const uint32_t base = sb + st * GBUF;
#pragma unroll
        for (int rep = 0; rep < 2; ++rep) {
            int c = t + rep * 256;
            int row = c >> 2, ch = c & 3;
            size_t so = (size_t)(m0 + row) * CC + k0 + ch * 8;
            CP_A16(base + row * 80 + ch * 16, Ah + so);
            CP_A16(base + 10240 + row * 80 + ch * 16, Al + so);
        }
        {
            int row = t >> 2, ch = t & 3;
            size_t so = (size_t)(n0 + row) * CC + k0 + ch * 8;
            CP_A16(base + 20480 + row * 80 + ch * 16, Wh + so);
            CP_A16(base + 25600 + row * 80 + ch * 16, Wl + so);
        }
    };

    auto compute = [&](int st) {
        const uint32_t base = sb + st * GBUF;
#pragma unroll
        for (int ks = 0; ks < 2; ++ks) {
            uint32_t ah[2][4], al2[2][4], bh[2][4], bl[2][4];
#pragma unroll
            for (int mt = 0; mt < 2; ++mt) {
                uint32_t off = (uint32_t)(((wm * 32 + mt * 16 + arow) * GP +
                                           ks * 16 + aseg * 8) * 2);
                ldm_x4(ah[mt], base + off);
                ldm_x4(al2[mt], base + 10240 + off);
            }
#pragma unroll
            for (int nt = 0; nt < 2; ++nt) {
                uint32_t off = (uint32_t)(((wn * 32 + nt * 16 + brow) * GP +
                                           ks * 16 + bcol) * 2);
                ldm_x4(bh[nt], base + 20480 + off);
                ldm_x4(bl[nt], base + 25600 + off);
            }
#pragma unroll
            for (int mt = 0; mt < 2; ++mt)
#pragma unroll
                for (int n8 = 0; n8 < 4; ++n8) {
                    const uint32_t* bhp = &bh[n8 >> 1][(n8 & 1) * 2];
                    const uint32_t* blp = &bl[n8 >> 1][(n8 & 1) * 2];
                    mma_bf16(acc[mt][n8], ah[mt], bhp);
                    mma_bf16(acc[mt][n8], ah[mt], blp);
                    mma_bf16(acc[mt][n8], al2[mt], bhp);
                }
        }
    };

    load_chunk(0, 0); CP_COMMIT();
    load_chunk(1, 1); CP_COMMIT();
    int cs = 0, ls = 2;
    for (int kc = 0; kc < 16; ++kc) {
        if (kc < 15) CP_WAIT1(); else CP_WAIT0();
        __syncthreads();
        compute(cs);
        if (kc < 14) { load_chunk(kc + 2, ls); CP_COMMIT(); }
        cs = (cs == 2) ? 0 : cs + 1;
        ls = (ls == 2) ? 0 : ls + 1;
    }
    __syncthreads();   // buffers free before stage aliasing

    float* stage = reinterpret_cast<float*>(sm);
    const int PITCH = (MODE == 0) ? 68 : 65;
#pragma unroll
    for (int mt = 0; mt < 2; ++mt)
#pragma unroll
        for (int n8 = 0; n8 < 4; ++n8) {
            int r = wm * 32 + mt * 16 + crow;
            int c = wn * 32 + n8 * 8 + ccol;
            stage[r * PITCH + c]           = acc[mt][n8][0];
            stage[r * PITCH + c + 1]       = acc[mt][n8][1];
            stage[(r + 8) * PITCH + c]     = acc[mt][n8][2];
            stage[(r + 8) * PITCH + c + 1] = acc[mt][n8][3];
        }
    __syncthreads();

    if (MODE == 0) {
#pragma unroll
        for (int i = 0; i < 8; ++i) {
            int f = t + 256 * i;
            int row = f >> 4, c4 = f & 15;
            float4 v = *(const float4*)&stage[row * 68 + c4 * 4];
            float4 bb = *(const float4*)&bias[n0 + c4 * 4];
            v.x += bb.x; v.y += bb.y; v.z += bb.z; v.w += bb.w;
            uint2 hv, lv;
            split4(v, hv, lv);
            size_t go = (size_t)(m0 + row) * Ntot + n0 + c4 * 4;
            *reinterpret_cast<uint2*>(oh + go) = hv;
            *reinterpret_cast<uint2*>(ol + go) = lv;
        }
    } else {
        const int b = m0 >> 10;
        const int s0 = m0 & 1023;
#pragma unroll
        for (int i = 0; i < 32; ++i) {
            int idx = i * 256 + t;
            int c = idx >> 7, srow = idx & 127;
            size_t gi = (size_t)(b * CC + n0 + c) * SS + s0 + srow;
            outf[gi] = stage[srow * 65 + c] + bias[n0 + c] + xres[gi];
        }
    }
}

// ---------------------------------------------------------------------------
// Kernel 3: flash attention, 128 queries/CTA, warp owns 16 full rows.
// Double-buffered K and V: 2 syncs per tile.  Groups: K(j)=2j, V(j)=2j+1.
// ---------------------------------------------------------------------------
#define AP 72
#define A_QH 0                    // Q: 128 x 144B (hi), then lo
#define A_QL 18432
#define A_KB 36864                // K stage i at A_KB + i*18432 (hi | lo 9216)
#define A_VB 73728                // V stage i at A_VB + i*18432
#define ATT_SMEM 110592

__global__ __launch_bounds__(256, 2) void attn_mma() {
    extern __shared__ __align__(16) char sm[];
    const uint32_t sb = smem_u32(sm);

    const int i0 = blockIdx.x * 128;
    const int bh = blockIdx.y;
    const int b = bh >> 3, h = bh & 7;
    const int t = threadIdx.x, w = t >> 5, L = t & 31;

    const int arow = L & 15, aseg = L >> 4;
    const int brow = ((L >> 4) << 3) + (L & 7), bcol = ((L >> 3) & 1) * 8;
    const int crow = L >> 2, ccol = (L & 3) * 2;

    const __nv_bfloat16* qkh = g_qkv_h + (size_t)b * SS * QKVC + h * 192;
    const __nv_bfloat16* qkl = g_qkv_l + (size_t)b * SS * QKVC + h * 192;

    // K/V tile loads: 64 rows x 64 cols into [hi | lo] at base
    auto cp_kv = [&](uint32_t base, const __nv_bfloat16* srh,
                     const __nv_bfloat16* srl) {
#pragma unroll
        for (int rep = 0; rep < 2; ++rep) {
            int c = t + rep * 256;
            int row = c >> 3, ch = c & 7;
            size_t so = (size_t)row * QKVC + ch * 8;
            CP_A16(base + row * 144 + ch * 16, srh + so);
            CP_A16(base + 9216 + row * 144 + ch * 16, srl + so);
        }
    };

    // prologue groups: 0 = Q+K(0), 1 = V(0), 2 = K(1)
    {
        const __nv_bfloat16* sqh = qkh + (size_t)i0 * QKVC;
        const __nv_bfloat16* sql = qkl + (size_t)i0 * QKVC;
#pragma unroll
        for (int rep = 0; rep < 4; ++rep) {
            int c = t + rep * 256;
            int row = c >> 3, ch = c & 7;
            size_t so = (size_t)row * QKVC + ch * 8;
            CP_A16(sb + A_QH + row * 144 + ch * 16, sqh + so);
            CP_A16(sb + A_QL + row * 144 + ch * 16, sql + so);
        }
    }
    cp_kv(sb + A_KB, qkh + 64, qkl + 64);
    CP_COMMIT();
    cp_kv(sb + A_VB, qkh + 128, qkl + 128);
    CP_COMMIT();
    cp_kv(sb + A_KB + 18432, qkh + (size_t)64 * QKVC + 64,
          qkl + (size_t)64 * QKVC + 64);
    CP_COMMIT();

    float m0 = -1e30f, m1 = -1e30f, l0 = 0.f, l1 = 0.f;
    float o[8][4] = {};

    for (int j = 0; j < 16; ++j) {
        const uint32_t kbase = sb + A_KB + (j & 1) * 18432;
        const uint32_t vbase = sb + A_VB + (j & 1) * 18432;

        if (j < 15) CP_WAIT2(); else CP_WAIT1();   // K(j) ready
        __syncthreads();

        // ---- S = Q K^T : warp's 16 rows x all 64 keys ----
        float sc[8][4] = {};
#pragma unroll
        for (int ks = 0; ks < 4; ++ks) {
            uint32_t aoff = (uint32_t)(((w * 16 + arow) * AP + ks * 16 + aseg * 8) * 2);
            uint32_t ah[4], al_[4];
            ldm_x4(ah, sb + A_QH + aoff);
            ldm_x4(al_, sb + A_QL + aoff);
            uint32_t bh_[4][4], bl_[4][4];
#pragma unroll
            for (int nt = 0; nt < 4; ++nt) {
                uint32_t boff = (uint32_t)(((nt * 16 + brow) * AP +
                                            ks * 16 + bcol) * 2);
                ldm_x4(bh_[nt], kbase + boff);
                ldm_x4(bl_[nt], kbase + 9216 + boff);
            }
#pragma unroll
            for (int n8 = 0; n8 < 8; ++n8) {
                const uint32_t* bhp = &bh_[n8 >> 1][(n8 & 1) * 2];
                const uint32_t* blp = &bl_[n8 >> 1][(n8 & 1) * 2];
                mma_bf16(sc[n8], ah, bhp);
                mma_bf16(sc[n8], ah, blp);
                mma_bf16(sc[n8], al_, bhp);
            }
        }

        if (j < 15) {             // prefetch V(j+1) into other V buffer
            size_t nb = (size_t)(j + 1) * 64 * QKVC;
            cp_kv(sb + A_VB + ((j + 1) & 1) * 18432, qkh + nb + 128, qkl + nb + 128);
            CP_COMMIT();
        }

        // ---- register softmax over the full row (in-warp only) ----
        float mx0 = -1e30f, mx1 = -1e30f;
#pragma unroll
        for (int n8 = 0; n8 < 8; ++n8) {
            sc[n8][0] *= 0.125f; sc[n8][1] *= 0.125f;
            sc[n8][2] *= 0.125f; sc[n8][3] *= 0.125f;
            mx0 = fmaxf(mx0, fmaxf(sc[n8][0], sc[n8][1]));
            mx1 = fmaxf(mx1, fmaxf(sc[n8][2], sc[n8][3]));
        }
        mx0 = fmaxf(mx0, __shfl_xor_sync(0xffffffff, mx0, 1));
        mx0 = fmaxf(mx0, __shfl_xor_sync(0xffffffff, mx0, 2));
        mx1 = fmaxf(mx1, __shfl_xor_sync(0xffffffff, mx1, 1));
        mx1 = fmaxf(mx1, __shfl_xor_sync(0xffffffff, mx1, 2));

        float mn0 = fmaxf(m0, mx0), mn1 = fmaxf(m1, mx1);
        float a0 = __expf(m0 - mn0), a1 = __expf(m1 - mn1);
        m0 = mn0; m1 = mn1;

        uint32_t ph[4][4], pl[4][4];
        float s0 = 0.f, s1 = 0.f;
#pragma unroll
        for (int g = 0; g < 4; ++g)
#pragma unroll
            for (int hf = 0; hf < 2; ++hf) {
                int tile = g * 2 + hf;
                float p00 = __expf(sc[tile][0] - mn0);
                float p01 = __expf(sc[tile][1] - mn0);
                float p10 = __expf(sc[tile][2] - mn1);
                float p11 = __expf(sc[tile][3] - mn1);
                s0 += p00 + p01; s1 += p10 + p11;
                split2(p00, p01, ph[g][hf * 2], pl[g][hf * 2]);
                split2(p10, p11, ph[g][hf * 2 + 1], pl[g][hf * 2 + 1]);
            }
        s0 += __shfl_xor_sync(0xffffffff, s0, 1);
        s0 += __shfl_xor_sync(0xffffffff, s0, 2);
        s1 += __shfl_xor_sync(0xffffffff, s1, 1);
        s1 += __shfl_xor_sync(0xffffffff, s1, 2);
        l0 = fmaf(l0, a0, s0);
        l1 = fmaf(l1, a1, s1);

#pragma unroll
        for (int n8 = 0; n8 < 8; ++n8) {
            o[n8][0] *= a0; o[n8][1] *= a0;
            o[n8][2] *= a1; o[n8][3] *= a1;
        }

        if (j < 15) CP_WAIT2(); else CP_WAIT0();   // V(j) ready
        __syncthreads();

        // ---- O += P V over all 64 keys ----
#pragma unroll
        for (int g = 0; g < 4; ++g) {
            int krow = g * 16 + ((L >> 3) & 1) * 8 + (L & 7);
            uint32_t vh[4][4], vl[4][4];
#pragma unroll
            for (int nt = 0; nt < 4; ++nt) {
                int dcol = nt * 16 + (L >> 4) * 8;
                uint32_t boff = (uint32_t)((krow * AP + dcol) * 2);
                ldm_x4_t(vh[nt], vbase + boff);
                ldm_x4_t(vl[nt], vbase + 9216 + boff);
            }
#pragma unroll
            for (int n8 = 0; n8 < 8; ++n8) {
                const uint32_t* bhp = &vh[n8 >> 1][(n8 & 1) * 2];
                const uint32_t* blp = &vl[n8 >> 1][(n8 & 1) * 2];
                mma_bf16(o[n8], ph[g], bhp);
                mma_bf16(o[n8], ph[g], blp);
                mma_bf16(o[n8], pl[g], bhp);
            }
        }

        if (j < 14) {             // prefetch K(j+2) into other K buffer
            size_t nb = (size_t)(j + 2) * 64 * QKVC;
            cp_kv(sb + A_KB + (j & 1) * 18432, qkh + nb + 64, qkl + nb + 64);
            CP_COMMIT();
        }
    }

    // ---- normalize + store hi/lo bf16 (warp owns full rows; no merge) ----
    float inv0 = 1.f / l0, inv1 = 1.f / l1;
#pragma unroll
    for (int n8 = 0; n8 < 8; ++n8) {
        int d = n8 * 8 + ccol;
        uint32_t h0, lo0, h1, lo1;
        split2(o[n8][0] * inv0, o[n8][1] * inv0, h0, lo0);
        split2(o[n8][2] * inv1, o[n8][3] * inv1, h1, lo1);
        size_t g0 = (size_t)(b * SS + i0 + w * 16 + crow) * CC + h * DK + d;
        size_t g1 = g0 + (size_t)8 * CC;
        *reinterpret_cast<uint32_t*>(g_ao_h + g0) = h0;
        *reinterpret_cast<uint32_t*>(g_ao_l + g0) = lo0;
        *reinterpret_cast<uint32_t*>(g_ao_h + g1) = h1;
        *reinterpret_cast<uint32_t*>(g_ao_l + g1) = lo1;
    }
}

// ---------------------------------------------------------------------------
extern "C" void kernel_launch(void* const* d_in, const int* in_sizes, int n_in,
                              void* d_out, int out_size) {
    const float* x = (const float*)d_in[0];
    const float* gn_w = (const float*)d_in[1];
    const float* gn_b = (const float*)d_in[2];
    const float* proj_w = (const float*)d_in[3];
    const float* proj_b = (const float*)d_in[4];
    const float* out_w = (const float*)d_in[5];
    const float* out_b = (const float*)d_in[6];
    float* out = (float*)d_out;

    __nv_bfloat16 *d_hh, *d_hl, *d_qh, *d_ql, *d_aoh, *d_aol;
    __nv_bfloat16 *d_pwh, *d_pwl, *d_owh, *d_owl;
    cudaGetSymbolAddress((void**)&d_hh, g_h_h);
    cudaGetSymbolAddress((void**)&d_hl, g_h_l);
    cudaGetSymbolAddress((void**)&d_qh, g_qkv_h);
    cudaGetSymbolAddress((void**)&d_ql, g_qkv_l);
    cudaGetSymbolAddress((void**)&d_aoh, g_ao_h);
    cudaGetSymbolAddress((void**)&d_aol, g_ao_l);
    cudaGetSymbolAddress((void**)&d_pwh, g_pw_h);
    cudaGetSymbolAddress((void**)&d_pwl, g_pw_l);
    cudaGetSymbolAddress((void**)&d_owh, g_ow_h);
    cudaGetSymbolAddress((void**)&d_owl, g_ow_l);

    cudaFuncSetAttribute(mma_gemm<0>, cudaFuncAttributeMaxDynamicSharedMemorySize, GEMM_SMEM);
    cudaFuncSetAttribute(mma_gemm<1>, cudaFuncAttributeMaxDynamicSharedMemorySize, GEMM_SMEM);
    cudaFuncSetAttribute(attn_mma, cudaFuncAttributeMaxDynamicSharedMemorySize, ATT_SMEM);

    cvt_w<<<(QKVC * CC / 4 + 255) / 256, 256>>>(proj_w, d_pwh, d_pwl, QKVC * CC / 4);
    cvt_w<<<(CC * CC / 4 + 255) / 256, 256>>>(out_w, d_owh, d_owl, CC * CC / 4);
    gn_kernel<<<BB * NG, 256>>>(x, gn_w, gn_b);

    mma_gemm<0><<<dim3(QKVC / 64, BB * SS / 128), 256, GEMM_SMEM>>>(
        d_hh, d_hl, d_pwh, d_pwl, proj_b, nullptr, nullptr, d_qh, d_ql, QKVC);

    attn_mma<<<dim3(SS / 128, BB * NH), 256, ATT_SMEM>>>();

    mma_gemm<1><<<dim3(CC / 64, BB * SS / 128), 256, GEMM_SMEM>>>(
        d_aoh, d_aol, d_owh, d_owl, out_b, x, out, nullptr, nullptr, CC);
}

// round 9
// speedup vs baseline: 3.0956x; 1.0136x over previous
#include <cuda_runtime.h>
#include <cuda_bf16.h>
#include <cstdint>

// Shapes: B=16, C=512, H=W=32 -> S=1024, 32 groups (16 ch/group), 8 heads, D=64.
#define BB 16
#define CC 512
#define SS 1024
#define NG 32
#define CPG 16
#define NH 8
#define DK 64
#define QKVC 1536

// hi/lo bf16 split storage for every mma operand (allocation-free rule)
static __device__ __nv_bfloat16 g_h_h[BB * SS * CC];
static __device__ __nv_bfloat16 g_h_l[BB * SS * CC];
static __device__ __nv_bfloat16 g_qkv_h[BB * SS * QKVC];
static __device__ __nv_bfloat16 g_qkv_l[BB * SS * QKVC];
static __device__ __nv_bfloat16 g_ao_h[BB * SS * CC];
static __device__ __nv_bfloat16 g_ao_l[BB * SS * CC];
static __device__ __nv_bfloat16 g_pw_h[QKVC * CC];
static __device__ __nv_bfloat16 g_pw_l[QKVC * CC];
static __device__ __nv_bfloat16 g_ow_h[CC * CC];
static __device__ __nv_bfloat16 g_ow_l[CC * CC];

// ============================================================================
// helpers
// ============================================================================
__device__ __forceinline__ uint32_t smem_u32(const void* p) {
    uint32_t a;
    asm("{ .reg .u64 t; cvta.to.shared.u64 t, %1; cvt.u32.u64 %0, t; }"
        : "=r"(a) : "l"(p));
    return a;
}

__device__ __forceinline__ void ldm_x4(uint32_t* r, uint32_t addr) {
    asm volatile("ldmatrix.sync.aligned.m8n8.x4.shared.b16 {%0,%1,%2,%3}, [%4];"
                 : "=r"(r[0]), "=r"(r[1]), "=r"(r[2]), "=r"(r[3]) : "r"(addr));
}
__device__ __forceinline__ void ldm_x4_t(uint32_t* r, uint32_t addr) {
    asm volatile("ldmatrix.sync.aligned.m8n8.x4.trans.shared.b16 {%0,%1,%2,%3}, [%4];"
                 : "=r"(r[0]), "=r"(r[1]), "=r"(r[2]), "=r"(r[3]) : "r"(addr));
}

__device__ __forceinline__ void mma_bf16(float* c, const uint32_t* a, const uint32_t* b) {
    asm volatile(
        "mma.sync.aligned.m16n8k16.row.col.f32.bf16.bf16.f32 "
        "{%0,%1,%2,%3}, {%4,%5,%6,%7}, {%8,%9}, {%0,%1,%2,%3};"
        : "+f"(c[0]), "+f"(c[1]), "+f"(c[2]), "+f"(c[3])
        : "r"(a[0]), "r"(a[1]), "r"(a[2]), "r"(a[3]), "r"(b[0]), "r"(b[1]));
}

#define CP_A16(dst, src) \
    asm volatile("cp.async.cg.shared.global [%0], [%1], 16;" :: "r"(dst), "l"(src))
#define CP_COMMIT() asm volatile("cp.async.commit_group;" ::: "memory")
#define CP_WAIT0()  asm volatile("cp.async.wait_group 0;" ::: "memory")
#define CP_WAIT1()  asm volatile("cp.async.wait_group 1;" ::: "memory")
#define CP_WAIT2()  asm volatile("cp.async.wait_group 2;" ::: "memory")

// fp32 pair -> packed bf16 hi + packed bf16 lo (fast path: cvt.rn.bf16x2.f32)
__device__ __forceinline__ void split2(float a, float b, uint32_t& h, uint32_t& l) {
    uint32_t hp;
    asm("cvt.rn.bf16x2.f32 %0, %1, %2;" : "=r"(hp) : "f"(b), "f"(a));
    float ha = __uint_as_float(hp << 16);
    float hb = __uint_as_float(hp & 0xffff0000u);
    uint32_t lp;
    asm("cvt.rn.bf16x2.f32 %0, %1, %2;" : "=r"(lp) : "f"(b - hb), "f"(a - ha));
    h = hp; l = lp;
}

__device__ __forceinline__ void split4(float4 v, uint2& hv, uint2& lv) {
    split2(v.x, v.y, hv.x, lv.x);
    split2(v.z, v.w, hv.y, lv.y);
}

// ---------------------------------------------------------------------------
// Kernel 0: one-time weight split fp32 -> bf16 hi/lo (both weights, 1 launch)
// ---------------------------------------------------------------------------
__global__ __launch_bounds__(256) void cvt_w2(
    const float* __restrict__ w1, __nv_bfloat16* __restrict__ h1,
    __nv_bfloat16* __restrict__ l1, int n1,
    const float* __restrict__ w2, __nv_bfloat16* __restrict__ h2,
    __nv_bfloat16* __restrict__ l2, int n2) {
    int i = blockIdx.x * 256 + threadIdx.x;
    const float* w; __nv_bfloat16 *hi, *lo;
    if (i < n1) { w = w1; hi = h1; lo = l1; }
    else if (i < n1 + n2) { i -= n1; w = w2; hi = h2; lo = l2; }
    else return;
    float4 v = reinterpret_cast<const float4*>(w)[i];
    uint2 hv, lv;
    split4(v, hv, lv);
    reinterpret_cast<uint2*>(hi)[i] = hv;
    reinterpret_cast<uint2*>(lo)[i] = lv;
}

// ---------------------------------------------------------------------------
// Kernel 1: GroupNorm, write transposed hi/lo bf16 to [B,S,C]
// ---------------------------------------------------------------------------
__global__ __launch_bounds__(256) void gn_kernel(const float* __restrict__ x,
                                                 const float* __restrict__ w,
                                                 const float* __restrict__ bgn) {
    const int b = blockIdx.x >> 5;
    const int g = blockIdx.x & 31;
    const float* xp = x + (size_t)(b * CC + g * CPG) * SS;
    const int t = threadIdx.x;

    float sum = 0.f, sq = 0.f;
    for (int i = t; i < CPG * SS; i += 256) {
        float v = xp[i];
        sum += v;
        sq = fmaf(v, v, sq);
    }
    __shared__ float s1[256], s2[256];
    s1[t] = sum; s2[t] = sq;
    __syncthreads();
    for (int o = 128; o > 0; o >>= 1) {
        if (t < o) { s1[t] += s1[t + o]; s2[t] += s2[t + o]; }
        __syncthreads();
    }
    __shared__ float mean_s, inv_s;
    if (t == 0) {
        const float n_inv = 1.f / (CPG * SS);
        float mean = s1[0] * n_inv;
        float var = s2[0] * n_inv - mean * mean;
        mean_s = mean;
        inv_s = rsqrtf(var + 1e-5f);
    }
    __syncthreads();
    const float mean = mean_s, inv = inv_s;

    const int cl = t & 15;
    const int c = g * CPG + cl;
    const float wc = w[c] * inv;
    const float bc = bgn[c] - mean * wc;
    for (int i = t; i < CPG * SS; i += 256) {
        int s = i >> 4;
        float v = xp[(size_t)cl * SS + s];
        float val = fmaf(v, wc, bc);
        __nv_bfloat16 hv = __float2bfloat16_rn(val);
        __nv_bfloat16 lv = __float2bfloat16_rn(val - __bfloat162float(hv));
        size_t idx = (size_t)(b * SS + s) * CC + c;
        g_h_h[idx] = hv;
        g_h_l[idx] = lv;
    }
}

// ---------------------------------------------------------------------------
// Kernel 2: convert-free mma GEMM, 128x64 CTA tile, 3-stage cp.async ring,
// one __syncthreads per k-chunk, chain-free mma order (3 separate passes).
// ---------------------------------------------------------------------------
#define GP 40                 // bf16 smem pitch (80B rows)
#define GBUF 30720            // Ah 10240 | Al 10240 | Bh 5120 | Bl 5120
#define GEMM_SMEM (3 * GBUF)  // 92160; fp32 stage (<=34816) aliases

template <int MODE>
__global__ __launch_bounds__(256, 2) void mma_gemm(
    const __nv_bfloat16* __restrict__ Ah, const __nv_bfloat16* __restrict__ Al,
    const __nv_bfloat16* __restrict__ Wh, const __nv_bfloat16* __restrict__ Wl,
    const float* __restrict__ bias, const float* __restrict__ xres,
    float* __restrict__ outf, __nv_bfloat16* __restrict__ oh,
    __nv_bfloat16* __restrict__ ol, int Ntot) {
    extern __shared__ __align__(16) char sm[];
    const uint32_t sb = smem_u32(sm);
    const int t = threadIdx.x, w = t >> 5, L = t & 31;
    const int n0 = blockIdx.x * 64;
    const int m0 = blockIdx.y * 128;
    const int wm = w >> 1, wn = w & 1;

    const int arow = L & 15, aseg = L >> 4;
    const int brow = ((L >> 4) << 3) + (L & 7), bcol = ((L >> 3) & 1) * 8;
    const int crow = L >> 2, ccol = (L & 3) * 2;

    float acc[2][4][4] = {};

    auto load_chunk = [&](int kc, int st) {
        const int k0 = kc * 32;
        const uint32_t base = sb + st * GBUF;
#pragma unroll
        for (int rep = 0; rep < 2; ++rep) {
            int c = t + rep * 256;
            int row = c >> 2, ch = c & 3;
            size_t so = (size_t)(m0 + row) * CC + k0 + ch * 8;
            CP_A16(base + row * 80 + ch * 16, Ah + so);
            CP_A16(base + 10240 + row * 80 + ch * 16, Al + so);
        }
        {
            int row = t >> 2, ch = t & 3;
            size_t so = (size_t)(n0 + row) * CC + k0 + ch * 8;
            CP_A16(base + 20480 + row * 80 + ch * 16, Wh + so);
            CP_A16(base + 25600 + row * 80 + ch * 16, Wl + so);
        }
    };

    auto compute = [&](int st) {
        const uint32_t base = sb + st * GBUF;
#pragma unroll
        for (int ks = 0; ks < 2; ++ks) {
            uint32_t ah[2][4], al2[2][4], bh[2][4], bl[2][4];
#pragma unroll
            for (int mt = 0; mt < 2; ++mt) {
                uint32_t off = (uint32_t)(((wm * 32 + mt * 16 + arow) * GP +
                                           ks * 16 + aseg * 8) * 2);
                ldm_x4(ah[mt], base + off);
                ldm_x4(al2[mt], base + 10240 + off);
            }
#pragma unroll
            for (int nt = 0; nt < 2; ++nt) {
                uint32_t off = (uint32_t)(((wn * 32 + nt * 16 + brow) * GP +
                                           ks * 16 + bcol) * 2);
                ldm_x4(bh[nt], base + 20480 + off);
                ldm_x4(bl[nt], base + 25600 + off);
            }
            // chain-free: 3 passes over 8 independent accumulators
#pragma unroll
            for (int mt = 0; mt < 2; ++mt)
#pragma unroll
                for (int n8 = 0; n8 < 4; ++n8)
                    mma_bf16(acc[mt][n8], ah[mt], &bh[n8 >> 1][(n8 & 1) * 2]);
#pragma unroll
            for (int mt = 0; mt < 2; ++mt)
#pragma unroll
                for (int n8 = 0; n8 < 4; ++n8)
                    mma_bf16(acc[mt][n8], ah[mt], &bl[n8 >> 1][(n8 & 1) * 2]);
#pragma unroll
            for (int mt = 0; mt < 2; ++mt)
#pragma unroll
                for (int n8 = 0; n8 < 4; ++n8)
                    mma_bf16(acc[mt][n8], al2[mt], &bh[n8 >> 1][(n8 & 1) * 2]);
        }
    };

    load_chunk(0, 0); CP_COMMIT();
    load_chunk(1, 1); CP_COMMIT();
    int cs = 0, ls = 2;
    for (int kc = 0; kc < 16; ++kc) {
        if (kc < 15) CP_WAIT1(); else CP_WAIT0();
        __syncthreads();
        compute(cs);
        if (kc < 14) { load_chunk(kc + 2, ls); CP_COMMIT(); }
        cs = (cs == 2) ? 0 : cs + 1;
        ls = (ls == 2) ? 0 : ls + 1;
    }
    __syncthreads();   // buffers free before stage aliasing

    float* stage = reinterpret_cast<float*>(sm);
    const int PITCH = (MODE == 0) ? 68 : 65;
#pragma unroll
    for (int mt = 0; mt < 2; ++mt)
#pragma unroll
        for (int n8 = 0; n8 < 4; ++n8) {
            int r = wm * 32 + mt * 16 + crow;
            int c = wn * 32 + n8 * 8 + ccol;
            stage[r * PITCH + c]           = acc[mt][n8][0];
            stage[r * PITCH + c + 1]       = acc[mt][n8][1];
            stage[(r + 8) * PITCH + c]     = acc[mt][n8][2];
            stage[(r + 8) * PITCH + c + 1] = acc[mt][n8][3];
        }
    __syncthreads();

    if (MODE == 0) {
#pragma unroll
        for (int i = 0; i < 8; ++i) {
            int f = t + 256 * i;
            int row = f >> 4, c4 = f & 15;
            float4 v = *(const float4*)&stage[row * 68 + c4 * 4];
            float4 bb = *(const float4*)&bias[n0 + c4 * 4];
            v.x += bb.x; v.y += bb.y; v.z += bb.z; v.w += bb.w;
            uint2 hv, lv;
            split4(v, hv, lv);
            size_t go = (size_t)(m0 + row) * Ntot + n0 + c4 * 4;
            *reinterpret_cast<uint2*>(oh + go) = hv;
            *reinterpret_cast<uint2*>(ol + go) = lv;
        }
    } else {
        const int b = m0 >> 10;
        const int s0 = m0 & 1023;
#pragma unroll
        for (int i = 0; i < 32; ++i) {
            int idx = i * 256 + t;
            int c = idx >> 7, srow = idx & 127;
            size_t gi = (size_t)(b * CC + n0 + c) * SS + s0 + srow;
            outf[gi] = stage[srow * 65 + c] + bias[n0 + c] + xres[gi];
        }
    }
}

// ---------------------------------------------------------------------------
// Kernel 3: flash attention, 128 queries/CTA, warp owns 16 full rows.
// Double-buffered K and V (2 syncs/tile), chain-free mma passes.
// ---------------------------------------------------------------------------
#define AP 72
#define A_QH 0                    // Q: 128 x 144B (hi), then lo
#define A_QL 18432
#define A_KB 36864                // K stage i at A_KB + i*18432 (hi | lo 9216)
#define A_VB 73728                // V stage i at A_VB + i*18432
#define ATT_SMEM 110592

__global__ __launch_bounds__(256, 2) void attn_mma() {
    extern __shared__ __align__(16) char sm[];
    const uint32_t sb = smem_u32(sm);

    const int i0 = blockIdx.x * 128;
    const int bh = blockIdx.y;
    const int b = bh >> 3, h = bh & 7;
    const int t = threadIdx.x, w = t >> 5, L = t & 31;

    const int arow = L & 15, aseg = L >> 4;
    const int brow = ((L >> 4) << 3) + (L & 7), bcol = ((L >> 3) & 1) * 8;
    const int crow = L >> 2, ccol = (L & 3) * 2;

    const __nv_bfloat16* qkh = g_qkv_h + (size_t)b * SS * QKVC + h * 192;
    const __nv_bfloat16* qkl = g_qkv_l + (size_t)b * SS * QKVC + h * 192;

    auto cp_kv = [&](uint32_t base, const __nv_bfloat16* srh,
                     const __nv_bfloat16* srl) {
#pragma unroll
        for (int rep = 0; rep < 2; ++rep) {
            int c = t + rep * 256;
            int row = c >> 3, ch = c & 7;
            size_t so = (size_t)row * QKVC + ch * 8;
            CP_A16(base + row * 144 + ch * 16, srh + so);
            CP_A16(base + 9216 + row * 144 + ch * 16, srl + so);
        }
    };

    // prologue groups: 0 = Q+K(0), 1 = V(0), 2 = K(1)
    {
        const __nv_bfloat16* sqh = qkh + (size_t)i0 * QKVC;
        const __nv_bfloat16* sql = qkl + (size_t)i0 * QKVC;
#pragma unroll
        for (int rep = 0; rep < 4; ++rep) {
            int c = t + rep * 256;
            int row = c >> 3, ch = c & 7;
            size_t so = (size_t)row * QKVC + ch * 8;
            CP_A16(sb + A_QH + row * 144 + ch * 16, sqh + so);
            CP_A16(sb + A_QL + row * 144 + ch * 16, sql + so);
        }
    }
    cp_kv(sb + A_KB, qkh + 64, qkl + 64);
    CP_COMMIT();
    cp_kv(sb + A_VB, qkh + 128, qkl + 128);
    CP_COMMIT();
    cp_kv(sb + A_KB + 18432, qkh + (size_t)64 * QKVC + 64,
          qkl + (size_t)64 * QKVC + 64);
    CP_COMMIT();

    float m0 = -1e30f, m1 = -1e30f, l0 = 0.f, l1 = 0.f;
    float o[8][4] = {};

    for (int j = 0; j < 16; ++j) {
        const uint32_t kbase = sb + A_KB + (j & 1) * 18432;
        const uint32_t vbase = sb + A_VB + (j & 1) * 18432;

        if (j < 15) CP_WAIT2(); else CP_WAIT1();   // K(j) ready
        __syncthreads();

        // ---- S = Q K^T : warp's 16 rows x all 64 keys, chain-free ----
        float sc[8][4] = {};
#pragma unroll
        for (int ks = 0; ks < 4; ++ks) {
            uint32_t aoff = (uint32_t)(((w * 16 + arow) * AP + ks * 16 + aseg * 8) * 2);
            uint32_t ah[4], al_[4];
            ldm_x4(ah, sb + A_QH + aoff);
            ldm_x4(al_, sb + A_QL + aoff);
            uint32_t bh_[4][4], bl_[4][4];
#pragma unroll
            for (int nt = 0; nt < 4; ++nt) {
                uint32_t boff = (uint32_t)(((nt * 16 + brow) * AP +
                                            ks * 16 + bcol) * 2);
                ldm_x4(bh_[nt], kbase + boff);
                ldm_x4(bl_[nt], kbase + 9216 + boff);
            }
#pragma unroll
            for (int n8 = 0; n8 < 8; ++n8)
                mma_bf16(sc[n8], ah, &bh_[n8 >> 1][(n8 & 1) * 2]);
#pragma unroll
            for (int n8 = 0; n8 < 8; ++n8)
                mma_bf16(sc[n8], ah, &bl_[n8 >> 1][(n8 & 1) * 2]);
#pragma unroll
            for (int n8 = 0; n8 < 8; ++n8)
                mma_bf16(sc[n8], al_, &bh_[n8 >> 1][(n8 & 1) * 2]);
        }

        if (j < 15) {             // prefetch V(j+1) into other V buffer
            size_t nb = (size_t)(j + 1) * 64 * QKVC;
            cp_kv(sb + A_VB + ((j + 1) & 1) * 18432, qkh + nb + 128, qkl + nb + 128);
            CP_COMMIT();
        }

        // ---- register softmax over the full row (in-warp only) ----
        float mx0 = -1e30f, mx1 = -1e30f;
#pragma unroll
        for (int n8 = 0; n8 < 8; ++n8) {
            sc[n8][0] *= 0.125f; sc[n8][1] *= 0.125f;
            sc[n8][2] *= 0.125f; sc[n8][3] *= 0.125f;
            mx0 = fmaxf(mx0, fmaxf(sc[n8][0], sc[n8][1]));
            mx1 = fmaxf(mx1, fmaxf(sc[n8][2], sc[n8][3]));
        }
        mx0 = fmaxf(mx0, __shfl_xor_sync(0xffffffff, mx0, 1));
        mx0 = fmaxf(mx0, __shfl_xor_sync(0xffffffff, mx0, 2));
        mx1 = fmaxf(mx1, __shfl_xor_sync(0xffffffff, mx1, 1));
        mx1 = fmaxf(mx1, __shfl_xor_sync(0xffffffff, mx1, 2));

        float mn0 = fmaxf(m0, mx0), mn1 = fmaxf(m1, mx1);
        float a0 = __expf(m0 - mn0), a1 = __expf(m1 - mn1);
        m0 = mn0; m1 = mn1;

        uint32_t ph[4][4], pl[4][4];
        float s0 = 0.f, s1 = 0.f;
#pragma unroll
        for (int g = 0; g < 4; ++g)
#pragma unroll
            for (int hf = 0; hf < 2; ++hf) {
                int tile = g * 2 + hf;
                float p00 = __expf(sc[tile][0] - mn0);
                float p01 = __expf(sc[tile][1] - mn0);
                float p10 = __expf(sc[tile][2] - mn1);
                float p11 = __expf(sc[tile][3] - mn1);
                s0 += p00 + p01; s1 += p10 + p11;
                split2(p00, p01, ph[g][hf * 2], pl[g][hf * 2]);
                split2(p10, p11, ph[g][hf * 2 + 1], pl[g][hf * 2 + 1]);
            }
        s0 += __shfl_xor_sync(0xffffffff, s0, 1);
        s0 += __shfl_xor_sync(0xffffffff, s0, 2);
        s1 += __shfl_xor_sync(0xffffffff, s1, 1);
        s1 += __shfl_xor_sync(0xffffffff, s1, 2);
        l0 = fmaf(l0, a0, s0);
        l1 = fmaf(l1, a1, s1);

#pragma unroll
        for (int n8 = 0; n8 < 8; ++n8) {
            o[n8][0] *= a0; o[n8][1] *= a0;
            o[n8][2] *= a1; o[n8][3] *= a1;
        }

        if (j < 15) CP_WAIT2(); else CP_WAIT0();   // V(j) ready
        __syncthreads();

        // ---- O += P V over all 64 keys, chain-free ----
#pragma unroll
        for (int g = 0; g < 4; ++g) {
            int krow = g * 16 + ((L >> 3) & 1) * 8 + (L & 7);
            uint32_t vh[4][4], vl[4][4];
#pragma unroll
            for (int nt = 0; nt < 4; ++nt) {
                int dcol = nt * 16 + (L >> 4) * 8;
                uint32_t boff = (uint32_t)((krow * AP + dcol) * 2);
                ldm_x4_t(vh[nt], vbase + boff);
                ldm_x4_t(vl[nt], vbase + 9216 + boff);
            }
#pragma unroll
            for (int n8 = 0; n8 < 8; ++n8)
                mma_bf16(o[n8], ph[g], &vh[n8 >> 1][(n8 & 1) * 2]);
#pragma unroll
            for (int n8 = 0; n8 < 8; ++n8)
                mma_bf16(o[n8], ph[g], &vl[n8 >> 1][(n8 & 1) * 2]);
#pragma unroll
            for (int n8 = 0; n8 < 8; ++n8)
                mma_bf16(o[n8], pl[g], &vh[n8 >> 1][(n8 & 1) * 2]);
        }

        if (j < 14) {             // prefetch K(j+2) into other K buffer
            size_t nb = (size_t)(j + 2) * 64 * QKVC;
            cp_kv(sb + A_KB + (j & 1) * 18432, qkh + nb + 64, qkl + nb + 64);
            CP_COMMIT();
        }
    }

    // ---- normalize + store hi/lo bf16 (warp owns full rows; no merge) ----
    float inv0 = 1.f / l0, inv1 = 1.f / l1;
#pragma unroll
    for (int n8 = 0; n8 < 8; ++n8) {
        int d = n8 * 8 + ccol;
        uint32_t h0, lo0, h1, lo1;
        split2(o[n8][0] * inv0, o[n8][1] * inv0, h0, lo0);
        split2(o[n8][2] * inv1, o[n8][3] * inv1, h1, lo1);
        size_t g0 = (size_t)(b * SS + i0 + w * 16 + crow) * CC + h * DK + d;
        size_t g1 = g0 + (size_t)8 * CC;
        *reinterpret_cast<uint32_t*>(g_ao_h + g0) = h0;
        *reinterpret_cast<uint32_t*>(g_ao_l + g0) = lo0;
        *reinterpret_cast<uint32_t*>(g_ao_h + g1) = h1;
        *reinterpret_cast<uint32_t*>(g_ao_l + g1) = lo1;
    }
}

// ---------------------------------------------------------------------------
extern "C" void kernel_launch(void* const* d_in, const int* in_sizes, int n_in,
                              void* d_out, int out_size) {
    const float* x = (const float*)d_in[0];
    const float* gn_w = (const float*)d_in[1];
    const float* gn_b = (const float*)d_in[2];
    const float* proj_w = (const float*)d_in[3];
    const float* proj_b = (const float*)d_in[4];
    const float* out_w = (const float*)d_in[5];
    const float* out_b = (const float*)d_in[6];
    float* out = (float*)d_out;

    __nv_bfloat16 *d_hh, *d_hl, *d_qh, *d_ql, *d_aoh, *d_aol;
    __nv_bfloat16 *d_pwh, *d_pwl, *d_owh, *d_owl;
    cudaGetSymbolAddress((void**)&d_hh, g_h_h);
    cudaGetSymbolAddress((void**)&d_hl, g_h_l);
    cudaGetSymbolAddress((void**)&d_qh, g_qkv_h);
    cudaGetSymbolAddress((void**)&d_ql, g_qkv_l);
    cudaGetSymbolAddress((void**)&d_aoh, g_ao_h);
    cudaGetSymbolAddress((void**)&d_aol, g_ao_l);
    cudaGetSymbolAddress((void**)&d_pwh, g_pw_h);
    cudaGetSymbolAddress((void**)&d_pwl, g_pw_l);
    cudaGetSymbolAddress((void**)&d_owh, g_ow_h);
    cudaGetSymbolAddress((void**)&d_owl, g_ow_l);

    cudaFuncSetAttribute(mma_gemm<0>, cudaFuncAttributeMaxDynamicSharedMemorySize, GEMM_SMEM);
    cudaFuncSetAttribute(mma_gemm<1>, cudaFuncAttributeMaxDynamicSharedMemorySize, GEMM_SMEM);
    cudaFuncSetAttribute(attn_mma, cudaFuncAttributeMaxDynamicSharedMemorySize, ATT_SMEM);

    const int n1 = QKVC * CC / 4, n2 = CC * CC / 4;
    cvt_w2<<<(n1 + n2 + 255) / 256, 256>>>(proj_w, d_pwh, d_pwl, n1,
                                           out_w, d_owh, d_owl, n2);
    gn_kernel<<<BB * NG, 256>>>(x, gn_w, gn_b);

    mma_gemm<0><<<dim3(QKVC / 64, BB * SS / 128), 256, GEMM_SMEM>>>(
        d_hh, d_hl, d_pwh, d_pwl, proj_b, nullptr, nullptr, d_qh, d_ql, QKVC);

    attn_mma<<<dim3(SS / 128, BB * NH), 256, ATT_SMEM>>>();

    mma_gemm<1><<<dim3(CC / 64, BB * SS / 128), 256, GEMM_SMEM>>>(
        d_aoh, d_aol, d_owh, d_owl, out_b, x, out, nullptr, nullptr, CC);
}

// round 10
// speedup vs baseline: 3.3106x; 1.0695x over previous
#include <cuda_runtime.h>
#include <cuda_fp16.h>
#include <cstdint>

// Shapes: B=16, C=512, H=W=32 -> S=1024, 32 groups (16 ch/group), 8 heads, D=64.
#define BB 16
#define CC 512
#define SS 1024
#define NG 32
#define CPG 16
#define NH 8
#define DK 64
#define QKVC 1536

// hi/lo fp16 split storage for every mma operand (allocation-free rule)
static __device__ __half g_h_h[BB * SS * CC];
static __device__ __half g_h_l[BB * SS * CC];
static __device__ __half g_qkv_h[BB * SS * QKVC];
static __device__ __half g_qkv_l[BB * SS * QKVC];
static __device__ __half g_ao_h[BB * SS * CC];
static __device__ __half g_ao_l[BB * SS * CC];
static __device__ __half g_pw_h[QKVC * CC];
static __device__ __half g_pw_l[QKVC * CC];
static __device__ __half g_ow_h[CC * CC];
static __device__ __half g_ow_l[CC * CC];

// ============================================================================
// helpers
// ============================================================================
__device__ __forceinline__ uint32_t smem_u32(const void* p) {
    uint32_t a;
    asm("{ .reg .u64 t; cvta.to.shared.u64 t, %1; cvt.u32.u64 %0, t; }"
        : "=r"(a) : "l"(p));
    return a;
}

__device__ __forceinline__ void ldm_x4(uint32_t* r, uint32_t addr) {
    asm volatile("ldmatrix.sync.aligned.m8n8.x4.shared.b16 {%0,%1,%2,%3}, [%4];"
                 : "=r"(r[0]), "=r"(r[1]), "=r"(r[2]), "=r"(r[3]) : "r"(addr));
}
__device__ __forceinline__ void ldm_x4_t(uint32_t* r, uint32_t addr) {
    asm volatile("ldmatrix.sync.aligned.m8n8.x4.trans.shared.b16 {%0,%1,%2,%3}, [%4];"
                 : "=r"(r[0]), "=r"(r[1]), "=r"(r[2]), "=r"(r[3]) : "r"(addr));
}

__device__ __forceinline__ void mma_f16(float* c, const uint32_t* a, const uint32_t* b) {
    asm volatile(
        "mma.sync.aligned.m16n8k16.row.col.f32.f16.f16.f32 "
        "{%0,%1,%2,%3}, {%4,%5,%6,%7}, {%8,%9}, {%0,%1,%2,%3};"
        : "+f"(c[0]), "+f"(c[1]), "+f"(c[2]), "+f"(c[3])
        : "r"(a[0]), "r"(a[1]), "r"(a[2]), "r"(a[3]), "r"(b[0]), "r"(b[1]));
}

#define CP_A16(dst, src) \
    asm volatile("cp.async.cg.shared.global [%0], [%1], 16;" :: "r"(dst), "l"(src))
#define CP_COMMIT() asm volatile("cp.async.commit_group;" ::: "memory")
#define CP_WAIT0()  asm volatile("cp.async.wait_group 0;" ::: "memory")
#define CP_WAIT1()  asm volatile("cp.async.wait_group 1;" ::: "memory")
#define CP_WAIT2()  asm volatile("cp.async.wait_group 2;" ::: "memory")

// fp32 pair -> packed fp16 hi + packed fp16 lo
__device__ __forceinline__ void split2(float a, float b, uint32_t& h, uint32_t& l) {
    __half2 hp = __floats2half2_rn(a, b);
    float2 hf = __half22float2(hp);
    __half2 lp = __floats2half2_rn(a - hf.x, b - hf.y);
    h = *reinterpret_cast<uint32_t*>(&hp);
    l = *reinterpret_cast<uint32_t*>(&lp);
}

__device__ __forceinline__ uint32_t pack2(float a, float b) {
    __half2 hp = __floats2half2_rn(a, b);
    return *reinterpret_cast<uint32_t*>(&hp);
}

__device__ __forceinline__ void split4(float4 v, uint2& hv, uint2& lv) {
    split2(v.x, v.y, hv.x, lv.x);
    split2(v.z, v.w, hv.y, lv.y);
}

// ---------------------------------------------------------------------------
// Kernel 0: one-time weight split fp32 -> fp16 hi/lo (both weights, 1 launch)
// ---------------------------------------------------------------------------
__global__ __launch_bounds__(256) void cvt_w2(
    const float* __restrict__ w1, __half* __restrict__ h1,
    __half* __restrict__ l1, int n1,
    const float* __restrict__ w2, __half* __restrict__ h2,
    __half* __restrict__ l2, int n2) {
    int i = blockIdx.x * 256 + threadIdx.x;
    const float* w; __half *hi, *lo;
    if (i < n1) { w = w1; hi = h1; lo = l1; }
    else if (i < n1 + n2) { i -= n1; w = w2; hi = h2; lo = l2; }
    else return;
    float4 v = reinterpret_cast<const float4*>(w)[i];
    uint2 hv, lv;
    split4(v, hv, lv);
    reinterpret_cast<uint2*>(hi)[i] = hv;
    reinterpret_cast<uint2*>(lo)[i] = lv;
}

// ---------------------------------------------------------------------------
// Kernel 1: GroupNorm, write transposed hi/lo fp16 to [B,S,C]
// ---------------------------------------------------------------------------
__global__ __launch_bounds__(256) void gn_kernel(const float* __restrict__ x,
                                                 const float* __restrict__ w,
                                                 const float* __restrict__ bgn) {
    const int b = blockIdx.x >> 5;
    const int g = blockIdx.x & 31;
    const float* xp = x + (size_t)(b * CC + g * CPG) * SS;
    const int t = threadIdx.x;

    float sum = 0.f, sq = 0.f;
    for (int i = t; i < CPG * SS; i += 256) {
        float v = xp[i];
        sum += v;
        sq = fmaf(v, v, sq);
    }
    __shared__ float s1[256], s2[256];
    s1[t] = sum; s2[t] = sq;
    __syncthreads();
    for (int o = 128; o > 0; o >>= 1) {
        if (t < o) { s1[t] += s1[t + o]; s2[t] += s2[t + o]; }
        __syncthreads();
    }
    __shared__ float mean_s, inv_s;
    if (t == 0) {
        const float n_inv = 1.f / (CPG * SS);
        float mean = s1[0] * n_inv;
        float var = s2[0] * n_inv - mean * mean;
        mean_s = mean;
        inv_s = rsqrtf(var + 1e-5f);
    }
    __syncthreads();
    const float mean = mean_s, inv = inv_s;

    const int cl = t & 15;
    const int c = g * CPG + cl;
    const float wc = w[c] * inv;
    const float bc = bgn[c] - mean * wc;
    for (int i = t; i < CPG * SS; i += 256) {
        int s = i >> 4;
        float v = xp[(size_t)cl * SS + s];
        float val = fmaf(v, wc, bc);
        __half hv = __float2half_rn(val);
        __half lv = __float2half_rn(val - __half2float(hv));
        size_t idx = (size_t)(b * SS + s) * CC + c;
        g_h_h[idx] = hv;
        g_h_l[idx] = lv;
    }
}

// ---------------------------------------------------------------------------
// Kernel 2: convert-free mma GEMM, 128x64 CTA tile, 3-stage cp.async ring,
// one __syncthreads per k-chunk, chain-free mma order (3 separate passes).
// ---------------------------------------------------------------------------
#define GP 40                 // fp16 smem pitch (80B rows)
#define GBUF 30720            // Ah 10240 | Al 10240 | Bh 5120 | Bl 5120
#define GEMM_SMEM (3 * GBUF)  // 92160; fp32 stage (<=34816) aliases

template <int MODE>
__global__ __launch_bounds__(256, 2) void mma_gemm(
    const __half* __restrict__ Ah, const __half* __restrict__ Al,
    const __half* __restrict__ Wh, const __half* __restrict__ Wl,
    const float* __restrict__ bias, const float* __restrict__ xres,
    float* __restrict__ outf, __half* __restrict__ oh,
    __half* __restrict__ ol, int Ntot) {
    extern __shared__ __align__(16) char sm[];
    const uint32_t sb = smem_u32(sm);
    const int t = threadIdx.x, w = t >> 5, L = t & 31;
    const int n0 = blockIdx.x * 64;
    const int m0 = blockIdx.y * 128;
    const int wm = w >> 1, wn = w & 1;

    const int arow = L & 15, aseg = L >> 4;
    const int brow = ((L >> 4) << 3) + (L & 7), bcol = ((L >> 3) & 1) * 8;
    const int crow = L >> 2, ccol = (L & 3) * 2;

    float acc[2][4][4] = {};

    auto load_chunk = [&](int kc, int st) {
        const int k0 = kc * 32;
        const uint32_t base = sb + st * GBUF;
#pragma unroll
        for (int rep = 0; rep < 2; ++rep) {
            int c = t + rep * 256;
            int row = c >> 2, ch = c & 3;
            size_t so = (size_t)(m0 + row) * CC + k0 + ch * 8;
            CP_A16(base + row * 80 + ch * 16, Ah + so);
            CP_A16(base + 10240 + row * 80 + ch * 16, Al + so);
        }
        {
            int row = t >> 2, ch = t & 3;
            size_t so = (size_t)(n0 + row) * CC + k0 + ch * 8;
            CP_A16(base + 20480 + row * 80 + ch * 16, Wh + so);
            CP_A16(base + 25600 + row * 80 + ch * 16, Wl + so);
        }
    };

    auto compute = [&](int st) {
        const uint32_t base = sb + st * GBUF;
#pragma unroll
        for (int ks = 0; ks < 2; ++ks) {
            uint32_t ah[2][4], al2[2][4], bh[2][4], bl[2][4];
#pragma unroll
            for (int mt = 0; mt < 2; ++mt) {
                uint32_t off = (uint32_t)(((wm * 32 + mt * 16 + arow) * GP +
                                           ks * 16 + aseg * 8) * 2);
                ldm_x4(ah[mt], base + off);
                ldm_x4(al2[mt], base + 10240 + off);
            }
#pragma unroll
            for (int nt = 0; nt < 2; ++nt) {
                uint32_t off = (uint32_t)(((wn * 32 + nt * 16 + brow) * GP +
                                           ks * 16 + bcol) * 2);
                ldm_x4(bh[nt], base + 20480 + off);
                ldm_x4(bl[nt], base + 25600 + off);
            }
            // chain-free: 3 passes over 8 independent accumulators
#pragma unroll
            for (int mt = 0; mt < 2; ++mt)
#pragma unroll
                for (int n8 = 0; n8 < 4; ++n8)
                    mma_f16(acc[mt][n8], ah[mt], &bh[n8 >> 1][(n8 & 1) * 2]);
#pragma unroll
            for (int mt = 0; mt < 2; ++mt)
#pragma unroll
                for (int n8 = 0; n8 < 4; ++n8)
                    mma_f16(acc[mt][n8], ah[mt], &bl[n8 >> 1][(n8 & 1) * 2]);
#pragma unroll
            for (int mt = 0; mt < 2; ++mt)
#pragma unroll
                for (int n8 = 0; n8 < 4; ++n8)
                    mma_f16(acc[mt][n8], al2[mt], &bh[n8 >> 1][(n8 & 1) * 2]);
        }
    };

    load_chunk(0, 0); CP_COMMIT();
    load_chunk(1, 1); CP_COMMIT();
    int cs = 0, ls = 2;
    for (int kc = 0; kc < 16; ++kc) {
        if (kc < 15) CP_WAIT1(); else CP_WAIT0();
        __syncthreads();
        compute(cs);
        if (kc < 14) { load_chunk(kc + 2, ls); CP_COMMIT(); }
        cs = (cs == 2) ? 0 : cs + 1;
        ls = (ls == 2) ? 0 : ls + 1;
    }
    __syncthreads();   // buffers free before stage aliasing

    float* stage = reinterpret_cast<float*>(sm);
    const int PITCH = (MODE == 0) ? 68 : 65;
#pragma unroll
    for (int mt = 0; mt < 2; ++mt)
#pragma unroll
        for (int n8 = 0; n8 < 4; ++n8) {
            int r = wm * 32 + mt * 16 + crow;
            int c = wn * 32 + n8 * 8 + ccol;
            stage[r * PITCH + c]           = acc[mt][n8][0];
            stage[r * PITCH + c + 1]       = acc[mt][n8][1];
            stage[(r + 8) * PITCH + c]     = acc[mt][n8][2];
            stage[(r + 8) * PITCH + c + 1] = acc[mt][n8][3];
        }
    __syncthreads();

    if (MODE == 0) {
#pragma unroll
        for (int i = 0; i < 8; ++i) {
            int f = t + 256 * i;
            int row = f >> 4, c4 = f & 15;
            float4 v = *(const float4*)&stage[row * 68 + c4 * 4];
            float4 bb = *(const float4*)&bias[n0 + c4 * 4];
            v.x += bb.x; v.y += bb.y; v.z += bb.z; v.w += bb.w;
            uint2 hv, lv;
            split4(v, hv, lv);
            size_t go = (size_t)(m0 + row) * Ntot + n0 + c4 * 4;
            *reinterpret_cast<uint2*>(oh + go) = hv;
            *reinterpret_cast<uint2*>(ol + go) = lv;
        }
    } else {
        const int b = m0 >> 10;
        const int s0 = m0 & 1023;
#pragma unroll
        for (int i = 0; i < 32; ++i) {
            int idx = i * 256 + t;
            int c = idx >> 7, srow = idx & 127;
            size_t gi = (size_t)(b * CC + n0 + c) * SS + s0 + srow;
            outf[gi] = stage[srow * 65 + c] + bias[n0 + c] + xres[gi];
        }
    }
}

// ---------------------------------------------------------------------------
// Kernel 3: flash attention, 128 queries/CTA, warp owns 16 full rows.
// Double-buffered K and V (2 syncs/tile).  QK^T: 3-pass fp16 hi/lo.
// PV: P single fp16 x V hi/lo (2 passes).  exp2-based softmax.
// ---------------------------------------------------------------------------
#define AP 72
#define A_QH 0                    // Q: 128 x 144B (hi), then lo
#define A_QL 18432
#define A_KB 36864                // K stage i at A_KB + i*18432 (hi | lo 9216)
#define A_VB 73728                // V stage i at A_VB + i*18432
#define ATT_SMEM 110592
#define SCL 0.18033688011112042f  // 0.125 * log2(e)

__global__ __launch_bounds__(256, 2) void attn_mma() {
    extern __shared__ __align__(16) char sm[];
    const uint32_t sb = smem_u32(sm);

    const int i0 = blockIdx.x * 128;
    const int bh = blockIdx.y;
    const int b = bh >> 3, h = bh & 7;
    const int t = threadIdx.x, w = t >> 5, L = t & 31;

    const int arow = L & 15, aseg = L >> 4;
    const int brow = ((L >> 4) << 3) + (L & 7), bcol = ((L >> 3) & 1) * 8;
    const int crow = L >> 2, ccol = (L & 3) * 2;

    const __half* qkh = g_qkv_h + (size_t)b * SS * QKVC + h * 192;
    const __half* qkl = g_qkv_l + (size_t)b * SS * QKVC + h * 192;

    auto cp_kv = [&](uint32_t base, const __half* srh, const __half* srl) {
#pragma unroll
        for (int rep = 0; rep < 2; ++rep) {
            int c = t + rep * 256;
            int row = c >> 3, ch = c & 7;
            size_t so = (size_t)row * QKVC + ch * 8;
            CP_A16(base + row * 144 + ch * 16, srh + so);
            CP_A16(base + 9216 + row * 144 + ch * 16, srl + so);
        }
    };

    // prologue groups: 0 = Q+K(0), 1 = V(0), 2 = K(1)
    {
        const __half* sqh = qkh + (size_t)i0 * QKVC;
        const __half* sql = qkl + (size_t)i0 * QKVC;
#pragma unroll
        for (int rep = 0; rep < 4; ++rep) {
            int c = t + rep * 256;
            int row = c >> 3, ch = c & 7;
            size_t so = (size_t)row * QKVC + ch * 8;
            CP_A16(sb + A_QH + row * 144 + ch * 16, sqh + so);
            CP_A16(sb + A_QL + row * 144 + ch * 16, sql + so);
        }
    }
    cp_kv(sb + A_KB, qkh + 64, qkl + 64);
    CP_COMMIT();
    cp_kv(sb + A_VB, qkh + 128, qkl + 128);
    CP_COMMIT();
    cp_kv(sb + A_KB + 18432, qkh + (size_t)64 * QKVC + 64,
          qkl + (size_t)64 * QKVC + 64);
    CP_COMMIT();

    float m0 = -1e30f, m1 = -1e30f, l0 = 0.f, l1 = 0.f;
    float o[8][4] = {};

    for (int j = 0; j < 16; ++j) {
        const uint32_t kbase = sb + A_KB + (j & 1) * 18432;
        const uint32_t vbase = sb + A_VB + (j & 1) * 18432;

        if (j < 15) CP_WAIT2(); else CP_WAIT1();   // K(j) ready
        __syncthreads();

        // ---- S = Q K^T : warp's 16 rows x all 64 keys, chain-free ----
        float sc[8][4] = {};
#pragma unroll
        for (int ks = 0; ks < 4; ++ks) {
            uint32_t aoff = (uint32_t)(((w * 16 + arow) * AP + ks * 16 + aseg * 8) * 2);
            uint32_t ah[4], al_[4];
            ldm_x4(ah, sb + A_QH + aoff);
            ldm_x4(al_, sb + A_QL + aoff);
            uint32_t bh_[4][4], bl_[4][4];
#pragma unroll
            for (int nt = 0; nt < 4; ++nt) {
                uint32_t boff = (uint32_t)(((nt * 16 + brow) * AP +
                                            ks * 16 + bcol) * 2);
                ldm_x4(bh_[nt], kbase + boff);
                ldm_x4(bl_[nt], kbase + 9216 + boff);
            }
#pragma unroll
            for (int n8 = 0; n8 < 8; ++n8)
                mma_f16(sc[n8], ah, &bh_[n8 >> 1][(n8 & 1) * 2]);
#pragma unroll
            for (int n8 = 0; n8 < 8; ++n8)
                mma_f16(sc[n8], ah, &bl_[n8 >> 1][(n8 & 1) * 2]);
#pragma unroll
            for (int n8 = 0; n8 < 8; ++n8)
                mma_f16(sc[n8], al_, &bh_[n8 >> 1][(n8 & 1) * 2]);
        }

        if (j < 15) {             // prefetch V(j+1) into other V buffer
            size_t nb = (size_t)(j + 1) * 64 * QKVC;
            cp_kv(sb + A_VB + ((j + 1) & 1) * 18432, qkh + nb + 128, qkl + nb + 128);
            CP_COMMIT();
        }

        // ---- register softmax (base-2 domain; SCL = 0.125*log2 e) ----
        float mx0 = -1e30f, mx1 = -1e30f;
#pragma unroll
        for (int n8 = 0; n8 < 8; ++n8) {
            sc[n8][0] *= SCL; sc[n8][1] *= SCL;
            sc[n8][2] *= SCL; sc[n8][3] *= SCL;
            mx0 = fmaxf(mx0, fmaxf(sc[n8][0], sc[n8][1]));
            mx1 = fmaxf(mx1, fmaxf(sc[n8][2], sc[n8][3]));
        }
        mx0 = fmaxf(mx0, __shfl_xor_sync(0xffffffff, mx0, 1));
        mx0 = fmaxf(mx0, __shfl_xor_sync(0xffffffff, mx0, 2));
        mx1 = fmaxf(mx1, __shfl_xor_sync(0xffffffff, mx1, 1));
        mx1 = fmaxf(mx1, __shfl_xor_sync(0xffffffff, mx1, 2));

        float mn0 = fmaxf(m0, mx0), mn1 = fmaxf(m1, mx1);
        float a0 = exp2f(m0 - mn0), a1 = exp2f(m1 - mn1);
        m0 = mn0; m1 = mn1;

        uint32_t ph[4][4];
        float s0 = 0.f, s1 = 0.f;
#pragma unroll
        for (int g = 0; g < 4; ++g)
#pragma unroll
            for (int hf = 0; hf < 2; ++hf) {
                int tile = g * 2 + hf;
                float p00 = exp2f(sc[tile][0] - mn0);
                float p01 = exp2f(sc[tile][1] - mn0);
                float p10 = exp2f(sc[tile][2] - mn1);
                float p11 = exp2f(sc[tile][3] - mn1);
                s0 += p00 + p01; s1 += p10 + p11;
                ph[g][hf * 2]     = pack2(p00, p01);
                ph[g][hf * 2 + 1] = pack2(p10, p11);
            }
        s0 += __shfl_xor_sync(0xffffffff, s0, 1);
        s0 += __shfl_xor_sync(0xffffffff, s0, 2);
        s1 += __shfl_xor_sync(0xffffffff, s1, 1);
        s1 += __shfl_xor_sync(0xffffffff, s1, 2);
        l0 = fmaf(l0, a0, s0);
        l1 = fmaf(l1, a1, s1);

#pragma unroll
        for (int n8 = 0; n8 < 8; ++n8) {
            o[n8][0] *= a0; o[n8][1] *= a0;
            o[n8][2] *= a1; o[n8][3] *= a1;
        }

        if (j < 15) CP_WAIT2(); else CP_WAIT0();   // V(j) ready
        __syncthreads();

        // ---- O += P V over all 64 keys: P(single) x V(hi/lo), 2 passes ----
#pragma unroll
        for (int g = 0; g < 4; ++g) {
            int krow = g * 16 + ((L >> 3) & 1) * 8 + (L & 7);
            uint32_t vh[4][4], vl[4][4];
#pragma unroll
            for (int nt = 0; nt < 4; ++nt) {
                int dcol = nt * 16 + (L >> 4) * 8;
                uint32_t boff = (uint32_t)((krow * AP + dcol) * 2);
                ldm_x4_t(vh[nt], vbase + boff);
                ldm_x4_t(vl[nt], vbase + 9216 + boff);
            }
#pragma unroll
            for (int n8 = 0; n8 < 8; ++n8)
                mma_f16(o[n8], ph[g], &vh[n8 >> 1][(n8 & 1) * 2]);
#pragma unroll
            for (int n8 = 0; n8 < 8; ++n8)
                mma_f16(o[n8], ph[g], &vl[n8 >> 1][(n8 & 1) * 2]);
        }

        if (j < 14) {             // prefetch K(j+2) into other K buffer
            size_t nb = (size_t)(j + 2) * 64 * QKVC;
            cp_kv(sb + A_KB + (j & 1) * 18432, qkh + nb + 64, qkl + nb + 64);
            CP_COMMIT();
        }
    }

    // ---- normalize + store hi/lo fp16 (warp owns full rows; no merge) ----
    float inv0 = 1.f / l0, inv1 = 1.f / l1;
#pragma unroll
    for (int n8 = 0; n8 < 8; ++n8) {
        int d = n8 * 8 + ccol;
        uint32_t h0, lo0, h1, lo1;
        split2(o[n8][0] * inv0, o[n8][1] * inv0, h0, lo0);
        split2(o[n8][2] * inv1, o[n8][3] * inv1, h1, lo1);
        size_t g0 = (size_t)(b * SS + i0 + w * 16 + crow) * CC + h * DK + d;
        size_t g1 = g0 + (size_t)8 * CC;
        *reinterpret_cast<uint32_t*>(g_ao_h + g0) = h0;
        *reinterpret_cast<uint32_t*>(g_ao_l + g0) = lo0;
        *reinterpret_cast<uint32_t*>(g_ao_h + g1) = h1;
        *reinterpret_cast<uint32_t*>(g_ao_l + g1) = lo1;
    }
}

// ---------------------------------------------------------------------------
extern "C" void kernel_launch(void* const* d_in, const int* in_sizes, int n_in,
                              void* d_out, int out_size) {
    const float* x = (const float*)d_in[0];
    const float* gn_w = (const float*)d_in[1];
    const float* gn_b = (const float*)d_in[2];
    const float* proj_w = (const float*)d_in[3];
    const float* proj_b = (const float*)d_in[4];
    const float* out_w = (const float*)d_in[5];
    const float* out_b = (const float*)d_in[6];
    float* out = (float*)d_out;

    __half *d_hh, *d_hl, *d_qh, *d_ql, *d_aoh, *d_aol;
    __half *d_pwh, *d_pwl, *d_owh, *d_owl;
    cudaGetSymbolAddress((void**)&d_hh, g_h_h);
    cudaGetSymbolAddress((void**)&d_hl, g_h_l);
    cudaGetSymbolAddress((void**)&d_qh, g_qkv_h);
    cudaGetSymbolAddress((void**)&d_ql, g_qkv_l);
    cudaGetSymbolAddress((void**)&d_aoh, g_ao_h);
    cudaGetSymbolAddress((void**)&d_aol, g_ao_l);
    cudaGetSymbolAddress((void**)&d_pwh, g_pw_h);
    cudaGetSymbolAddress((void**)&d_pwl, g_pw_l);
    cudaGetSymbolAddress((void**)&d_owh, g_ow_h);
    cudaGetSymbolAddress((void**)&d_owl, g_ow_l);

    cudaFuncSetAttribute(mma_gemm<0>, cudaFuncAttributeMaxDynamicSharedMemorySize, GEMM_SMEM);
    cudaFuncSetAttribute(mma_gemm<1>, cudaFuncAttributeMaxDynamicSharedMemorySize, GEMM_SMEM);
    cudaFuncSetAttribute(attn_mma, cudaFuncAttributeMaxDynamicSharedMemorySize, ATT_SMEM);

    const int n1 = QKVC * CC / 4, n2 = CC * CC / 4;
    cvt_w2<<<(n1 + n2 + 255) / 256, 256>>>(proj_w, d_pwh, d_pwl, n1,
                                           out_w, d_owh, d_owl, n2);
    gn_kernel<<<BB * NG, 256>>>(x, gn_w, gn_b);

    mma_gemm<0><<<dim3(QKVC / 64, BB * SS / 128), 256, GEMM_SMEM>>>(
        d_hh, d_hl, d_pwh, d_pwl, proj_b, nullptr, nullptr, d_qh, d_ql, QKVC);

    attn_mma<<<dim3(SS / 128, BB * NH), 256, ATT_SMEM>>>();

    mma_gemm<1><<<dim3(CC / 64, BB * SS / 128), 256, GEMM_SMEM>>>(
        d_aoh, d_aol, d_owh, d_owl, out_b, x, out, nullptr, nullptr, CC);
}

// round 11
// speedup vs baseline: 4.3267x; 1.3069x over previous
#include <cuda_runtime.h>
#include <cuda_fp16.h>
#include <cstdint>

// Shapes: B=16, C=512, H=W=32 -> S=1024, 32 groups (16 ch/group), 8 heads, D=64.
#define BB 16
#define CC 512
#define SS 1024
#define NG 32
#define CPG 16
#define NH 8
#define DK 64
#define QKVC 1536

// fp16 storage (hi/lo split only where error does NOT dilute)
static __device__ __half g_h_h[BB * SS * CC];        // gn out: single fp16
static __device__ __half g_qkv_h[BB * SS * QKVC];
static __device__ __half g_qkv_l[BB * SS * QKVC];    // lo used by Q only
static __device__ __half g_ao_h[BB * SS * CC];
static __device__ __half g_ao_l[BB * SS * CC];
static __device__ __half g_pw_h[QKVC * CC];
static __device__ __half g_pw_l[QKVC * CC];
static __device__ __half g_ow_h[CC * CC];
static __device__ __half g_ow_l[CC * CC];

// ============================================================================
// helpers
// ============================================================================
__device__ __forceinline__ uint32_t smem_u32(const void* p) {
    uint32_t a;
    asm("{ .reg .u64 t; cvta.to.shared.u64 t, %1; cvt.u32.u64 %0, t; }"
        : "=r"(a) : "l"(p));
    return a;
}

__device__ __forceinline__ void ldm_x4(uint32_t* r, uint32_t addr) {
    asm volatile("ldmatrix.sync.aligned.m8n8.x4.shared.b16 {%0,%1,%2,%3}, [%4];"
                 : "=r"(r[0]), "=r"(r[1]), "=r"(r[2]), "=r"(r[3]) : "r"(addr));
}
__device__ __forceinline__ void ldm_x4_t(uint32_t* r, uint32_t addr) {
    asm volatile("ldmatrix.sync.aligned.m8n8.x4.trans.shared.b16 {%0,%1,%2,%3}, [%4];"
                 : "=r"(r[0]), "=r"(r[1]), "=r"(r[2]), "=r"(r[3]) : "r"(addr));
}

__device__ __forceinline__ void mma_f16(float* c, const uint32_t* a, const uint32_t* b) {
    asm volatile(
        "mma.sync.aligned.m16n8k16.row.col.f32.f16.f16.f32 "
        "{%0,%1,%2,%3}, {%4,%5,%6,%7}, {%8,%9}, {%0,%1,%2,%3};"
        : "+f"(c[0]), "+f"(c[1]), "+f"(c[2]), "+f"(c[3])
        : "r"(a[0]), "r"(a[1]), "r"(a[2]), "r"(a[3]), "r"(b[0]), "r"(b[1]));
}

#define CP_A16(dst, src) \
    asm volatile("cp.async.cg.shared.global [%0], [%1], 16;" :: "r"(dst), "l"(src))
#define CP_COMMIT() asm volatile("cp.async.commit_group;" ::: "memory")
#define CP_WAIT0()  asm volatile("cp.async.wait_group 0;" ::: "memory")
#define CP_WAIT1()  asm volatile("cp.async.wait_group 1;" ::: "memory")
#define CP_WAIT2()  asm volatile("cp.async.wait_group 2;" ::: "memory")

// fp32 pair -> packed fp16 hi + packed fp16 lo
__device__ __forceinline__ void split2(float a, float b, uint32_t& h, uint32_t& l) {
    __half2 hp = __floats2half2_rn(a, b);
    float2 hf = __half22float2(hp);
    __half2 lp = __floats2half2_rn(a - hf.x, b - hf.y);
    h = *reinterpret_cast<uint32_t*>(&hp);
    l = *reinterpret_cast<uint32_t*>(&lp);
}

__device__ __forceinline__ uint32_t pack2(float a, float b) {
    __half2 hp = __floats2half2_rn(a, b);
    return *reinterpret_cast<uint32_t*>(&hp);
}

__device__ __forceinline__ void split4(float4 v, uint2& hv, uint2& lv) {
    split2(v.x, v.y, hv.x, lv.x);
    split2(v.z, v.w, hv.y, lv.y);
}

// ---------------------------------------------------------------------------
// Kernel 0: one-time weight split fp32 -> fp16 hi/lo (both weights, 1 launch)
// ---------------------------------------------------------------------------
__global__ __launch_bounds__(256) void cvt_w2(
    const float* __restrict__ w1, __half* __restrict__ h1,
    __half* __restrict__ l1, int n1,
    const float* __restrict__ w2, __half* __restrict__ h2,
    __half* __restrict__ l2, int n2) {
    int i = blockIdx.x * 256 + threadIdx.x;
    const float* w; __half *hi, *lo;
    if (i < n1) { w = w1; hi = h1; lo = l1; }
    else if (i < n1 + n2) { i -= n1; w = w2; hi = h2; lo = l2; }
    else return;
    float4 v = reinterpret_cast<const float4*>(w)[i];
    uint2 hv, lv;
    split4(v, hv, lv);
    reinterpret_cast<uint2*>(hi)[i] = hv;
    reinterpret_cast<uint2*>(lo)[i] = lv;
}

// ---------------------------------------------------------------------------
// Kernel 1: GroupNorm, write transposed single-fp16 to [B,S,C]
// ---------------------------------------------------------------------------
__global__ __launch_bounds__(256) void gn_kernel(const float* __restrict__ x,
                                                 const float* __restrict__ w,
                                                 const float* __restrict__ bgn) {
    const int b = blockIdx.x >> 5;
    const int g = blockIdx.x & 31;
    const float* xp = x + (size_t)(b * CC + g * CPG) * SS;
    const int t = threadIdx.x;

    float sum = 0.f, sq = 0.f;
    for (int i = t; i < CPG * SS; i += 256) {
        float v = xp[i];
        sum += v;
        sq = fmaf(v, v, sq);
    }
    __shared__ float s1[256], s2[256];
    s1[t] = sum; s2[t] = sq;
    __syncthreads();
    for (int o = 128; o > 0; o >>= 1) {
        if (t < o) { s1[t] += s1[t + o]; s2[t] += s2[t + o]; }
        __syncthreads();
    }
    __shared__ float mean_s, inv_s;
    if (t == 0) {
        const float n_inv = 1.f / (CPG * SS);
        float mean = s1[0] * n_inv;
        float var = s2[0] * n_inv - mean * mean;
        mean_s = mean;
        inv_s = rsqrtf(var + 1e-5f);
    }
    __syncthreads();
    const float mean = mean_s, inv = inv_s;

    const int cl = t & 15;
    const int c = g * CPG + cl;
    const float wc = w[c] * inv;
    const float bc = bgn[c] - mean * wc;
    for (int i = t; i < CPG * SS; i += 256) {
        int s = i >> 4;
        float v = xp[(size_t)cl * SS + s];
        g_h_h[(size_t)(b * SS + s) * CC + c] = __float2half_rn(fmaf(v, wc, bc));
    }
}

// ---------------------------------------------------------------------------
// Kernel 2: mma GEMM, 128x64 CTA tile, 3-stage cp.async ring.
// MODE 0 (qkv): A single fp16 x W hi/lo -> 2 passes; epi +bias, hi/lo out.
// MODE 1 (out): A hi/lo x W hi/lo -> 3 passes; epi +bias+residual, fp32 CM.
// ---------------------------------------------------------------------------
#define GP 40                 // fp16 smem pitch (80B rows)

template <int MODE>
__global__ __launch_bounds__(256, 2) void mma_gemm(
    const __half* __restrict__ Ah, const __half* __restrict__ Al,
    const __half* __restrict__ Wh, const __half* __restrict__ Wl,
    const float* __restrict__ bias, const float* __restrict__ xres,
    float* __restrict__ outf, __half* __restrict__ oh,
    __half* __restrict__ ol, int Ntot) {
    constexpr int GBUF = (MODE == 0) ? 20480 : 30720;
    constexpr int W_OFF = (MODE == 0) ? 10240 : 20480;   // Wh offset; Wl at +5120
    extern __shared__ __align__(16) char sm[];
    const uint32_t sb = smem_u32(sm);
    const int t = threadIdx.x, w = t >> 5, L = t & 31;
    const int n0 = blockIdx.x * 64;
    const int m0 = blockIdx.y * 128;
    const int wm = w >> 1, wn = w & 1;

    const int arow = L & 15, aseg = L >> 4;
    const int brow = ((L >> 4) << 3) + (L & 7), bcol = ((L >> 3) & 1) * 8;
    const int crow = L >> 2, ccol = (L & 3) * 2;

    float acc[2][4][4] = {};

    auto load_chunk = [&](int kc, int st) {
        const int k0 = kc * 32;
        const uint32_t base = sb + st * GBUF;
#pragma unroll
        for (int rep = 0; rep < 2; ++rep) {
            int c = t + rep * 256;
            int row = c >> 2, ch = c & 3;
            size_t so = (size_t)(m0 + row) * CC + k0 + ch * 8;
            CP_A16(base + row * 80 + ch * 16, Ah + so);
            if (MODE == 1) CP_A16(base + 10240 + row * 80 + ch * 16, Al + so);
        }
        {
            int row = t >> 2, ch = t & 3;
            size_t so = (size_t)(n0 + row) * CC + k0 + ch * 8;
            CP_A16(base + W_OFF + row * 80 + ch * 16, Wh + so);
            CP_A16(base + W_OFF + 5120 + row * 80 + ch * 16, Wl + so);
        }
    };

    auto compute = [&](int st) {
        const uint32_t base = sb + st * GBUF;
#pragma unroll
        for (int ks = 0; ks < 2; ++ks) {
            uint32_t ah[2][4], al2[2][4], bh[2][4], bl[2][4];
#pragma unroll
            for (int mt = 0; mt < 2; ++mt) {
                uint32_t off = (uint32_t)(((wm * 32 + mt * 16 + arow) * GP +
                                           ks * 16 + aseg * 8) * 2);
                ldm_x4(ah[mt], base + off);
                if (MODE == 1) ldm_x4(al2[mt], base + 10240 + off);
            }
#pragma unroll
            for (int nt = 0; nt < 2; ++nt) {
                uint32_t off = (uint32_t)(((wn * 32 + nt * 16 + brow) * GP +
                                           ks * 16 + bcol) * 2);
                ldm_x4(bh[nt], base + W_OFF + off);
                ldm_x4(bl[nt], base + W_OFF + 5120 + off);
            }
#pragma unroll
            for (int mt = 0; mt < 2; ++mt)
#pragma unroll
                for (int n8 = 0; n8 < 4; ++n8)
                    mma_f16(acc[mt][n8], ah[mt], &bh[n8 >> 1][(n8 & 1) * 2]);
#pragma unroll
            for (int mt = 0; mt < 2; ++mt)
#pragma unroll
                for (int n8 = 0; n8 < 4; ++n8)
                    mma_f16(acc[mt][n8], ah[mt], &bl[n8 >> 1][(n8 & 1) * 2]);
            if (MODE == 1) {
#pragma unroll
                for (int mt = 0; mt < 2; ++mt)
#pragma unroll
                    for (int n8 = 0; n8 < 4; ++n8)
                        mma_f16(acc[mt][n8], al2[mt], &bh[n8 >> 1][(n8 & 1) * 2]);
            }
        }
    };

    load_chunk(0, 0); CP_COMMIT();
    load_chunk(1, 1); CP_COMMIT();
    int cs = 0, ls = 2;
    for (int kc = 0; kc < 16; ++kc) {
        if (kc < 15) CP_WAIT1(); else CP_WAIT0();
        __syncthreads();
        compute(cs);
        if (kc < 14) { load_chunk(kc + 2, ls); CP_COMMIT(); }
        cs = (cs == 2) ? 0 : cs + 1;
        ls = (ls == 2) ? 0 : ls + 1;
    }
    __syncthreads();   // buffers free before stage aliasing

    float* stage = reinterpret_cast<float*>(sm);
    const int PITCH = (MODE == 0) ? 68 : 65;
#pragma unroll
    for (int mt = 0; mt < 2; ++mt)
#pragma unroll
        for (int n8 = 0; n8 < 4; ++n8) {
            int r = wm * 32 + mt * 16 + crow;
            int c = wn * 32 + n8 * 8 + ccol;
            stage[r * PITCH + c]           = acc[mt][n8][0];
            stage[r * PITCH + c + 1]       = acc[mt][n8][1];
            stage[(r + 8) * PITCH + c]     = acc[mt][n8][2];
            stage[(r + 8) * PITCH + c + 1] = acc[mt][n8][3];
        }
    __syncthreads();

    if (MODE == 0) {
#pragma unroll
        for (int i = 0; i < 8; ++i) {
            int f = t + 256 * i;
            int row = f >> 4, c4 = f & 15;
            float4 v = *(const float4*)&stage[row * 68 + c4 * 4];
            float4 bb = *(const float4*)&bias[n0 + c4 * 4];
            v.x += bb.x; v.y += bb.y; v.z += bb.z; v.w += bb.w;
            uint2 hv, lv;
            split4(v, hv, lv);
            size_t go = (size_t)(m0 + row) * Ntot + n0 + c4 * 4;
            *reinterpret_cast<uint2*>(oh + go) = hv;
            *reinterpret_cast<uint2*>(ol + go) = lv;
        }
    } else {
        const int b = m0 >> 10;
        const int s0 = m0 & 1023;
#pragma unroll
        for (int i = 0; i < 32; ++i) {
            int idx = i * 256 + t;
            int c = idx >> 7, srow = idx & 127;
            size_t gi = (size_t)(b * CC + n0 + c) * SS + s0 + srow;
            outf[gi] = stage[srow * 65 + c] + bias[n0 + c] + xres[gi];
        }
    }
}

// ---------------------------------------------------------------------------
// Kernel 3: flash attention, 128 queries/CTA, warp owns 16 full rows.
// Q hi/lo; K,V single fp16 (diluting errors).  QK^T 2-pass, PV 1-pass.
// Double-buffered K and V.  exp2 softmax.
// ---------------------------------------------------------------------------
#define AP 72
#define A_QH 0                    // Q: 128 x 144B (hi), then lo
#define A_QL 18432
#define A_KB 36864                // K stage i at A_KB + i*9216
#define A_VB 55296                // V stage i at A_VB + i*9216
#define ATT_SMEM 73728
#define SCL 0.18033688011112042f  // 0.125 * log2(e)

__global__ __launch_bounds__(256, 2) void attn_mma() {
    extern __shared__ __align__(16) char sm[];
    const uint32_t sb = smem_u32(sm);

    const int i0 = blockIdx.x * 128;
    const int bh = blockIdx.y;
    const int b = bh >> 3, h = bh & 7;
    const int t = threadIdx.x, w = t >> 5, L = t & 31;

    const int arow = L & 15, aseg = L >> 4;
    const int brow = ((L >> 4) << 3) + (L & 7), bcol = ((L >> 3) & 1) * 8;
    const int crow = L >> 2, ccol = (L & 3) * 2;

    const __half* qkh = g_qkv_h + (size_t)b * SS * QKVC + h * 192;
    const __half* qkl = g_qkv_l + (size_t)b * SS * QKVC + h * 192;

    // single-plane 64x64 tile load (K hi or V hi)
    auto cp_kv = [&](uint32_t base, const __half* src) {
#pragma unroll
        for (int rep = 0; rep < 2; ++rep) {
            int c = t + rep * 256;
            int row = c >> 3, ch = c & 7;
            CP_A16(base + row * 144 + ch * 16, src + (size_t)row * QKVC + ch * 8);
        }
    };

    // prologue groups: 0 = Q(hi+lo)+K(0), 1 = V(0), 2 = K(1)
    {
        const __half* sqh = qkh + (size_t)i0 * QKVC;
        const __half* sql = qkl + (size_t)i0 * QKVC;
#pragma unroll
        for (int rep = 0; rep < 4; ++rep) {
            int c = t + rep * 256;
            int row = c >> 3, ch = c & 7;
            size_t so = (size_t)row * QKVC + ch * 8;
            CP_A16(sb + A_QH + row * 144 + ch * 16, sqh + so);
            CP_A16(sb + A_QL + row * 144 + ch * 16, sql + so);
        }
    }
    cp_kv(sb + A_KB, qkh + 64);
    CP_COMMIT();
    cp_kv(sb + A_VB, qkh + 128);
    CP_COMMIT();
    cp_kv(sb + A_KB + 9216, qkh + (size_t)64 * QKVC + 64);
    CP_COMMIT();

    float m0 = -1e30f, m1 = -1e30f, l0 = 0.f, l1 = 0.f;
    float o[8][4] = {};

    for (int j = 0; j < 16; ++j) {
        const uint32_t kbase = sb + A_KB + (j & 1) * 9216;
        const uint32_t vbase = sb + A_VB + (j & 1) * 9216;

        if (j < 15) CP_WAIT2(); else CP_WAIT1();   // K(j) ready
        __syncthreads();

        // ---- S = Q K^T : 2 passes ((Qh + Ql) x Kh) ----
        float sc[8][4] = {};
#pragma unroll
        for (int ks = 0; ks < 4; ++ks) {
            uint32_t aoff = (uint32_t)(((w * 16 + arow) * AP + ks * 16 + aseg * 8) * 2);
            uint32_t ah[4], al_[4];
            ldm_x4(ah, sb + A_QH + aoff);
            ldm_x4(al_, sb + A_QL + aoff);
            uint32_t bh_[4][4];
#pragma unroll
            for (int nt = 0; nt < 4; ++nt) {
                uint32_t boff = (uint32_t)(((nt * 16 + brow) * AP +
                                            ks * 16 + bcol) * 2);
                ldm_x4(bh_[nt], kbase + boff);
            }
#pragma unroll
            for (int n8 = 0; n8 < 8; ++n8)
                mma_f16(sc[n8], ah, &bh_[n8 >> 1][(n8 & 1) * 2]);
#pragma unroll
            for (int n8 = 0; n8 < 8; ++n8)
                mma_f16(sc[n8], al_, &bh_[n8 >> 1][(n8 & 1) * 2]);
        }

        if (j < 15) {             // prefetch V(j+1) into other V buffer
            size_t nb = (size_t)(j + 1) * 64 * QKVC;
            cp_kv(sb + A_VB + ((j + 1) & 1) * 9216, qkh + nb + 128);
            CP_COMMIT();
        }

        // ---- register softmax (base-2 domain; SCL = 0.125*log2 e) ----
        float mx0 = -1e30f, mx1 = -1e30f;
#pragma unroll
        for (int n8 = 0; n8 < 8; ++n8) {
            sc[n8][0] *= SCL; sc[n8][1] *= SCL;
            sc[n8][2] *= SCL; sc[n8][3] *= SCL;
            mx0 = fmaxf(mx0, fmaxf(sc[n8][0], sc[n8][1]));
            mx1 = fmaxf(mx1, fmaxf(sc[n8][2], sc[n8][3]));
        }
        mx0 = fmaxf(mx0, __shfl_xor_sync(0xffffffff, mx0, 1));
        mx0 = fmaxf(mx0, __shfl_xor_sync(0xffffffff, mx0, 2));
        mx1 = fmaxf(mx1, __shfl_xor_sync(0xffffffff, mx1, 1));
        mx1 = fmaxf(mx1, __shfl_xor_sync(0xffffffff, mx1, 2));

        float mn0 = fmaxf(m0, mx0), mn1 = fmaxf(m1, mx1);
        float a0 = exp2f(m0 - mn0), a1 = exp2f(m1 - mn1);
        m0 = mn0; m1 = mn1;

        uint32_t ph[4][4];
        float s0 = 0.f, s1 = 0.f;
#pragma unroll
        for (int g = 0; g < 4; ++g)
#pragma unroll
            for (int hf = 0; hf < 2; ++hf) {
                int tile = g * 2 + hf;
                float p00 = exp2f(sc[tile][0] - mn0);
                float p01 = exp2f(sc[tile][1] - mn0);
                float p10 = exp2f(sc[tile][2] - mn1);
                float p11 = exp2f(sc[tile][3] - mn1);
                s0 += p00 + p01; s1 += p10 + p11;
                ph[g][hf * 2]     = pack2(p00, p01);
                ph[g][hf * 2 + 1] = pack2(p10, p11);
            }
        s0 += __shfl_xor_sync(0xffffffff, s0, 1);
        s0 += __shfl_xor_sync(0xffffffff, s0, 2);
        s1 += __shfl_xor_sync(0xffffffff, s1, 1);
        s1 += __shfl_xor_sync(0xffffffff, s1, 2);
        l0 = fmaf(l0, a0, s0);
        l1 = fmaf(l1, a1, s1);

#pragma unroll
        for (int n8 = 0; n8 < 8; ++n8) {
            o[n8][0] *= a0; o[n8][1] *= a0;
            o[n8][2] *= a1; o[n8][3] *= a1;
        }

        if (j < 15) CP_WAIT2(); else CP_WAIT0();   // V(j) ready
        __syncthreads();

        // ---- O += P V : single pass over V hi ----
#pragma unroll
        for (int g = 0; g < 4; ++g) {
            int krow = g * 16 + ((L >> 3) & 1) * 8 + (L & 7);
            uint32_t vh[4][4];
#pragma unroll
            for (int nt = 0; nt < 4; ++nt) {
                int dcol = nt * 16 + (L >> 4) * 8;
                ldm_x4_t(vh[nt], vbase + (uint32_t)((krow * AP + dcol) * 2));
            }
#pragma unroll
            for (int n8 = 0; n8 < 8; ++n8)
                mma_f16(o[n8], ph[g], &vh[n8 >> 1][(n8 & 1) * 2]);
        }

        if (j < 14) {             // prefetch K(j+2) into other K buffer
            size_t nb = (size_t)(j + 2) * 64 * QKVC;
            cp_kv(sb + A_KB + (j & 1) * 9216, qkh + nb + 64);
            CP_COMMIT();
        }
    }

    // ---- normalize + store hi/lo fp16 (ao feeds 3-pass out GEMM) ----
    float inv0 = 1.f / l0, inv1 = 1.f / l1;
#pragma unroll
    for (int n8 = 0; n8 < 8; ++n8) {
        int d = n8 * 8 + ccol;
        uint32_t h0, lo0, h1, lo1;
        split2(o[n8][0] * inv0, o[n8][1] * inv0, h0, lo0);
        split2(o[n8][2] * inv1, o[n8][3] * inv1, h1, lo1);
        size_t g0 = (size_t)(b * SS + i0 + w * 16 + crow) * CC + h * DK + d;
        size_t g1 = g0 + (size_t)8 * CC;
        *reinterpret_cast<uint32_t*>(g_ao_h + g0) = h0;
        *reinterpret_cast<uint32_t*>(g_ao_l + g0) = lo0;
        *reinterpret_cast<uint32_t*>(g_ao_h + g1) = h1;
        *reinterpret_cast<uint32_t*>(g_ao_l + g1) = lo1;
    }
}

// ---------------------------------------------------------------------------
extern "C" void kernel_launch(void* const* d_in, const int* in_sizes, int n_in,
                              void* d_out, int out_size) {
    const float* x = (const float*)d_in[0];
    const float* gn_w = (const float*)d_in[1];
    const float* gn_b = (const float*)d_in[2];
    const float* proj_w = (const float*)d_in[3];
    const float* proj_b = (const float*)d_in[4];
    const float* out_w = (const float*)d_in[5];
    const float* out_b = (const float*)d_in[6];
    float* out = (float*)d_out;

    __half *d_hh, *d_qh, *d_ql, *d_aoh, *d_aol;
    __half *d_pwh, *d_pwl, *d_owh, *d_owl;
    cudaGetSymbolAddress((void**)&d_hh, g_h_h);
    cudaGetSymbolAddress((void**)&d_qh, g_qkv_h);
    cudaGetSymbolAddress((void**)&d_ql, g_qkv_l);
    cudaGetSymbolAddress((void**)&d_aoh, g_ao_h);
    cudaGetSymbolAddress((void**)&d_aol, g_ao_l);
    cudaGetSymbolAddress((void**)&d_pwh, g_pw_h);
    cudaGetSymbolAddress((void**)&d_pwl, g_pw_l);
    cudaGetSymbolAddress((void**)&d_owh, g_ow_h);
    cudaGetSymbolAddress((void**)&d_owl, g_ow_l);

    const int SMEM0 = 3 * 20480;
    const int SMEM1 = 3 * 30720;
    cudaFuncSetAttribute(mma_gemm<0>, cudaFuncAttributeMaxDynamicSharedMemorySize, SMEM0);
    cudaFuncSetAttribute(mma_gemm<1>, cudaFuncAttributeMaxDynamicSharedMemorySize, SMEM1);
    cudaFuncSetAttribute(attn_mma, cudaFuncAttributeMaxDynamicSharedMemorySize, ATT_SMEM);

    const int n1 = QKVC * CC / 4, n2 = CC * CC / 4;
    cvt_w2<<<(n1 + n2 + 255) / 256, 256>>>(proj_w, d_pwh, d_pwl, n1,
                                           out_w, d_owh, d_owl, n2);
    gn_kernel<<<BB * NG, 256>>>(x, gn_w, gn_b);

    mma_gemm<0><<<dim3(QKVC / 64, BB * SS / 128), 256, SMEM0>>>(
        d_hh, nullptr, d_pwh, d_pwl, proj_b, nullptr, nullptr, d_qh, d_ql, QKVC);

    attn_mma<<<dim3(SS / 128, BB * NH), 256, ATT_SMEM>>>();

    mma_gemm<1><<<dim3(CC / 64, BB * SS / 128), 256, SMEM1>>>(
        d_aoh, d_aol, d_owh, d_owl, out_b, x, out, nullptr, nullptr, CC);
}

// round 12
// speedup vs baseline: 5.2052x; 1.2031x over previous
#include <cuda_runtime.h>
#include <cuda_fp16.h>
#include <cstdint>

// Shapes: B=16, C=512, H=W=32 -> S=1024, 32 groups (16 ch/group), 8 heads, D=64.
#define BB 16
#define CC 512
#define SS 1024
#define NG 32
#define CPG 16
#define NH 8
#define DK 64
#define QKVC 1536

// fp16 storage (hi/lo split only where error does NOT dilute)
static __device__ __half g_h_h[BB * SS * CC];        // gn out: single fp16
static __device__ __half g_qkv_h[BB * SS * QKVC];    // qkv: single fp16
static __device__ __half g_ao_h[BB * SS * CC];       // ao: hi/lo (undiluted path)
static __device__ __half g_ao_l[BB * SS * CC];
static __device__ __half g_pw_h[QKVC * CC];          // proj_w: single fp16
static __device__ __half g_ow_h[CC * CC];            // out_w: hi/lo
static __device__ __half g_ow_l[CC * CC];

// ============================================================================
// helpers
// ============================================================================
__device__ __forceinline__ uint32_t smem_u32(const void* p) {
    uint32_t a;
    asm("{ .reg .u64 t; cvta.to.shared.u64 t, %1; cvt.u32.u64 %0, t; }"
        : "=r"(a) : "l"(p));
    return a;
}

__device__ __forceinline__ void ldm_x4(uint32_t* r, uint32_t addr) {
    asm volatile("ldmatrix.sync.aligned.m8n8.x4.shared.b16 {%0,%1,%2,%3}, [%4];"
                 : "=r"(r[0]), "=r"(r[1]), "=r"(r[2]), "=r"(r[3]) : "r"(addr));
}
__device__ __forceinline__ void ldm_x4_t(uint32_t* r, uint32_t addr) {
    asm volatile("ldmatrix.sync.aligned.m8n8.x4.trans.shared.b16 {%0,%1,%2,%3}, [%4];"
                 : "=r"(r[0]), "=r"(r[1]), "=r"(r[2]), "=r"(r[3]) : "r"(addr));
}

__device__ __forceinline__ void mma_f16(float* c, const uint32_t* a, const uint32_t* b) {
    asm volatile(
        "mma.sync.aligned.m16n8k16.row.col.f32.f16.f16.f32 "
        "{%0,%1,%2,%3}, {%4,%5,%6,%7}, {%8,%9}, {%0,%1,%2,%3};"
        : "+f"(c[0]), "+f"(c[1]), "+f"(c[2]), "+f"(c[3])
        : "r"(a[0]), "r"(a[1]), "r"(a[2]), "r"(a[3]), "r"(b[0]), "r"(b[1]));
}

#define CP_A16(dst, src) \
    asm volatile("cp.async.cg.shared.global [%0], [%1], 16;" :: "r"(dst), "l"(src))
#define CP_COMMIT() asm volatile("cp.async.commit_group;" ::: "memory")
#define CP_WAIT0()  asm volatile("cp.async.wait_group 0;" ::: "memory")
#define CP_WAIT1()  asm volatile("cp.async.wait_group 1;" ::: "memory")
#define CP_WAIT2()  asm volatile("cp.async.wait_group 2;" ::: "memory")

// fp32 pair -> packed fp16 hi + packed fp16 lo
__device__ __forceinline__ void split2(float a, float b, uint32_t& h, uint32_t& l) {
    __half2 hp = __floats2half2_rn(a, b);
    float2 hf = __half22float2(hp);
    __half2 lp = __floats2half2_rn(a - hf.x, b - hf.y);
    h = *reinterpret_cast<uint32_t*>(&hp);
    l = *reinterpret_cast<uint32_t*>(&lp);
}

__device__ __forceinline__ uint32_t pack2(float a, float b) {
    __half2 hp = __floats2half2_rn(a, b);
    return *reinterpret_cast<uint32_t*>(&hp);
}

// ---------------------------------------------------------------------------
// Kernel 0: one-time weight conversion: proj_w -> single fp16; out_w -> hi/lo
// ---------------------------------------------------------------------------
__global__ __launch_bounds__(256) void cvt_w2(
    const float* __restrict__ w1, __half* __restrict__ h1, int n1,
    const float* __restrict__ w2, __half* __restrict__ h2,
    __half* __restrict__ l2, int n2) {
    int i = blockIdx.x * 256 + threadIdx.x;
    if (i < n1) {
        float4 v = reinterpret_cast<const float4*>(w1)[i];
        uint2 hv = make_uint2(pack2(v.x, v.y), pack2(v.z, v.w));
        reinterpret_cast<uint2*>(h1)[i] = hv;
    } else if (i < n1 + n2) {
        i -= n1;
        float4 v = reinterpret_cast<const float4*>(w2)[i];
        uint2 hv, lv;
        split2(v.x, v.y, hv.x, lv.x);
        split2(v.z, v.w, hv.y, lv.y);
        reinterpret_cast<uint2*>(h2)[i] = hv;
        reinterpret_cast<uint2*>(l2)[i] = lv;
    }
}

// ---------------------------------------------------------------------------
// Kernel 1: GroupNorm, write transposed single-fp16 to [B,S,C]
// ---------------------------------------------------------------------------
__global__ __launch_bounds__(256) void gn_kernel(const float* __restrict__ x,
                                                 const float* __restrict__ w,
                                                 const float* __restrict__ bgn) {
    const int b = blockIdx.x >> 5;
    const int g = blockIdx.x & 31;
    const float* xp = x + (size_t)(b * CC + g * CPG) * SS;
    const int t = threadIdx.x;

    float sum = 0.f, sq = 0.f;
    for (int i = t; i < CPG * SS; i += 256) {
        float v = xp[i];
        sum += v;
        sq = fmaf(v, v, sq);
    }
    __shared__ float s1[256], s2[256];
    s1[t] = sum; s2[t] = sq;
    __syncthreads();
    for (int o = 128; o > 0; o >>= 1) {
        if (t < o) { s1[t] += s1[t + o]; s2[t] += s2[t + o]; }
        __syncthreads();
    }
    __shared__ float mean_s, inv_s;
    if (t == 0) {
        const float n_inv = 1.f / (CPG * SS);
        float mean = s1[0] * n_inv;
        float var = s2[0] * n_inv - mean * mean;
        mean_s = mean;
        inv_s = rsqrtf(var + 1e-5f);
    }
    __syncthreads();
    const float mean = mean_s, inv = inv_s;

    const int cl = t & 15;
    const int c = g * CPG + cl;
    const float wc = w[c] * inv;
    const float bc = bgn[c] - mean * wc;
    for (int i = t; i < CPG * SS; i += 256) {
        int s = i >> 4;
        float v = xp[(size_t)cl * SS + s];
        g_h_h[(size_t)(b * SS + s) * CC + c] = __float2half_rn(fmaf(v, wc, bc));
    }
}

// ---------------------------------------------------------------------------
// Kernel 2: mma GEMM, 128x64 CTA tile, 3-stage cp.async ring.
// MODE 0 (qkv): pure fp16, 1 pass; epi +bias, single fp16 out.
// MODE 1 (out): A hi/lo x W hi/lo, 3 passes; epi +bias+residual, fp32 CM.
// ---------------------------------------------------------------------------
#define GP 40                 // fp16 smem pitch (80B rows)

template <int MODE>
__global__ __launch_bounds__(256, 2) void mma_gemm(
    const __half* __restrict__ Ah, const __half* __restrict__ Al,
    const __half* __restrict__ Wh, const __half* __restrict__ Wl,
    const float* __restrict__ bias, const float* __restrict__ xres,
    float* __restrict__ outf, __half* __restrict__ oh, int Ntot) {
    constexpr int GBUF = (MODE == 0) ? 15360 : 30720;
    constexpr int W_OFF = (MODE == 0) ? 10240 : 20480;   // Wh offset; Wl at +5120
    extern __shared__ __align__(16) char sm[];
    const uint32_t sb = smem_u32(sm);
    const int t = threadIdx.x, w = t >> 5, L = t & 31;
    const int n0 = blockIdx.x * 64;
    const int m0 = blockIdx.y * 128;
    const int wm = w >> 1, wn = w & 1;

    const int arow = L & 15, aseg = L >> 4;
    const int brow = ((L >> 4) << 3) + (L & 7), bcol = ((L >> 3) & 1) * 8;
    const int crow = L >> 2, ccol = (L & 3) * 2;

    float acc[2][4][4] = {};

    auto load_chunk = [&](int kc, int st) {
        const int k0 = kc * 32;
        const uint32_t base = sb + st * GBUF;
#pragma unroll
        for (int rep = 0; rep < 2; ++rep) {
            int c = t + rep * 256;
            int row = c >> 2, ch = c & 3;
            size_t so = (size_t)(m0 + row) * CC + k0 + ch * 8;
            CP_A16(base + row * 80 + ch * 16, Ah + so);
            if (MODE == 1) CP_A16(base + 10240 + row * 80 + ch * 16, Al + so);
        }
        {
            int row = t >> 2, ch = t & 3;
            size_t so = (size_t)(n0 + row) * CC + k0 + ch * 8;
            CP_A16(base + W_OFF + row * 80 + ch * 16, Wh + so);
            if (MODE == 1)
                CP_A16(base + W_OFF + 5120 + row * 80 + ch * 16, Wl + so);
        }
    };

    auto compute = [&](int st) {
        const uint32_t base = sb + st * GBUF;
#pragma unroll
        for (int ks = 0; ks < 2; ++ks) {
            uint32_t ah[2][4], al2[2][4], bh[2][4], bl[2][4];
#pragma unroll
            for (int mt = 0; mt < 2; ++mt) {
                uint32_t off = (uint32_t)(((wm * 32 + mt * 16 + arow) * GP +
                                           ks * 16 + aseg * 8) * 2);
                ldm_x4(ah[mt], base + off);
                if (MODE == 1) ldm_x4(al2[mt], base + 10240 + off);
            }
#pragma unroll
            for (int nt = 0; nt < 2; ++nt) {
                uint32_t off = (uint32_t)(((wn * 32 + nt * 16 + brow) * GP +
                                           ks * 16 + bcol) * 2);
                ldm_x4(bh[nt], base + W_OFF + off);
                if (MODE == 1) ldm_x4(bl[nt], base + W_OFF + 5120 + off);
            }
#pragma unroll
            for (int mt = 0; mt < 2; ++mt)
#pragma unroll
                for (int n8 = 0; n8 < 4; ++n8)
                    mma_f16(acc[mt][n8], ah[mt], &bh[n8 >> 1][(n8 & 1) * 2]);
            if (MODE == 1) {
#pragma unroll
                for (int mt = 0; mt < 2; ++mt)
#pragma unroll
                    for (int n8 = 0; n8 < 4; ++n8)
                        mma_f16(acc[mt][n8], ah[mt], &bl[n8 >> 1][(n8 & 1) * 2]);
#pragma unroll
                for (int mt = 0; mt < 2; ++mt)
#pragma unroll
                    for (int n8 = 0; n8 < 4; ++n8)
                        mma_f16(acc[mt][n8], al2[mt], &bh[n8 >> 1][(n8 & 1) * 2]);
            }
        }
    };

    load_chunk(0, 0); CP_COMMIT();
    load_chunk(1, 1); CP_COMMIT();
    int cs = 0, ls = 2;
    for (int kc = 0; kc < 16; ++kc) {
        if (kc < 15) CP_WAIT1(); else CP_WAIT0();
        __syncthreads();
        compute(cs);
        if (kc < 14) { load_chunk(kc + 2, ls); CP_COMMIT(); }
        cs = (cs == 2) ? 0 : cs + 1;
        ls = (ls == 2) ? 0 : ls + 1;
    }
    __syncthreads();   // buffers free before stage aliasing

    float* stage = reinterpret_cast<float*>(sm);
    const int PITCH = (MODE == 0) ? 68 : 65;
#pragma unroll
    for (int mt = 0; mt < 2; ++mt)
#pragma unroll
        for (int n8 = 0; n8 < 4; ++n8) {
            int r = wm * 32 + mt * 16 + crow;
            int c = wn * 32 + n8 * 8 + ccol;
            stage[r * PITCH + c]           = acc[mt][n8][0];
            stage[r * PITCH + c + 1]       = acc[mt][n8][1];
            stage[(r + 8) * PITCH + c]     = acc[mt][n8][2];
            stage[(r + 8) * PITCH + c + 1] = acc[mt][n8][3];
        }
    __syncthreads();

    if (MODE == 0) {
#pragma unroll
        for (int i = 0; i < 8; ++i) {
            int f = t + 256 * i;
            int row = f >> 4, c4 = f & 15;
            float4 v = *(const float4*)&stage[row * 68 + c4 * 4];
            float4 bb = *(const float4*)&bias[n0 + c4 * 4];
            uint2 hv = make_uint2(pack2(v.x + bb.x, v.y + bb.y),
                                  pack2(v.z + bb.z, v.w + bb.w));
            size_t go = (size_t)(m0 + row) * Ntot + n0 + c4 * 4;
            *reinterpret_cast<uint2*>(oh + go) = hv;
        }
    } else {
        const int b = m0 >> 10;
        const int s0 = m0 & 1023;
#pragma unroll
        for (int i = 0; i < 32; ++i) {
            int idx = i * 256 + t;
            int c = idx >> 7, srow = idx & 127;
            size_t gi = (size_t)(b * CC + n0 + c) * SS + s0 + srow;
            outf[gi] = stage[srow * 65 + c] + bias[n0 + c] + xres[gi];
        }
    }
}

// ---------------------------------------------------------------------------
// Kernel 3: flash attention, 128 queries/CTA, warp owns 16 full rows.
// Q, K, V all single fp16.  QK^T 1 pass, PV 1 pass.  Double-buffered K/V.
// ---------------------------------------------------------------------------
#define AP 72
#define A_Q  0                    // Q: 128 x 144B
#define A_KB 18432                // K stage i at A_KB + i*9216
#define A_VB 36864                // V stage i at A_VB + i*9216
#define ATT_SMEM 55296
#define SCL 0.18033688011112042f  // 0.125 * log2(e)

__global__ __launch_bounds__(256, 2) void attn_mma() {
    extern __shared__ __align__(16) char sm[];
    const uint32_t sb = smem_u32(sm);

    const int i0 = blockIdx.x * 128;
    const int bh = blockIdx.y;
    const int b = bh >> 3, h = bh & 7;
    const int t = threadIdx.x, w = t >> 5, L = t & 31;

    const int arow = L & 15, aseg = L >> 4;
    const int brow = ((L >> 4) << 3) + (L & 7), bcol = ((L >> 3) & 1) * 8;
    const int crow = L >> 2, ccol = (L & 3) * 2;

    const __half* qk = g_qkv_h + (size_t)b * SS * QKVC + h * 192;

    // single-plane 64x64 tile load
    auto cp_kv = [&](uint32_t base, const __half* src) {
#pragma unroll
        for (int rep = 0; rep < 2; ++rep) {
            int c = t + rep * 256;
            int row = c >> 3, ch = c & 7;
            CP_A16(base + row * 144 + ch * 16, src + (size_t)row * QKVC + ch * 8);
        }
    };

    // prologue groups: 0 = Q+K(0), 1 = V(0), 2 = K(1)
    {
        const __half* sq = qk + (size_t)i0 * QKVC;
#pragma unroll
        for (int rep = 0; rep < 4; ++rep) {
            int c = t + rep * 256;
            int row = c >> 3, ch = c & 7;
            CP_A16(sb + A_Q + row * 144 + ch * 16, sq + (size_t)row * QKVC + ch * 8);
        }
    }
    cp_kv(sb + A_KB, qk + 64);
    CP_COMMIT();
    cp_kv(sb + A_VB, qk + 128);
    CP_COMMIT();
    cp_kv(sb + A_KB + 9216, qk + (size_t)64 * QKVC + 64);
    CP_COMMIT();

    float m0 = -1e30f, m1 = -1e30f, l0 = 0.f, l1 = 0.f;
    float o[8][4] = {};

    for (int j = 0; j < 16; ++j) {
        const uint32_t kbase = sb + A_KB + (j & 1) * 9216;
        const uint32_t vbase = sb + A_VB + (j & 1) * 9216;

        if (j < 15) CP_WAIT2(); else CP_WAIT1();   // K(j) ready
        __syncthreads();

        // ---- S = Q K^T : 1 pass ----
        float sc[8][4] = {};
#pragma unroll
        for (int ks = 0; ks < 4; ++ks) {
            uint32_t aoff = (uint32_t)(((w * 16 + arow) * AP + ks * 16 + aseg * 8) * 2);
            uint32_t ah[4];
            ldm_x4(ah, sb + A_Q + aoff);
            uint32_t bh_[4][4];
#pragma unroll
            for (int nt = 0; nt < 4; ++nt) {
                uint32_t boff = (uint32_t)(((nt * 16 + brow) * AP +
                                            ks * 16 + bcol) * 2);
                ldm_x4(bh_[nt], kbase + boff);
            }
#pragma unroll
            for (int n8 = 0; n8 < 8; ++n8)
                mma_f16(sc[n8], ah, &bh_[n8 >> 1][(n8 & 1) * 2]);
        }

        if (j < 15) {             // prefetch V(j+1) into other V buffer
            size_t nb = (size_t)(j + 1) * 64 * QKVC;
            cp_kv(sb + A_VB + ((j + 1) & 1) * 9216, qk + nb + 128);
            CP_COMMIT();
        }

        // ---- register softmax (base-2 domain; SCL = 0.125*log2 e) ----
        float mx0 = -1e30f, mx1 = -1e30f;
#pragma unroll
        for (int n8 = 0; n8 < 8; ++n8) {
            sc[n8][0] *= SCL; sc[n8][1] *= SCL;
            sc[n8][2] *= SCL; sc[n8][3] *= SCL;
            mx0 = fmaxf(mx0, fmaxf(sc[n8][0], sc[n8][1]));
            mx1 = fmaxf(mx1, fmaxf(sc[n8][2], sc[n8][3]));
        }
        mx0 = fmaxf(mx0, __shfl_xor_sync(0xffffffff, mx0, 1));
        mx0 = fmaxf(mx0, __shfl_xor_sync(0xffffffff, mx0, 2));
        mx1 = fmaxf(mx1, __shfl_xor_sync(0xffffffff, mx1, 1));
        mx1 = fmaxf(mx1, __shfl_xor_sync(0xffffffff, mx1, 2));

        float mn0 = fmaxf(m0, mx0), mn1 = fmaxf(m1, mx1);
        float a0 = exp2f(m0 - mn0), a1 = exp2f(m1 - mn1);
        m0 = mn0; m1 = mn1;

        uint32_t ph[4][4];
        float s0 = 0.f, s1 = 0.f;
#pragma unroll
        for (int g = 0; g < 4; ++g)
#pragma unroll
            for (int hf = 0; hf < 2; ++hf) {
                int tile = g * 2 + hf;
                float p00 = exp2f(sc[tile][0] - mn0);
                float p01 = exp2f(sc[tile][1] - mn0);
                float p10 = exp2f(sc[tile][2] - mn1);
                float p11 = exp2f(sc[tile][3] - mn1);
                s0 += p00 + p01; s1 += p10 + p11;
                ph[g][hf * 2]     = pack2(p00, p01);
                ph[g][hf * 2 + 1] = pack2(p10, p11);
            }
        s0 += __shfl_xor_sync(0xffffffff, s0, 1);
        s0 += __shfl_xor_sync(0xffffffff, s0, 2);
        s1 += __shfl_xor_sync(0xffffffff, s1, 1);
        s1 += __shfl_xor_sync(0xffffffff, s1, 2);
        l0 = fmaf(l0, a0, s0);
        l1 = fmaf(l1, a1, s1);

#pragma unroll
        for (int n8 = 0; n8 < 8; ++n8) {
            o[n8][0] *= a0; o[n8][1] *= a0;
            o[n8][2] *= a1; o[n8][3] *= a1;
        }

        if (j < 15) CP_WAIT2(); else CP_WAIT0();   // V(j) ready
        __syncthreads();

        // ---- O += P V : 1 pass ----
#pragma unroll
        for (int g = 0; g < 4; ++g) {
            int krow = g * 16 + ((L >> 3) & 1) * 8 + (L & 7);
            uint32_t vh[4][4];
#pragma unroll
            for (int nt = 0; nt < 4; ++nt) {
                int dcol = nt * 16 + (L >> 4) * 8;
                ldm_x4_t(vh[nt], vbase + (uint32_t)((krow * AP + dcol) * 2));
            }
#pragma unroll
            for (int n8 = 0; n8 < 8; ++n8)
                mma_f16(o[n8], ph[g], &vh[n8 >> 1][(n8 & 1) * 2]);
        }

        if (j < 14) {             // prefetch K(j+2) into other K buffer
            size_t nb = (size_t)(j + 2) * 64 * QKVC;
            cp_kv(sb + A_KB + (j & 1) * 9216, qk + nb + 64);
            CP_COMMIT();
        }
    }

    // ---- normalize + store hi/lo fp16 (ao feeds 3-pass out GEMM) ----
    float inv0 = 1.f / l0, inv1 = 1.f / l1;
#pragma unroll
    for (int n8 = 0; n8 < 8; ++n8) {
        int d = n8 * 8 + ccol;
        uint32_t h0, lo0, h1, lo1;
        split2(o[n8][0] * inv0, o[n8][1] * inv0, h0, lo0);
        split2(o[n8][2] * inv1, o[n8][3] * inv1, h1, lo1);
        size_t g0 = (size_t)(b * SS + i0 + w * 16 + crow) * CC + h * DK + d;
        size_t g1 = g0 + (size_t)8 * CC;
        *reinterpret_cast<uint32_t*>(g_ao_h + g0) = h0;
        *reinterpret_cast<uint32_t*>(g_ao_l + g0) = lo0;
        *reinterpret_cast<uint32_t*>(g_ao_h + g1) = h1;
        *reinterpret_cast<uint32_t*>(g_ao_l + g1) = lo1;
    }
}

// ---------------------------------------------------------------------------
extern "C" void kernel_launch(void* const* d_in, const int* in_sizes, int n_in,
                              void* d_out, int out_size) {
    const float* x = (const float*)d_in[0];
    const float* gn_w = (const float*)d_in[1];
    const float* gn_b = (const float*)d_in[2];
    const float* proj_w = (const float*)d_in[3];
    const float* proj_b = (const float*)d_in[4];
    const float* out_w = (const float*)d_in[5];
    const float* out_b = (const float*)d_in[6];
    float* out = (float*)d_out;

    __half *d_hh, *d_qh, *d_aoh, *d_aol, *d_pwh, *d_owh, *d_owl;
    cudaGetSymbolAddress((void**)&d_hh, g_h_h);
    cudaGetSymbolAddress((void**)&d_qh, g_qkv_h);
    cudaGetSymbolAddress((void**)&d_aoh, g_ao_h);
    cudaGetSymbolAddress((void**)&d_aol, g_ao_l);
    cudaGetSymbolAddress((void**)&d_pwh, g_pw_h);
    cudaGetSymbolAddress((void**)&d_owh, g_ow_h);
    cudaGetSymbolAddress((void**)&d_owl, g_ow_l);

    const int SMEM0 = 3 * 15360;
    const int SMEM1 = 3 * 30720;
    cudaFuncSetAttribute(mma_gemm<0>, cudaFuncAttributeMaxDynamicSharedMemorySize, SMEM0);
    cudaFuncSetAttribute(mma_gemm<1>, cudaFuncAttributeMaxDynamicSharedMemorySize, SMEM1);
    cudaFuncSetAttribute(attn_mma, cudaFuncAttributeMaxDynamicSharedMemorySize, ATT_SMEM);

    const int n1 = QKVC * CC / 4, n2 = CC * CC / 4;
    cvt_w2<<<(n1 + n2 + 255) / 256, 256>>>(proj_w, d_pwh, n1,
                                           out_w, d_owh, d_owl, n2);
    gn_kernel<<<BB * NG, 256>>>(x, gn_w, gn_b);

    mma_gemm<0><<<dim3(QKVC / 64, BB * SS / 128), 256, SMEM0>>>(
        d_hh, nullptr, d_pwh, nullptr, proj_b, nullptr, nullptr, d_qh, QKVC);

    attn_mma<<<dim3(SS / 128, BB * NH), 256, ATT_SMEM>>>();

    mma_gemm<1><<<dim3(CC / 64, BB * SS / 128), 256, SMEM1>>>(
        d_aoh, d_aol, d_owh, d_owl, out_b, x, out, nullptr, CC);
}

// round 13
// speedup vs baseline: 5.8235x; 1.1188x over previous
#include <cuda_runtime.h>
#include <cuda_fp16.h>
#include <cstdint>

// Shapes: B=16, C=512, H=W=32 -> S=1024, 32 groups (16 ch/group), 8 heads, D=64.
#define BB 16
#define CC 512
#define SS 1024
#define NG 32
#define CPG 16
#define NH 8
#define DK 64
#define QKVC 1536

// fp16 storage (hi/lo split only where error does NOT dilute)
static __device__ __half g_h_h[BB * SS * CC];        // gn out: single fp16
static __device__ __half g_qkv_h[BB * SS * QKVC];    // qkv: single fp16 (q pre-scaled)
static __device__ __half g_ao_h[BB * SS * CC];       // ao: single fp16
static __device__ __half g_pw_h[QKVC * CC];          // proj_w: single fp16
static __device__ __half g_ow_h[CC * CC];            // out_w: hi/lo
static __device__ __half g_ow_l[CC * CC];

#define SCL 0.18033688011112042f  // 0.125 * log2(e), folded into q

// ============================================================================
// helpers
// ============================================================================
__device__ __forceinline__ uint32_t smem_u32(const void* p) {
    uint32_t a;
    asm("{ .reg .u64 t; cvta.to.shared.u64 t, %1; cvt.u32.u64 %0, t; }"
        : "=r"(a) : "l"(p));
    return a;
}

__device__ __forceinline__ void ldm_x4(uint32_t* r, uint32_t addr) {
    asm volatile("ldmatrix.sync.aligned.m8n8.x4.shared.b16 {%0,%1,%2,%3}, [%4];"
                 : "=r"(r[0]), "=r"(r[1]), "=r"(r[2]), "=r"(r[3]) : "r"(addr));
}
__device__ __forceinline__ void ldm_x4_t(uint32_t* r, uint32_t addr) {
    asm volatile("ldmatrix.sync.aligned.m8n8.x4.trans.shared.b16 {%0,%1,%2,%3}, [%4];"
                 : "=r"(r[0]), "=r"(r[1]), "=r"(r[2]), "=r"(r[3]) : "r"(addr));
}

__device__ __forceinline__ void mma_f16(float* c, const uint32_t* a, const uint32_t* b) {
    asm volatile(
        "mma.sync.aligned.m16n8k16.row.col.f32.f16.f16.f32 "
        "{%0,%1,%2,%3}, {%4,%5,%6,%7}, {%8,%9}, {%0,%1,%2,%3};"
        : "+f"(c[0]), "+f"(c[1]), "+f"(c[2]), "+f"(c[3])
        : "r"(a[0]), "r"(a[1]), "r"(a[2]), "r"(a[3]), "r"(b[0]), "r"(b[1]));
}

#define CP_A16(dst, src) \
    asm volatile("cp.async.cg.shared.global [%0], [%1], 16;" :: "r"(dst), "l"(src))
#define CP_COMMIT() asm volatile("cp.async.commit_group;" ::: "memory")
#define CP_WAIT0()  asm volatile("cp.async.wait_group 0;" ::: "memory")
#define CP_WAIT1()  asm volatile("cp.async.wait_group 1;" ::: "memory")
#define CP_WAIT2()  asm volatile("cp.async.wait_group 2;" ::: "memory")

// fp32 pair -> packed fp16 hi + packed fp16 lo
__device__ __forceinline__ void split2(float a, float b, uint32_t& h, uint32_t& l) {
    __half2 hp = __floats2half2_rn(a, b);
    float2 hf = __half22float2(hp);
    __half2 lp = __floats2half2_rn(a - hf.x, b - hf.y);
    h = *reinterpret_cast<uint32_t*>(&hp);
    l = *reinterpret_cast<uint32_t*>(&lp);
}

__device__ __forceinline__ uint32_t pack2(float a, float b) {
    __half2 hp = __floats2half2_rn(a, b);
    return *reinterpret_cast<uint32_t*>(&hp);
}

__device__ __forceinline__ uint32_t packh2(__half a, __half b) {
    __half2 hp = __halves2half2(a, b);
    return *reinterpret_cast<uint32_t*>(&hp);
}

// ---------------------------------------------------------------------------
// Kernel 0: one-time weight conversion: proj_w -> single fp16; out_w -> hi/lo
// ---------------------------------------------------------------------------
__global__ __launch_bounds__(256) void cvt_w2(
    const float* __restrict__ w1, __half* __restrict__ h1, int n1,
    const float* __restrict__ w2, __half* __restrict__ h2,
    __half* __restrict__ l2, int n2) {
    int i = blockIdx.x * 256 + threadIdx.x;
    if (i < n1) {
        float4 v = reinterpret_cast<const float4*>(w1)[i];
        uint2 hv = make_uint2(pack2(v.x, v.y), pack2(v.z, v.w));
        reinterpret_cast<uint2*>(h1)[i] = hv;
    } else if (i < n1 + n2) {
        i -= n1;
        float4 v = reinterpret_cast<const float4*>(w2)[i];
        uint2 hv, lv;
        split2(v.x, v.y, hv.x, lv.x);
        split2(v.z, v.w, hv.y, lv.y);
        reinterpret_cast<uint2*>(h2)[i] = hv;
        reinterpret_cast<uint2*>(l2)[i] = lv;
    }
}

// ---------------------------------------------------------------------------
// Kernel 1: GroupNorm, smem-transposed pass 2 (coalesced loads + 16B stores)
// ---------------------------------------------------------------------------
__global__ __launch_bounds__(256) void gn_kernel(const float* __restrict__ x,
                                                 const float* __restrict__ w,
                                                 const float* __restrict__ bgn) {
    const int b = blockIdx.x >> 5;
    const int g = blockIdx.x & 31;
    const float* xp = x + (size_t)(b * CC + g * CPG) * SS;
    const int t = threadIdx.x;

    float sum = 0.f, sq = 0.f;
    for (int i = t; i < CPG * SS; i += 256) {
        float v = xp[i];
        sum += v;
        sq = fmaf(v, v, sq);
    }
    __shared__ float s1[256], s2[256];
    s1[t] = sum; s2[t] = sq;
    __syncthreads();
    for (int o = 128; o > 0; o >>= 1) {
        if (t < o) { s1[t] += s1[t + o]; s2[t] += s2[t + o]; }
        __syncthreads();
    }
    __shared__ float mean_s, inv_s;
    if (t == 0) {
        const float n_inv = 1.f / (CPG * SS);
        float mean = s1[0] * n_inv;
        float var = s2[0] * n_inv - mean * mean;
        mean_s = mean;
        inv_s = rsqrtf(var + 1e-5f);
    }
    __syncthreads();

    __shared__ float swc[16], sbc[16];
    if (t < 16) {
        int c = g * CPG + t;
        float wc = w[c] * inv_s;
        swc[t] = wc;
        sbc[t] = bgn[c] - mean_s * wc;
    }
    __shared__ __half tile[16][264];
    __syncthreads();

    const int s2i = t >> 1, hb = t & 1;
    for (int chunk = 0; chunk < 4; ++chunk) {
#pragma unroll
        for (int k = 0; k < 16; ++k) {
            float v = xp[k * SS + chunk * 256 + t];
            tile[k][t] = __float2half_rn(fmaf(v, swc[k], sbc[k]));
        }
        __syncthreads();
#pragma unroll
        for (int rep = 0; rep < 2; ++rep) {
            int s = s2i + rep * 128;
            __half v0 = tile[hb * 8 + 0][s], v1 = tile[hb * 8 + 1][s];
            __half v2 = tile[hb * 8 + 2][s], v3 = tile[hb * 8 + 3][s];
            __half v4 = tile[hb * 8 + 4][s], v5 = tile[hb * 8 + 5][s];
            __half v6 = tile[hb * 8 + 6][s], v7 = tile[hb * 8 + 7][s];
            uint4 u;
            u.x = packh2(v0, v1); u.y = packh2(v2, v3);
            u.z = packh2(v4, v5); u.w = packh2(v6, v7);
            size_t off = (size_t)(b * SS + chunk * 256 + s) * CC + g * CPG + hb * 8;
            *reinterpret_cast<uint4*>(g_h_h + off) = u;
        }
        __syncthreads();
    }
}

// ---------------------------------------------------------------------------
// Kernel 2: mma GEMM, 128x64 CTA tile, 3-stage cp.async ring.
// MODE 0 (qkv): pure fp16, 1 pass; epi +bias (+SCL on q tiles), fp16 out.
// MODE 1 (out): A single x W hi/lo, 2 passes; epi +bias+residual, fp32 CM.
// ---------------------------------------------------------------------------
#define GP 40                 // fp16 smem pitch (80B rows)

template <int MODE>
__global__ __launch_bounds__(256, 2) void mma_gemm(
    const __half* __restrict__ Ah,
    const __half* __restrict__ Wh, const __half* __restrict__ Wl,
    const float* __restrict__ bias, const float* __restrict__ xres,
    float* __restrict__ outf, __half* __restrict__ oh, int Ntot) {
    constexpr int GBUF = (MODE == 0) ? 15360 : 20480;
    extern __shared__ __align__(16) char sm[];
    const uint32_t sb = smem_u32(sm);
    const int t = threadIdx.x, w = t >> 5, L = t & 31;
    const int n0 = blockIdx.x * 64;
    const int m0 = blockIdx.y * 128;
    const int wm = w >> 1, wn = w & 1;

    const int arow = L & 15, aseg = L >> 4;
    const int brow = ((L >> 4) << 3) + (L & 7), bcol = ((L >> 3) & 1) * 8;
    const int crow = L >> 2, ccol = (L & 3) * 2;

    float acc[2][4][4] = {};

    auto load_chunk = [&](int kc, int st) {
        const int k0 = kc * 32;
        const uint32_t base = sb + st * GBUF;
#pragma unroll
        for (int rep = 0; rep < 2; ++rep) {
            int c = t + rep * 256;
            int row = c >> 2, ch = c & 3;
            size_t so = (size_t)(m0 + row) * CC + k0 + ch * 8;
            CP_A16(base + row * 80 + ch * 16, Ah + so);
        }
        {
            int row = t >> 2, ch = t & 3;
            size_t so = (size_t)(n0 + row) * CC + k0 + ch * 8;
            CP_A16(base + 10240 + row * 80 + ch * 16, Wh + so);
            if (MODE == 1)
                CP_A16(base + 15360 + row * 80 + ch * 16, Wl + so);
        }
    };

    auto compute = [&](int st) {
        const uint32_t base = sb + st * GBUF;
#pragma unroll
        for (int ks = 0; ks < 2; ++ks) {
            uint32_t ah[2][4], bh[2][4], bl[2][4];
#pragma unroll
            for (int mt = 0; mt < 2; ++mt) {
                uint32_t off = (uint32_t)(((wm * 32 + mt * 16 + arow) * GP +
                                           ks * 16 + aseg * 8) * 2);
                ldm_x4(ah[mt], base + off);
            }
#pragma unroll
            for (int nt = 0; nt < 2; ++nt) {
                uint32_t off = (uint32_t)(((wn * 32 + nt * 16 + brow) * GP +
                                           ks * 16 + bcol) * 2);
                ldm_x4(bh[nt], base + 10240 + off);
                if (MODE == 1) ldm_x4(bl[nt], base + 15360 + off);
            }
#pragma unroll
            for (int mt = 0; mt < 2; ++mt)
#pragma unroll
                for (int n8 = 0; n8 < 4; ++n8)
                    mma_f16(acc[mt][n8], ah[mt], &bh[n8 >> 1][(n8 & 1) * 2]);
            if (MODE == 1) {
#pragma unroll
                for (int mt = 0; mt < 2; ++mt)
#pragma unroll
                    for (int n8 = 0; n8 < 4; ++n8)
                        mma_f16(acc[mt][n8], ah[mt], &bl[n8 >> 1][(n8 & 1) * 2]);
            }
        }
    };

    load_chunk(0, 0); CP_COMMIT();
    load_chunk(1, 1); CP_COMMIT();
    int cs = 0, ls = 2;
    for (int kc = 0; kc < 16; ++kc) {
        if (kc < 15) CP_WAIT1(); else CP_WAIT0();
        __syncthreads();
        compute(cs);
        if (kc < 14) { load_chunk(kc + 2, ls); CP_COMMIT(); }
        cs = (cs == 2) ? 0 : cs + 1;
        ls = (ls == 2) ? 0 : ls + 1;
    }
    __syncthreads();   // buffers free before stage aliasing

    float* stage = reinterpret_cast<float*>(sm);
    const int PITCH = (MODE == 0) ? 68 : 65;
#pragma unroll
    for (int mt = 0; mt < 2; ++mt)
#pragma unroll
        for (int n8 = 0; n8 < 4; ++n8) {
            int r = wm * 32 + mt * 16 + crow;
            int c = wn * 32 + n8 * 8 + ccol;
            stage[r * PITCH + c]           = acc[mt][n8][0];
            stage[r * PITCH + c + 1]       = acc[mt][n8][1];
            stage[(r + 8) * PITCH + c]     = acc[mt][n8][2];
            stage[(r + 8) * PITCH + c + 1] = acc[mt][n8][3];
        }
    __syncthreads();

    if (MODE == 0) {
        // q tiles (n0 % 192 == 0) get the folded softmax scale
        const float scale = (n0 % 192 == 0) ? SCL : 1.0f;
#pragma unroll
        for (int i = 0; i < 8; ++i) {
            int f = t + 256 * i;
            int row = f >> 4, c4 = f & 15;
            float4 v = *(const float4*)&stage[row * 68 + c4 * 4];
            float4 bb = *(const float4*)&bias[n0 + c4 * 4];
            uint2 hv = make_uint2(pack2((v.x + bb.x) * scale, (v.y + bb.y) * scale),
                                  pack2((v.z + bb.z) * scale, (v.w + bb.w) * scale));
            size_t go = (size_t)(m0 + row) * Ntot + n0 + c4 * 4;
            *reinterpret_cast<uint2*>(oh + go) = hv;
        }
    } else {
        const int b = m0 >> 10;
        const int s0 = m0 & 1023;
#pragma unroll
        for (int i = 0; i < 32; ++i) {
            int idx = i * 256 + t;
            int c = idx >> 7, srow = idx & 127;
            size_t gi = (size_t)(b * CC + n0 + c) * SS + s0 + srow;
            outf[gi] = stage[srow * 65 + c] + bias[n0 + c] + xres[gi];
        }
    }
}

// ---------------------------------------------------------------------------
// Kernel 3: flash attention, 128 queries/CTA, warp owns 16 full rows.
// Q (pre-scaled), K, V single fp16.  QK^T 1 pass, PV 1 pass.
// Double-buffered K/V.  exp2 softmax (scale folded upstream).
// ---------------------------------------------------------------------------
#define AP 72
#define A_Q  0                    // Q: 128 x 144B
#define A_KB 18432                // K stage i at A_KB + i*9216
#define A_VB 36864                // V stage i at A_VB + i*9216
#define ATT_SMEM 55296

__global__ __launch_bounds__(256, 2) void attn_mma() {
    extern __shared__ __align__(16) char sm[];
    const uint32_t sb = smem_u32(sm);

    const int i0 = blockIdx.x * 128;
    const int bh = blockIdx.y;
    const int b = bh >> 3, h = bh & 7;
    const int t = threadIdx.x, w = t >> 5, L = t & 31;

    const int arow = L & 15, aseg = L >> 4;
    const int brow = ((L >> 4) << 3) + (L & 7), bcol = ((L >> 3) & 1) * 8;
    const int crow = L >> 2, ccol = (L & 3) * 2;

    const __half* qk = g_qkv_h + (size_t)b * SS * QKVC + h * 192;

    auto cp_kv = [&](uint32_t base, const __half* src) {
#pragma unroll
        for (int rep = 0; rep < 2; ++rep) {
            int c = t + rep * 256;
            int row = c >> 3, ch = c & 7;
            CP_A16(base + row * 144 + ch * 16, src + (size_t)row * QKVC + ch * 8);
        }
    };

    // prologue groups: 0 = Q+K(0), 1 = V(0), 2 = K(1)
    {
        const __half* sq = qk + (size_t)i0 * QKVC;
#pragma unroll
        for (int rep = 0; rep < 4; ++rep) {
            int c = t + rep * 256;
            int row = c >> 3, ch = c & 7;
            CP_A16(sb + A_Q + row * 144 + ch * 16, sq + (size_t)row * QKVC + ch * 8);
        }
    }
    cp_kv(sb + A_KB, qk + 64);
    CP_COMMIT();
    cp_kv(sb + A_VB, qk + 128);
    CP_COMMIT();
    cp_kv(sb + A_KB + 9216, qk + (size_t)64 * QKVC + 64);
    CP_COMMIT();

    float m0 = -1e30f, m1 = -1e30f, l0 = 0.f, l1 = 0.f;
    float o[8][4] = {};

    for (int j = 0; j < 16; ++j) {
        const uint32_t kbase = sb + A_KB + (j & 1) * 9216;
        const uint32_t vbase = sb + A_VB + (j & 1) * 9216;

        if (j < 15) CP_WAIT2(); else CP_WAIT1();   // K(j) ready
        __syncthreads();

        // ---- S = Q K^T : 1 pass (scale already folded into Q) ----
        float sc[8][4] = {};
#pragma unroll
        for (int ks = 0; ks < 4; ++ks) {
            uint32_t aoff = (uint32_t)(((w * 16 + arow) * AP + ks * 16 + aseg * 8) * 2);
            uint32_t ah[4];
            ldm_x4(ah, sb + A_Q + aoff);
            uint32_t bh_[4][4];
#pragma unroll
            for (int nt = 0; nt < 4; ++nt) {
                uint32_t boff = (uint32_t)(((nt * 16 + brow) * AP +
                                            ks * 16 + bcol) * 2);
                ldm_x4(bh_[nt], kbase + boff);
            }
#pragma unroll
            for (int n8 = 0; n8 < 8; ++n8)
                mma_f16(sc[n8], ah, &bh_[n8 >> 1][(n8 & 1) * 2]);
        }

        if (j < 15) {             // prefetch V(j+1) into other V buffer
            size_t nb = (size_t)(j + 1) * 64 * QKVC;
            cp_kv(sb + A_VB + ((j + 1) & 1) * 9216, qk + nb + 128);
            CP_COMMIT();
        }

        // ---- register softmax (base-2 domain) ----
        float mx0 = -1e30f, mx1 = -1e30f;
#pragma unroll
        for (int n8 = 0; n8 < 8; ++n8) {
            mx0 = fmaxf(mx0, fmaxf(sc[n8][0], sc[n8][1]));
            mx1 = fmaxf(mx1, fmaxf(sc[n8][2], sc[n8][3]));
        }
        mx0 = fmaxf(mx0, __shfl_xor_sync(0xffffffff, mx0, 1));
        mx0 = fmaxf(mx0, __shfl_xor_sync(0xffffffff, mx0, 2));
        mx1 = fmaxf(mx1, __shfl_xor_sync(0xffffffff, mx1, 1));
        mx1 = fmaxf(mx1, __shfl_xor_sync(0xffffffff, mx1, 2));

        float mn0 = fmaxf(m0, mx0), mn1 = fmaxf(m1, mx1);
        float a0 = exp2f(m0 - mn0), a1 = exp2f(m1 - mn1);
        m0 = mn0; m1 = mn1;

        uint32_t ph[4][4];
        float s0 = 0.f, s1 = 0.f;
#pragma unroll
        for (int g = 0; g < 4; ++g)
#pragma unroll
            for (int hf = 0; hf < 2; ++hf) {
                int tile = g * 2 + hf;
                float p00 = exp2f(sc[tile][0] - mn0);
                float p01 = exp2f(sc[tile][1] - mn0);
                float p10 = exp2f(sc[tile][2] - mn1);
                float p11 = exp2f(sc[tile][3] - mn1);
                s0 += p00 + p01; s1 += p10 + p11;
                ph[g][hf * 2]     = pack2(p00, p01);
                ph[g][hf * 2 + 1] = pack2(p10, p11);
            }
        s0 += __shfl_xor_sync(0xffffffff, s0, 1);
        s0 += __shfl_xor_sync(0xffffffff, s0, 2);
        s1 += __shfl_xor_sync(0xffffffff, s1, 1);
        s1 += __shfl_xor_sync(0xffffffff, s1, 2);
        l0 = fmaf(l0, a0, s0);
        l1 = fmaf(l1, a1, s1);

#pragma unroll
        for (int n8 = 0; n8 < 8; ++n8) {
            o[n8][0] *= a0; o[n8][1] *= a0;
            o[n8][2] *= a1; o[n8][3] *= a1;
        }

        if (j < 15) CP_WAIT2(); else CP_WAIT0();   // V(j) ready
        __syncthreads();

        // ---- O += P V : 1 pass ----
#pragma unroll
        for (int g = 0; g < 4; ++g) {
            int krow = g * 16 + ((L >> 3) & 1) * 8 + (L & 7);
            uint32_t vh[4][4];
#pragma unroll
            for (int nt = 0; nt < 4; ++nt) {
                int dcol = nt * 16 + (L >> 4) * 8;
                ldm_x4_t(vh[nt], vbase + (uint32_t)((krow * AP + dcol) * 2));
            }
#pragma unroll
            for (int n8 = 0; n8 < 8; ++n8)
                mma_f16(o[n8], ph[g], &vh[n8 >> 1][(n8 & 1) * 2]);
        }

        if (j < 14) {             // prefetch K(j+2) into other K buffer
            size_t nb = (size_t)(j + 2) * 64 * QKVC;
            cp_kv(sb + A_KB + (j & 1) * 9216, qk + nb + 64);
            CP_COMMIT();
        }
    }

    // ---- normalize + store single fp16 ----
    float inv0 = 1.f / l0, inv1 = 1.f / l1;
#pragma unroll
    for (int n8 = 0; n8 < 8; ++n8) {
        int d = n8 * 8 + ccol;
        uint32_t h0 = pack2(o[n8][0] * inv0, o[n8][1] * inv0);
        uint32_t h1 = pack2(o[n8][2] * inv1, o[n8][3] * inv1);
        size_t g0 = (size_t)(b * SS + i0 + w * 16 + crow) * CC + h * DK + d;
        size_t g1 = g0 + (size_t)8 * CC;
        *reinterpret_cast<uint32_t*>(g_ao_h + g0) = h0;
        *reinterpret_cast<uint32_t*>(g_ao_h + g1) = h1;
    }
}

// ---------------------------------------------------------------------------
extern "C" void kernel_launch(void* const* d_in, const int* in_sizes, int n_in,
                              void* d_out, int out_size) {
    const float* x = (const float*)d_in[0];
    const float* gn_w = (const float*)d_in[1];
    const float* gn_b = (const float*)d_in[2];
    const float* proj_w = (const float*)d_in[3];
    const float* proj_b = (const float*)d_in[4];
    const float* out_w = (const float*)d_in[5];
    const float* out_b = (const float*)d_in[6];
    float* out = (float*)d_out;

    __half *d_hh, *d_qh, *d_aoh, *d_pwh, *d_owh, *d_owl;
    cudaGetSymbolAddress((void**)&d_hh, g_h_h);
    cudaGetSymbolAddress((void**)&d_qh, g_qkv_h);
    cudaGetSymbolAddress((void**)&d_aoh, g_ao_h);
    cudaGetSymbolAddress((void**)&d_pwh, g_pw_h);
    cudaGetSymbolAddress((void**)&d_owh, g_ow_h);
    cudaGetSymbolAddress((void**)&d_owl, g_ow_l);

    const int SMEM0 = 3 * 15360;
    const int SMEM1 = 3 * 20480;
    cudaFuncSetAttribute(mma_gemm<0>, cudaFuncAttributeMaxDynamicSharedMemorySize, SMEM0);
    cudaFuncSetAttribute(mma_gemm<1>, cudaFuncAttributeMaxDynamicSharedMemorySize, SMEM1);
    cudaFuncSetAttribute(attn_mma, cudaFuncAttributeMaxDynamicSharedMemorySize, ATT_SMEM);

    const int n1 = QKVC * CC / 4, n2 = CC * CC / 4;
    cvt_w2<<<(n1 + n2 + 255) / 256, 256>>>(proj_w, d_pwh, n1,
                                           out_w, d_owh, d_owl, n2);
    gn_kernel<<<BB * NG, 256>>>(x, gn_w, gn_b);

    mma_gemm<0><<<dim3(QKVC / 64, BB * SS / 128), 256, SMEM0>>>(
        d_hh, d_pwh, nullptr, proj_b, nullptr, nullptr, d_qh, QKVC);

    attn_mma<<<dim3(SS / 128, BB * NH), 256, ATT_SMEM>>>();

    mma_gemm<1><<<dim3(CC / 64, BB * SS / 128), 256, SMEM1>>>(
        d_aoh, d_owh, d_owl, out_b, x, out, nullptr, CC);
}

// round 14
// speedup vs baseline: 6.0946x; 1.0466x over previous
#include <cuda_runtime.h>
#include <cuda_fp16.h>
#include <cstdint>

// Shapes: B=16, C=512, H=W=32 -> S=1024, 32 groups (16 ch/group), 8 heads, D=64.
#define BB 16
#define CC 512
#define SS 1024
#define NG 32
#define CPG 16
#define NH 8
#define DK 64
#define QKVC 1536

// fp16 storage (hi/lo split only where error does NOT dilute)
static __device__ __half g_h_h[BB * SS * CC];        // gn out: single fp16
static __device__ __half g_qkv_h[BB * SS * QKVC];    // qkv: single fp16 (q pre-scaled)
static __device__ __half g_ao_h[BB * SS * CC];       // ao: single fp16
static __device__ __half g_pw_h[QKVC * CC];          // proj_w: single fp16
static __device__ __half g_ow_h[CC * CC];            // out_w: hi/lo
static __device__ __half g_ow_l[CC * CC];

#define SCL 0.18033688011112042f  // 0.125 * log2(e), folded into q

// ============================================================================
// helpers
// ============================================================================
__device__ __forceinline__ uint32_t smem_u32(const void* p) {
    uint32_t a;
    asm("{ .reg .u64 t; cvta.to.shared.u64 t, %1; cvt.u32.u64 %0, t; }"
        : "=r"(a) : "l"(p));
    return a;
}

__device__ __forceinline__ void ldm_x4(uint32_t* r, uint32_t addr) {
    asm volatile("ldmatrix.sync.aligned.m8n8.x4.shared.b16 {%0,%1,%2,%3}, [%4];"
                 : "=r"(r[0]), "=r"(r[1]), "=r"(r[2]), "=r"(r[3]) : "r"(addr));
}
__device__ __forceinline__ void ldm_x4_t(uint32_t* r, uint32_t addr) {
    asm volatile("ldmatrix.sync.aligned.m8n8.x4.trans.shared.b16 {%0,%1,%2,%3}, [%4];"
                 : "=r"(r[0]), "=r"(r[1]), "=r"(r[2]), "=r"(r[3]) : "r"(addr));
}

__device__ __forceinline__ void mma_f16(float* c, const uint32_t* a, const uint32_t* b) {
    asm volatile(
        "mma.sync.aligned.m16n8k16.row.col.f32.f16.f16.f32 "
        "{%0,%1,%2,%3}, {%4,%5,%6,%7}, {%8,%9}, {%0,%1,%2,%3};"
        : "+f"(c[0]), "+f"(c[1]), "+f"(c[2]), "+f"(c[3])
        : "r"(a[0]), "r"(a[1]), "r"(a[2]), "r"(a[3]), "r"(b[0]), "r"(b[1]));
}

#define CP_A16(dst, src) \
    asm volatile("cp.async.cg.shared.global [%0], [%1], 16;" :: "r"(dst), "l"(src))
#define CP_COMMIT() asm volatile("cp.async.commit_group;" ::: "memory")
#define CP_WAIT0()  asm volatile("cp.async.wait_group 0;" ::: "memory")
#define CP_WAIT1()  asm volatile("cp.async.wait_group 1;" ::: "memory")
#define CP_WAIT2()  asm volatile("cp.async.wait_group 2;" ::: "memory")

// fp32 pair -> packed fp16 hi + packed fp16 lo
__device__ __forceinline__ void split2(float a, float b, uint32_t& h, uint32_t& l) {
    __half2 hp = __floats2half2_rn(a, b);
    float2 hf = __half22float2(hp);
    __half2 lp = __floats2half2_rn(a - hf.x, b - hf.y);
    h = *reinterpret_cast<uint32_t*>(&hp);
    l = *reinterpret_cast<uint32_t*>(&lp);
}

__device__ __forceinline__ uint32_t pack2(float a, float b) {
    __half2 hp = __floats2half2_rn(a, b);
    return *reinterpret_cast<uint32_t*>(&hp);
}

__device__ __forceinline__ uint32_t packh2(__half a, __half b) {
    __half2 hp = __halves2half2(a, b);
    return *reinterpret_cast<uint32_t*>(&hp);
}

// 2x exp2 in one MUFU op, result packed fp16x2 (mma-ready)
__device__ __forceinline__ uint32_t exp2_h2(float a, float b) {
    __half2 hv = __floats2half2_rn(a, b);
    uint32_t r;
    asm("ex2.approx.f16x2 %0, %1;" : "=r"(r) : "r"(*reinterpret_cast<uint32_t*>(&hv)));
    return r;
}

// ---------------------------------------------------------------------------
// Kernel 0: one-time weight conversion: proj_w -> single fp16; out_w -> hi/lo
// ---------------------------------------------------------------------------
__global__ __launch_bounds__(256) void cvt_w2(
    const float* __restrict__ w1, __half* __restrict__ h1, int n1,
    const float* __restrict__ w2, __half* __restrict__ h2,
    __half* __restrict__ l2, int n2) {
    int i = blockIdx.x * 256 + threadIdx.x;
    if (i < n1) {
        float4 v = reinterpret_cast<const float4*>(w1)[i];
        uint2 hv = make_uint2(pack2(v.x, v.y), pack2(v.z, v.w));
        reinterpret_cast<uint2*>(h1)[i] = hv;
    } else if (i < n1 + n2) {
        i -= n1;
        float4 v = reinterpret_cast<const float4*>(w2)[i];
        uint2 hv, lv;
        split2(v.x, v.y, hv.x, lv.x);
        split2(v.z, v.w, hv.y, lv.y);
        reinterpret_cast<uint2*>(h2)[i] = hv;
        reinterpret_cast<uint2*>(l2)[i] = lv;
    }
}

// ---------------------------------------------------------------------------
// Kernel 1: GroupNorm, smem-transposed pass 2 (coalesced loads + 16B stores)
// ---------------------------------------------------------------------------
__global__ __launch_bounds__(256) void gn_kernel(const float* __restrict__ x,
                                                 const float* __restrict__ w,
                                                 const float* __restrict__ bgn) {
    const int b = blockIdx.x >> 5;
    const int g = blockIdx.x & 31;
    const float* xp = x + (size_t)(b * CC + g * CPG) * SS;
    const int t = threadIdx.x;

    float sum = 0.f, sq = 0.f;
    for (int i = t; i < CPG * SS; i += 256) {
        float v = xp[i];
        sum += v;
        sq = fmaf(v, v, sq);
    }
    __shared__ float s1[256], s2[256];
    s1[t] = sum; s2[t] = sq;
    __syncthreads();
    for (int o = 128; o > 0; o >>= 1) {
        if (t < o) { s1[t] += s1[t + o]; s2[t] += s2[t + o]; }
        __syncthreads();
    }
    __shared__ float mean_s, inv_s;
    if (t == 0) {
        const float n_inv = 1.f / (CPG * SS);
        float mean = s1[0] * n_inv;
        float var = s2[0] * n_inv - mean * mean;
        mean_s = mean;
        inv_s = rsqrtf(var + 1e-5f);
    }
    __syncthreads();

    __shared__ float swc[16], sbc[16];
    if (t < 16) {
        int c = g * CPG + t;
        float wc = w[c] * inv_s;
        swc[t] = wc;
        sbc[t] = bgn[c] - mean_s * wc;
    }
    __shared__ __half tile[16][264];
    __syncthreads();

    const int s2i = t >> 1, hb = t & 1;
    for (int chunk = 0; chunk < 4; ++chunk) {
#pragma unroll
        for (int k = 0; k < 16; ++k) {
            float v = xp[k * SS + chunk * 256 + t];
            tile[k][t] = __float2half_rn(fmaf(v, swc[k], sbc[k]));
        }
        __syncthreads();
#pragma unroll
        for (int rep = 0; rep < 2; ++rep) {
            int s = s2i + rep * 128;
            __half v0 = tile[hb * 8 + 0][s], v1 = tile[hb * 8 + 1][s];
            __half v2 = tile[hb * 8 + 2][s], v3 = tile[hb * 8 + 3][s];
            __half v4 = tile[hb * 8 + 4][s], v5 = tile[hb * 8 + 5][s];
            __half v6 = tile[hb * 8 + 6][s], v7 = tile[hb * 8 + 7][s];
            uint4 u;
            u.x = packh2(v0, v1); u.y = packh2(v2, v3);
            u.z = packh2(v4, v5); u.w = packh2(v6, v7);
            size_t off = (size_t)(b * SS + chunk * 256 + s) * CC + g * CPG + hb * 8;
            *reinterpret_cast<uint4*>(g_h_h + off) = u;
        }
        __syncthreads();
    }
}

// ---------------------------------------------------------------------------
// Kernel 2: mma GEMM, 128x64 CTA tile, 3-stage cp.async ring.
// MODE 0 (qkv): pure fp16, 1 pass, 3 CTAs/SM; epi +bias (+SCL on q), fp16 out.
// MODE 1 (out): A single x W hi/lo, 2 passes; epi +bias+residual, fp32 CM.
// ---------------------------------------------------------------------------
#define GP 40                 // fp16 smem pitch (80B rows)

template <int MODE>
__global__ __launch_bounds__(256, MODE == 0 ? 3 : 2) void mma_gemm(
    const __half* __restrict__ Ah,
    const __half* __restrict__ Wh, const __half* __restrict__ Wl,
    const float* __restrict__ bias, const float* __restrict__ xres,
    float* __restrict__ outf, __half* __restrict__ oh, int Ntot) {
    constexpr int GBUF = (MODE == 0) ? 15360 : 20480;
    extern __shared__ __align__(16) char sm[];
    const uint32_t sb = smem_u32(sm);
    const int t = threadIdx.x, w = t >> 5, L = t & 31;
    const int n0 = blockIdx.x * 64;
    const int m0 = blockIdx.y * 128;
    const int wm = w >> 1, wn = w & 1;

    const int arow = L & 15, aseg = L >> 4;
    const int brow = ((L >> 4) << 3) + (L & 7), bcol = ((L >> 3) & 1) * 8;
    const int crow = L >> 2, ccol = (L & 3) * 2;

    float acc[2][4][4] = {};

    auto load_chunk = [&](int kc, int st) {
        const int k0 = kc * 32;
        const uint32_t base = sb + st * GBUF;
#pragma unroll
        for (int rep = 0; rep < 2; ++rep) {
            int c = t + rep * 256;
            int row = c >> 2, ch = c & 3;
            size_t so = (size_t)(m0 + row) * CC + k0 + ch * 8;
            CP_A16(base + row * 80 + ch * 16, Ah + so);
        }
        {
            int row = t >> 2, ch = t & 3;
            size_t so = (size_t)(n0 + row) * CC + k0 + ch * 8;
            CP_A16(base + 10240 + row * 80 + ch * 16, Wh + so);
            if (MODE == 1)
                CP_A16(base + 15360 + row * 80 + ch * 16, Wl + so);
        }
    };

    auto compute = [&](int st) {
        const uint32_t base = sb + st * GBUF;
#pragma unroll
        for (int ks = 0; ks < 2; ++ks) {
            uint32_t ah[2][4], bh[2][4], bl[2][4];
#pragma unroll
            for (int mt = 0; mt < 2; ++mt) {
                uint32_t off = (uint32_t)(((wm * 32 + mt * 16 + arow) * GP +
                                           ks * 16 + aseg * 8) * 2);
                ldm_x4(ah[mt], base + off);
            }
#pragma unroll
            for (int nt = 0; nt < 2; ++nt) {
                uint32_t off = (uint32_t)(((wn * 32 + nt * 16 + brow) * GP +
                                           ks * 16 + bcol) * 2);
                ldm_x4(bh[nt], base + 10240 + off);
                if (MODE == 1) ldm_x4(bl[nt], base + 15360 + off);
            }
#pragma unroll
            for (int mt = 0; mt < 2; ++mt)
#pragma unroll
                for (int n8 = 0; n8 < 4; ++n8)
                    mma_f16(acc[mt][n8], ah[mt], &bh[n8 >> 1][(n8 & 1) * 2]);
            if (MODE == 1) {
#pragma unroll
                for (int mt = 0; mt < 2; ++mt)
#pragma unroll
                    for (int n8 = 0; n8 < 4; ++n8)
                        mma_f16(acc[mt][n8], ah[mt], &bl[n8 >> 1][(n8 & 1) * 2]);
            }
        }
    };

    load_chunk(0, 0); CP_COMMIT();
    load_chunk(1, 1); CP_COMMIT();
    int cs = 0, ls = 2;
    for (int kc = 0; kc < 16; ++kc) {
        if (kc < 15) CP_WAIT1(); else CP_WAIT0();
        __syncthreads();
        compute(cs);
        if (kc < 14) { load_chunk(kc + 2, ls); CP_COMMIT(); }
        cs = (cs == 2) ? 0 : cs + 1;
        ls = (ls == 2) ? 0 : ls + 1;
    }
    __syncthreads();   // buffers free before stage aliasing

    float* stage = reinterpret_cast<float*>(sm);
    const int PITCH = (MODE == 0) ? 68 : 65;
#pragma unroll
    for (int mt = 0; mt < 2; ++mt)
#pragma unroll
        for (int n8 = 0; n8 < 4; ++n8) {
            int r = wm * 32 + mt * 16 + crow;
            int c = wn * 32 + n8 * 8 + ccol;
            stage[r * PITCH + c]           = acc[mt][n8][0];
            stage[r * PITCH + c + 1]       = acc[mt][n8][1];
            stage[(r + 8) * PITCH + c]     = acc[mt][n8][2];
            stage[(r + 8) * PITCH + c + 1] = acc[mt][n8][3];
        }
    __syncthreads();

    if (MODE == 0) {
        // q tiles (n0 % 192 == 0) get the folded softmax scale
        const float scale = (n0 % 192 == 0) ? SCL : 1.0f;
#pragma unroll
        for (int i = 0; i < 8; ++i) {
            int f = t + 256 * i;
            int row = f >> 4, c4 = f & 15;
            float4 v = *(const float4*)&stage[row * 68 + c4 * 4];
            float4 bb = *(const float4*)&bias[n0 + c4 * 4];
            uint2 hv = make_uint2(pack2((v.x + bb.x) * scale, (v.y + bb.y) * scale),
                                  pack2((v.z + bb.z) * scale, (v.w + bb.w) * scale));
            size_t go = (size_t)(m0 + row) * Ntot + n0 + c4 * 4;
            *reinterpret_cast<uint2*>(oh + go) = hv;
        }
    } else {
        const int b = m0 >> 10;
        const int s0 = m0 & 1023;
#pragma unroll
        for (int i = 0; i < 32; ++i) {
            int idx = i * 256 + t;
            int c = idx >> 7, srow = idx & 127;
            size_t gi = (size_t)(b * CC + n0 + c) * SS + s0 + srow;
            outf[gi] = stage[srow * 65 + c] + bias[n0 + c] + xres[gi];
        }
    }
}

// ---------------------------------------------------------------------------
// Kernel 3: flash attention, 128 queries/CTA, warp owns 16 full rows.
// Q (pre-scaled), K, V single fp16.  QK^T 1 pass, PV 1 pass.
// Double-buffered K/V.  ex2.approx.f16x2 softmax (2 exps / MUFU op).
// ---------------------------------------------------------------------------
#define AP 72
#define A_Q  0                    // Q: 128 x 144B
#define A_KB 18432                // K stage i at A_KB + i*9216
#define A_VB 36864                // V stage i at A_VB + i*9216
#define ATT_SMEM 55296

__global__ __launch_bounds__(256, 2) void attn_mma() {
    extern __shared__ __align__(16) char sm[];
    const uint32_t sb = smem_u32(sm);

    const int i0 = blockIdx.x * 128;
    const int bh = blockIdx.y;
    const int b = bh >> 3, h = bh & 7;
    const int t = threadIdx.x, w = t >> 5, L = t & 31;

    const int arow = L & 15, aseg = L >> 4;
    const int brow = ((L >> 4) << 3) + (L & 7), bcol = ((L >> 3) & 1) * 8;
    const int crow = L >> 2, ccol = (L & 3) * 2;

    const __half* qk = g_qkv_h + (size_t)b * SS * QKVC + h * 192;

    auto cp_kv = [&](uint32_t base, const __half* src) {
#pragma unroll
        for (int rep = 0; rep < 2; ++rep) {
            int c = t + rep * 256;
            int row = c >> 3, ch = c & 7;
            CP_A16(base + row * 144 + ch * 16, src + (size_t)row * QKVC + ch * 8);
        }
    };

    // prologue groups: 0 = Q+K(0), 1 = V(0), 2 = K(1)
    {
        const __half* sq = qk + (size_t)i0 * QKVC;
#pragma unroll
        for (int rep = 0; rep < 4; ++rep) {
            int c = t + rep * 256;
            int row = c >> 3, ch = c & 7;
            CP_A16(sb + A_Q + row * 144 + ch * 16, sq + (size_t)row * QKVC + ch * 8);
        }
    }
    cp_kv(sb + A_KB, qk + 64);
    CP_COMMIT();
    cp_kv(sb + A_VB, qk + 128);
    CP_COMMIT();
    cp_kv(sb + A_KB + 9216, qk + (size_t)64 * QKVC + 64);
    CP_COMMIT();

    float m0 = -1e30f, m1 = -1e30f, l0 = 0.f, l1 = 0.f;
    float o[8][4] = {};

    for (int j = 0; j < 16; ++j) {
        const uint32_t kbase = sb + A_KB + (j & 1) * 9216;
        const uint32_t vbase = sb + A_VB + (j & 1) * 9216;

        if (j < 15) CP_WAIT2(); else CP_WAIT1();   // K(j) ready
        __syncthreads();

        // ---- S = Q K^T : 1 pass (scale already folded into Q) ----
        float sc[8][4] = {};
#pragma unroll
        for (int ks = 0; ks < 4; ++ks) {
            uint32_t aoff = (uint32_t)(((w * 16 + arow) * AP + ks * 16 + aseg * 8) * 2);
            uint32_t ah[4];
            ldm_x4(ah, sb + A_Q + aoff);
            uint32_t bh_[4][4];
#pragma unroll
            for (int nt = 0; nt < 4; ++nt) {
                uint32_t boff = (uint32_t)(((nt * 16 + brow) * AP +
                                            ks * 16 + bcol) * 2);
                ldm_x4(bh_[nt], kbase + boff);
            }
#pragma unroll
            for (int n8 = 0; n8 < 8; ++n8)
                mma_f16(sc[n8], ah, &bh_[n8 >> 1][(n8 & 1) * 2]);
        }

        if (j < 15) {             // prefetch V(j+1) into other V buffer
            size_t nb = (size_t)(j + 1) * 64 * QKVC;
            cp_kv(sb + A_VB + ((j + 1) & 1) * 9216, qk + nb + 128);
            CP_COMMIT();
        }

        // ---- register softmax (base-2 domain) ----
        float mx0 = -1e30f, mx1 = -1e30f;
#pragma unroll
        for (int n8 = 0; n8 < 8; ++n8) {
            mx0 = fmaxf(mx0, fmaxf(sc[n8][0], sc[n8][1]));
            mx1 = fmaxf(mx1, fmaxf(sc[n8][2], sc[n8][3]));
        }
        mx0 = fmaxf(mx0, __shfl_xor_sync(0xffffffff, mx0, 1));
        mx0 = fmaxf(mx0, __shfl_xor_sync(0xffffffff, mx0, 2));
        mx1 = fmaxf(mx1, __shfl_xor_sync(0xffffffff, mx1, 1));
        mx1 = fmaxf(mx1, __shfl_xor_sync(0xffffffff, mx1, 2));

        float mn0 = fmaxf(m0, mx0), mn1 = fmaxf(m1, mx1);
        float a0 = exp2f(m0 - mn0), a1 = exp2f(m1 - mn1);
        m0 = mn0; m1 = mn1;

        // exp via ex2.approx.f16x2: fp16 P fragments; l-sum from the SAME
        // fp16-rounded values so numerator/denominator stay consistent.
        uint32_t ph[4][4];
        float s0 = 0.f, s1 = 0.f;
#pragma unroll
        for (int g = 0; g < 4; ++g)
#pragma unroll
            for (int hf = 0; hf < 2; ++hf) {
                int tile = g * 2 + hf;
                uint32_t p0 = exp2_h2(sc[tile][0] - mn0, sc[tile][1] - mn0);
                uint32_t p1 = exp2_h2(sc[tile][2] - mn1, sc[tile][3] - mn1);
                ph[g][hf * 2]     = p0;
                ph[g][hf * 2 + 1] = p1;
                float2 f0 = __half22float2(*reinterpret_cast<__half2*>(&p0));
                float2 f1 = __half22float2(*reinterpret_cast<__half2*>(&p1));
                s0 += f0.x + f0.y;
                s1 += f1.x + f1.y;
            }
        s0 += __shfl_xor_sync(0xffffffff, s0, 1);
        s0 += __shfl_xor_sync(0xffffffff, s0, 2);
        s1 += __shfl_xor_sync(0xffffffff, s1, 1);
        s1 += __shfl_xor_sync(0xffffffff, s1, 2);
        l0 = fmaf(l0, a0, s0);
        l1 = fmaf(l1, a1, s1);

#pragma unroll
        for (int n8 = 0; n8 < 8; ++n8) {
            o[n8][0] *= a0; o[n8][1] *= a0;
            o[n8][2] *= a1; o[n8][3] *= a1;
        }

        if (j < 15) CP_WAIT2(); else CP_WAIT0();   // V(j) ready
        __syncthreads();

        // ---- O += P V : 1 pass ----
#pragma unroll
        for (int g = 0; g < 4; ++g) {
            int krow = g * 16 + ((L >> 3) & 1) * 8 + (L & 7);
            uint32_t vh[4][4];
#pragma unroll
            for (int nt = 0; nt < 4; ++nt) {
                int dcol = nt * 16 + (L >> 4) * 8;
                ldm_x4_t(vh[nt], vbase + (uint32_t)((krow * AP + dcol) * 2));
            }
#pragma unroll
            for (int n8 = 0; n8 < 8; ++n8)
                mma_f16(o[n8], ph[g], &vh[n8 >> 1][(n8 & 1) * 2]);
        }

        if (j < 14) {             // prefetch K(j+2) into other K buffer
            size_t nb = (size_t)(j + 2) * 64 * QKVC;
            cp_kv(sb + A_KB + (j & 1) * 9216, qk + nb + 64);
            CP_COMMIT();
        }
    }

    // ---- normalize + store single fp16 ----
    float inv0 = 1.f / l0, inv1 = 1.f / l1;
#pragma unroll
    for (int n8 = 0; n8 < 8; ++n8) {
        int d = n8 * 8 + ccol;
        uint32_t h0 = pack2(o[n8][0] * inv0, o[n8][1] * inv0);
        uint32_t h1 = pack2(o[n8][2] * inv1, o[n8][3] * inv1);
        size_t g0 = (size_t)(b * SS + i0 + w * 16 + crow) * CC + h * DK + d;
        size_t g1 = g0 + (size_t)8 * CC;
        *reinterpret_cast<uint32_t*>(g_ao_h + g0) = h0;
        *reinterpret_cast<uint32_t*>(g_ao_h + g1) = h1;
    }
}

// ---------------------------------------------------------------------------
extern "C" void kernel_launch(void* const* d_in, const int* in_sizes, int n_in,
                              void* d_out, int out_size) {
    const float* x = (const float*)d_in[0];
    const float* gn_w = (const float*)d_in[1];
    const float* gn_b = (const float*)d_in[2];
    const float* proj_w = (const float*)d_in[3];
    const float* proj_b = (const float*)d_in[4];
    const float* out_w = (const float*)d_in[5];
    const float* out_b = (const float*)d_in[6];
    float* out = (float*)d_out;

    __half *d_hh, *d_qh, *d_aoh, *d_pwh, *d_owh, *d_owl;
    cudaGetSymbolAddress((void**)&d_hh, g_h_h);
    cudaGetSymbolAddress((void**)&d_qh, g_qkv_h);
    cudaGetSymbolAddress((void**)&d_aoh, g_ao_h);
    cudaGetSymbolAddress((void**)&d_pwh, g_pw_h);
    cudaGetSymbolAddress((void**)&d_owh, g_ow_h);
    cudaGetSymbolAddress((void**)&d_owl, g_ow_l);

    const int SMEM0 = 3 * 15360;
    const int SMEM1 = 3 * 20480;
    cudaFuncSetAttribute(mma_gemm<0>, cudaFuncAttributeMaxDynamicSharedMemorySize, SMEM0);
    cudaFuncSetAttribute(mma_gemm<1>, cudaFuncAttributeMaxDynamicSharedMemorySize, SMEM1);
    cudaFuncSetAttribute(attn_mma, cudaFuncAttributeMaxDynamicSharedMemorySize, ATT_SMEM);

    const int n1 = QKVC * CC / 4, n2 = CC * CC / 4;
    cvt_w2<<<(n1 + n2 + 255) / 256, 256>>>(proj_w, d_pwh, n1,
                                           out_w, d_owh, d_owl, n2);
    gn_kernel<<<BB * NG, 256>>>(x, gn_w, gn_b);

    mma_gemm<0><<<dim3(QKVC / 64, BB * SS / 128), 256, SMEM0>>>(
        d_hh, d_pwh, nullptr, proj_b, nullptr, nullptr, d_qh, QKVC);

    attn_mma<<<dim3(SS / 128, BB * NH), 256, ATT_SMEM>>>();

    mma_gemm<1><<<dim3(CC / 64, BB * SS / 128), 256, SMEM1>>>(
        d_aoh, d_owh, d_owl, out_b, x, out, nullptr, CC);
}

// round 15
// speedup vs baseline: 6.3196x; 1.0369x over previous
#include <cuda_runtime.h>
#include <cuda_fp16.h>
#include <cstdint>

// Shapes: B=16, C=512, H=W=32 -> S=1024, 32 groups (16 ch/group), 8 heads, D=64.
#define BB 16
#define CC 512
#define SS 1024
#define NG 32
#define CPG 16
#define NH 8
#define DK 64
#define QKVC 1536

// fp16 storage (hi/lo split only where error does NOT dilute)
static __device__ __half g_h_h[BB * SS * CC];        // gn out: single fp16
static __device__ __half g_qkv_h[BB * SS * QKVC];    // qkv: single fp16 (q pre-scaled)
static __device__ __half g_ao_h[BB * SS * CC];       // ao: single fp16
static __device__ __half g_pw_h[QKVC * CC];          // proj_w: single fp16
static __device__ __half g_ow_h[CC * CC];            // out_w: hi/lo
static __device__ __half g_ow_l[CC * CC];

#define SCL 0.18033688011112042f  // 0.125 * log2(e), folded into q

// ============================================================================
// helpers
// ============================================================================
__device__ __forceinline__ uint32_t smem_u32(const void* p) {
    uint32_t a;
    asm("{ .reg .u64 t; cvta.to.shared.u64 t, %1; cvt.u32.u64 %0, t; }"
        : "=r"(a) : "l"(p));
    return a;
}

__device__ __forceinline__ void ldm_x4(uint32_t* r, uint32_t addr) {
    asm volatile("ldmatrix.sync.aligned.m8n8.x4.shared.b16 {%0,%1,%2,%3}, [%4];"
                 : "=r"(r[0]), "=r"(r[1]), "=r"(r[2]), "=r"(r[3]) : "r"(addr));
}
__device__ __forceinline__ void ldm_x4_t(uint32_t* r, uint32_t addr) {
    asm volatile("ldmatrix.sync.aligned.m8n8.x4.trans.shared.b16 {%0,%1,%2,%3}, [%4];"
                 : "=r"(r[0]), "=r"(r[1]), "=r"(r[2]), "=r"(r[3]) : "r"(addr));
}

__device__ __forceinline__ void mma_f16(float* c, const uint32_t* a, const uint32_t* b) {
    asm volatile(
        "mma.sync.aligned.m16n8k16.row.col.f32.f16.f16.f32 "
        "{%0,%1,%2,%3}, {%4,%5,%6,%7}, {%8,%9}, {%0,%1,%2,%3};"
        : "+f"(c[0]), "+f"(c[1]), "+f"(c[2]), "+f"(c[3])
        : "r"(a[0]), "r"(a[1]), "r"(a[2]), "r"(a[3]), "r"(b[0]), "r"(b[1]));
}

#define CP_A16(dst, src) \
    asm volatile("cp.async.cg.shared.global [%0], [%1], 16;" :: "r"(dst), "l"(src))
#define CP_COMMIT() asm volatile("cp.async.commit_group;" ::: "memory")
#define CP_WAIT0()  asm volatile("cp.async.wait_group 0;" ::: "memory")
#define CP_WAIT1()  asm volatile("cp.async.wait_group 1;" ::: "memory")
#define CP_WAIT2()  asm volatile("cp.async.wait_group 2;" ::: "memory")

// fp32 pair -> packed fp16 hi + packed fp16 lo
__device__ __forceinline__ void split2(float a, float b, uint32_t& h, uint32_t& l) {
    __half2 hp = __floats2half2_rn(a, b);
    float2 hf = __half22float2(hp);
    __half2 lp = __floats2half2_rn(a - hf.x, b - hf.y);
    h = *reinterpret_cast<uint32_t*>(&hp);
    l = *reinterpret_cast<uint32_t*>(&lp);
}

__device__ __forceinline__ uint32_t pack2(float a, float b) {
    __half2 hp = __floats2half2_rn(a, b);
    return *reinterpret_cast<uint32_t*>(&hp);
}

__device__ __forceinline__ uint32_t packh2(__half a, __half b) {
    __half2 hp = __halves2half2(a, b);
    return *reinterpret_cast<uint32_t*>(&hp);
}

// 2x exp2 in one MUFU op, result packed fp16x2 (mma-ready)
__device__ __forceinline__ uint32_t exp2_h2(float a, float b) {
    __half2 hv = __floats2half2_rn(a, b);
    uint32_t r;
    asm("ex2.approx.f16x2 %0, %1;" : "=r"(r) : "r"(*reinterpret_cast<uint32_t*>(&hv)));
    return r;
}

// ---------------------------------------------------------------------------
// Kernel 0: one-time weight conversion: proj_w -> single fp16; out_w -> hi/lo
// ---------------------------------------------------------------------------
__global__ __launch_bounds__(256) void cvt_w2(
    const float* __restrict__ w1, __half* __restrict__ h1, int n1,
    const float* __restrict__ w2, __half* __restrict__ h2,
    __half* __restrict__ l2, int n2) {
    int i = blockIdx.x * 256 + threadIdx.x;
    if (i < n1) {
        float4 v = reinterpret_cast<const float4*>(w1)[i];
        uint2 hv = make_uint2(pack2(v.x, v.y), pack2(v.z, v.w));
        reinterpret_cast<uint2*>(h1)[i] = hv;
    } else if (i < n1 + n2) {
        i -= n1;
        float4 v = reinterpret_cast<const float4*>(w2)[i];
        uint2 hv, lv;
        split2(v.x, v.y, hv.x, lv.x);
        split2(v.z, v.w, hv.y, lv.y);
        reinterpret_cast<uint2*>(h2)[i] = hv;
        reinterpret_cast<uint2*>(l2)[i] = lv;
    }
}

// ---------------------------------------------------------------------------
// Kernel 1: GroupNorm, smem-transposed pass 2 (coalesced loads + 16B stores)
// ---------------------------------------------------------------------------
__global__ __launch_bounds__(256) void gn_kernel(const float* __restrict__ x,
                                                 const float* __restrict__ w,
                                                 const float* __restrict__ bgn) {
    const int b = blockIdx.x >> 5;
    const int g = blockIdx.x & 31;
    const float* xp = x + (size_t)(b * CC + g * CPG) * SS;
    const int t = threadIdx.x;

    float sum = 0.f, sq = 0.f;
    for (int i = t; i < CPG * SS; i += 256) {
        float v = xp[i];
        sum += v;
        sq = fmaf(v, v, sq);
    }
    __shared__ float s1[256], s2[256];
    s1[t] = sum; s2[t] = sq;
    __syncthreads();
    for (int o = 128; o > 0; o >>= 1) {
        if (t < o) { s1[t] += s1[t + o]; s2[t] += s2[t + o]; }
        __syncthreads();
    }
    __shared__ float mean_s, inv_s;
    if (t == 0) {
        const float n_inv = 1.f / (CPG * SS);
        float mean = s1[0] * n_inv;
        float var = s2[0] * n_inv - mean * mean;
        mean_s = mean;
        inv_s = rsqrtf(var + 1e-5f);
    }
    __syncthreads();

    __shared__ float swc[16], sbc[16];
    if (t < 16) {
        int c = g * CPG + t;
        float wc = w[c] * inv_s;
        swc[t] = wc;
        sbc[t] = bgn[c] - mean_s * wc;
    }
    __shared__ __half tile[16][264];
    __syncthreads();

    const int s2i = t >> 1, hb = t & 1;
    for (int chunk = 0; chunk < 4; ++chunk) {
#pragma unroll
        for (int k = 0; k < 16; ++k) {
            float v = xp[k * SS + chunk * 256 + t];
            tile[k][t] = __float2half_rn(fmaf(v, swc[k], sbc[k]));
        }
        __syncthreads();
#pragma unroll
        for (int rep = 0; rep < 2; ++rep) {
            int s = s2i + rep * 128;
            __half v0 = tile[hb * 8 + 0][s], v1 = tile[hb * 8 + 1][s];
            __half v2 = tile[hb * 8 + 2][s], v3 = tile[hb * 8 + 3][s];
            __half v4 = tile[hb * 8 + 4][s], v5 = tile[hb * 8 + 5][s];
            __half v6 = tile[hb * 8 + 6][s], v7 = tile[hb * 8 + 7][s];
            uint4 u;
            u.x = packh2(v0, v1); u.y = packh2(v2, v3);
            u.z = packh2(v4, v5); u.w = packh2(v6, v7);
            size_t off = (size_t)(b * SS + chunk * 256 + s) * CC + g * CPG + hb * 8;
            *reinterpret_cast<uint4*>(g_h_h + off) = u;
        }
        __syncthreads();
    }
}

// ---------------------------------------------------------------------------
// Kernel 2: mma GEMM, 128x64 CTA tile, 3-stage cp.async ring, 3 CTAs/SM.
// MODE 0 (qkv): pure fp16, 1 pass; epi +bias (+SCL on q), fp16 out.
// MODE 1 (out): A single x W hi/lo, 2 passes; epi +bias+residual, fp32 CM.
// ---------------------------------------------------------------------------
#define GP 40                 // fp16 smem pitch (80B rows)

template <int MODE>
__global__ __launch_bounds__(256, 3) void mma_gemm(
    const __half* __restrict__ Ah,
    const __half* __restrict__ Wh, const __half* __restrict__ Wl,
    const float* __restrict__ bias, const float* __restrict__ xres,
    float* __restrict__ outf, __half* __restrict__ oh, int Ntot) {
    constexpr int GBUF = (MODE == 0) ? 15360 : 20480;
    extern __shared__ __align__(16) char sm[];
    const uint32_t sb = smem_u32(sm);
    const int t = threadIdx.x, w = t >> 5, L = t & 31;
    const int n0 = blockIdx.x * 64;
    const int m0 = blockIdx.y * 128;
    const int wm = w >> 1, wn = w & 1;

    const int arow = L & 15, aseg = L >> 4;
    const int brow = ((L >> 4) << 3) + (L & 7), bcol = ((L >> 3) & 1) * 8;
    const int crow = L >> 2, ccol = (L & 3) * 2;

    float acc[2][4][4] = {};

    auto load_chunk = [&](int kc, int st) {
        const int k0 = kc * 32;
        const uint32_t base = sb + st * GBUF;
#pragma unroll
        for (int rep = 0; rep < 2; ++rep) {
            int c = t + rep * 256;
            int row = c >> 2, ch = c & 3;
            size_t so = (size_t)(m0 + row) * CC + k0 + ch * 8;
            CP_A16(base + row * 80 + ch * 16, Ah + so);
        }
        {
            int row = t >> 2, ch = t & 3;
            size_t so = (size_t)(n0 + row) * CC + k0 + ch * 8;
            CP_A16(base + 10240 + row * 80 + ch * 16, Wh + so);
            if (MODE == 1)
                CP_A16(base + 15360 + row * 80 + ch * 16, Wl + so);
        }
    };

    auto compute = [&](int st) {
        const uint32_t base = sb + st * GBUF;
#pragma unroll
        for (int ks = 0; ks < 2; ++ks) {
            uint32_t ah[2][4], bh[2][4], bl[2][4];
#pragma unroll
            for (int mt = 0; mt < 2; ++mt) {
                uint32_t off = (uint32_t)(((wm * 32 + mt * 16 + arow) * GP +
                                           ks * 16 + aseg * 8) * 2);
                ldm_x4(ah[mt], base + off);
            }
#pragma unroll
            for (int nt = 0; nt < 2; ++nt) {
                uint32_t off = (uint32_t)(((wn * 32 + nt * 16 + brow) * GP +
                                           ks * 16 + bcol) * 2);
                ldm_x4(bh[nt], base + 10240 + off);
                if (MODE == 1) ldm_x4(bl[nt], base + 15360 + off);
            }
#pragma unroll
            for (int mt = 0; mt < 2; ++mt)
#pragma unroll
                for (int n8 = 0; n8 < 4; ++n8)
                    mma_f16(acc[mt][n8], ah[mt], &bh[n8 >> 1][(n8 & 1) * 2]);
            if (MODE == 1) {
#pragma unroll
                for (int mt = 0; mt < 2; ++mt)
#pragma unroll
                    for (int n8 = 0; n8 < 4; ++n8)
                        mma_f16(acc[mt][n8], ah[mt], &bl[n8 >> 1][(n8 & 1) * 2]);
            }
        }
    };

    load_chunk(0, 0); CP_COMMIT();
    load_chunk(1, 1); CP_COMMIT();
    int cs = 0, ls = 2;
    for (int kc = 0; kc < 16; ++kc) {
        if (kc < 15) CP_WAIT1(); else CP_WAIT0();
        __syncthreads();
        compute(cs);
        if (kc < 14) { load_chunk(kc + 2, ls); CP_COMMIT(); }
        cs = (cs == 2) ? 0 : cs + 1;
        ls = (ls == 2) ? 0 : ls + 1;
    }
    __syncthreads();   // buffers free before stage aliasing

    float* stage = reinterpret_cast<float*>(sm);
    const int PITCH = (MODE == 0) ? 68 : 65;
#pragma unroll
    for (int mt = 0; mt < 2; ++mt)
#pragma unroll
        for (int n8 = 0; n8 < 4; ++n8) {
            int r = wm * 32 + mt * 16 + crow;
            int c = wn * 32 + n8 * 8 + ccol;
            stage[r * PITCH + c]           = acc[mt][n8][0];
            stage[r * PITCH + c + 1]       = acc[mt][n8][1];
            stage[(r + 8) * PITCH + c]     = acc[mt][n8][2];
            stage[(r + 8) * PITCH + c + 1] = acc[mt][n8][3];
        }
    __syncthreads();

    if (MODE == 0) {
        // q tiles (n0 % 192 == 0) get the folded softmax scale
        const float scale = (n0 % 192 == 0) ? SCL : 1.0f;
#pragma unroll
        for (int i = 0; i < 8; ++i) {
            int f = t + 256 * i;
            int row = f >> 4, c4 = f & 15;
            float4 v = *(const float4*)&stage[row * 68 + c4 * 4];
            float4 bb = *(const float4*)&bias[n0 + c4 * 4];
            uint2 hv = make_uint2(pack2((v.x + bb.x) * scale, (v.y + bb.y) * scale),
                                  pack2((v.z + bb.z) * scale, (v.w + bb.w) * scale));
            size_t go = (size_t)(m0 + row) * Ntot + n0 + c4 * 4;
            *reinterpret_cast<uint2*>(oh + go) = hv;
        }
    } else {
        const int b = m0 >> 10;
        const int s0 = m0 & 1023;
#pragma unroll
        for (int i = 0; i < 32; ++i) {
            int idx = i * 256 + t;
            int c = idx >> 7, srow = idx & 127;
            size_t gi = (size_t)(b * CC + n0 + c) * SS + s0 + srow;
            outf[gi] = stage[srow * 65 + c] + bias[n0 + c] + xres[gi];
        }
    }
}

// ---------------------------------------------------------------------------
// Kernel 3: flash attention, 128 queries/CTA, warp owns 16 full rows.
// Q fragments hoisted out of the j loop (loop-invariant).  K, V single fp16.
// QK^T 1 pass, PV 1 pass.  Double-buffered K/V.  ex2.approx.f16x2 softmax.
// ---------------------------------------------------------------------------
#define AP 72
#define A_Q  0                    // Q: 128 x 144B
#define A_KB 18432                // K stage i at A_KB + i*9216
#define A_VB 36864                // V stage i at A_VB + i*9216
#define ATT_SMEM 55296

__global__ __launch_bounds__(256, 2) void attn_mma() {
    extern __shared__ __align__(16) char sm[];
    const uint32_t sb = smem_u32(sm);

    const int i0 = blockIdx.x * 128;
    const int bh = blockIdx.y;
    const int b = bh >> 3, h = bh & 7;
    const int t = threadIdx.x, w = t >> 5, L = t & 31;

    const int arow = L & 15, aseg = L >> 4;
    const int brow = ((L >> 4) << 3) + (L & 7), bcol = ((L >> 3) & 1) * 8;
    const int crow = L >> 2, ccol = (L & 3) * 2;

    const __half* qk = g_qkv_h + (size_t)b * SS * QKVC + h * 192;

    auto cp_kv = [&](uint32_t base, const __half* src) {
#pragma unroll
        for (int rep = 0; rep < 2; ++rep) {
            int c = t + rep * 256;
            int row = c >> 3, ch = c & 7;
            CP_A16(base + row * 144 + ch * 16, src + (size_t)row * QKVC + ch * 8);
        }
    };

    // prologue groups: 0 = Q+K(0), 1 = V(0), 2 = K(1)
    {
        const __half* sq = qk + (size_t)i0 * QKVC;
#pragma unroll
        for (int rep = 0; rep < 4; ++rep) {
            int c = t + rep * 256;
            int row = c >> 3, ch = c & 7;
            CP_A16(sb + A_Q + row * 144 + ch * 16, sq + (size_t)row * QKVC + ch * 8);
        }
    }
    cp_kv(sb + A_KB, qk + 64);
    CP_COMMIT();
    cp_kv(sb + A_VB, qk + 128);
    CP_COMMIT();
    cp_kv(sb + A_KB + 9216, qk + (size_t)64 * QKVC + 64);
    CP_COMMIT();

    // ---- hoist Q fragments (loop-invariant): wait group 0, load once ----
    CP_WAIT2();                   // Q + K(0) landed
    __syncthreads();
    uint32_t qf[4][4];
#pragma unroll
    for (int ks = 0; ks < 4; ++ks) {
        uint32_t aoff = (uint32_t)(((w * 16 + arow) * AP + ks * 16 + aseg * 8) * 2);
        ldm_x4(qf[ks], sb + A_Q + aoff);
    }

    float m0 = -1e30f, m1 = -1e30f, l0 = 0.f, l1 = 0.f;
    float o[8][4] = {};

    for (int j = 0; j < 16; ++j) {
        const uint32_t kbase = sb + A_KB + (j & 1) * 9216;
        const uint32_t vbase = sb + A_VB + (j & 1) * 9216;

        if (j > 0) {              // j=0 wait already done above
            if (j < 15) CP_WAIT2(); else CP_WAIT1();   // K(j) ready
            __syncthreads();
        }

        // ---- S = Q K^T : 1 pass (Q frags in registers) ----
        float sc[8][4] = {};
#pragma unroll
        for (int ks = 0; ks < 4; ++ks) {
            uint32_t bh_[4][4];
#pragma unroll
            for (int nt = 0; nt < 4; ++nt) {
                uint32_t boff = (uint32_t)(((nt * 16 + brow) * AP +
                                            ks * 16 + bcol) * 2);
                ldm_x4(bh_[nt], kbase + boff);
            }
#pragma unroll
            for (int n8 = 0; n8 < 8; ++n8)
                mma_f16(sc[n8], qf[ks], &bh_[n8 >> 1][(n8 & 1) * 2]);
        }

        if (j < 15) {             // prefetch V(j+1) into other V buffer
            size_t nb = (size_t)(j + 1) * 64 * QKVC;
            cp_kv(sb + A_VB + ((j + 1) & 1) * 9216, qk + nb + 128);
            CP_COMMIT();
        }

        // ---- register softmax (base-2 domain) ----
        float mx0 = -1e30f, mx1 = -1e30f;
#pragma unroll
        for (int n8 = 0; n8 < 8; ++n8) {
            mx0 = fmaxf(mx0, fmaxf(sc[n8][0], sc[n8][1]));
            mx1 = fmaxf(mx1, fmaxf(sc[n8][2], sc[n8][3]));
        }
        mx0 = fmaxf(mx0, __shfl_xor_sync(0xffffffff, mx0, 1));
        mx0 = fmaxf(mx0, __shfl_xor_sync(0xffffffff, mx0, 2));
        mx1 = fmaxf(mx1, __shfl_xor_sync(0xffffffff, mx1, 1));
        mx1 = fmaxf(mx1, __shfl_xor_sync(0xffffffff, mx1, 2));

        float mn0 = fmaxf(m0, mx0), mn1 = fmaxf(m1, mx1);
        float a0 = exp2f(m0 - mn0), a1 = exp2f(m1 - mn1);
        m0 = mn0; m1 = mn1;

        // exp via ex2.approx.f16x2; l-sum from the SAME fp16-rounded values.
        uint32_t ph[4][4];
        float s0 = 0.f, s1 = 0.f;
#pragma unroll
        for (int g = 0; g < 4; ++g)
#pragma unroll
            for (int hf = 0; hf < 2; ++hf) {
                int tile = g * 2 + hf;
                uint32_t p0 = exp2_h2(sc[tile][0] - mn0, sc[tile][1] - mn0);
                uint32_t p1 = exp2_h2(sc[tile][2] - mn1, sc[tile][3] - mn1);
                ph[g][hf * 2]     = p0;
                ph[g][hf * 2 + 1] = p1;
                float2 f0 = __half22float2(*reinterpret_cast<__half2*>(&p0));
                float2 f1 = __half22float2(*reinterpret_cast<__half2*>(&p1));
                s0 += f0.x + f0.y;
                s1 += f1.x + f1.y;
            }
        s0 += __shfl_xor_sync(0xffffffff, s0, 1);
        s0 += __shfl_xor_sync(0xffffffff, s0, 2);
        s1 += __shfl_xor_sync(0xffffffff, s1, 1);
        s1 += __shfl_xor_sync(0xffffffff, s1, 2);
        l0 = fmaf(l0, a0, s0);
        l1 = fmaf(l1, a1, s1);

#pragma unroll
        for (int n8 = 0; n8 < 8; ++n8) {
            o[n8][0] *= a0; o[n8][1] *= a0;
            o[n8][2] *= a1; o[n8][3] *= a1;
        }

        if (j < 15) CP_WAIT2(); else CP_WAIT0();   // V(j) ready
        __syncthreads();

        // ---- O += P V : 1 pass ----
#pragma unroll
        for (int g = 0; g < 4; ++g) {
            int krow = g * 16 + ((L >> 3) & 1) * 8 + (L & 7);
            uint32_t vh[4][4];
#pragma unroll
            for (int nt = 0; nt < 4; ++nt) {
                int dcol = nt * 16 + (L >> 4) * 8;
                ldm_x4_t(vh[nt], vbase + (uint32_t)((krow * AP + dcol) * 2));
            }
#pragma unroll
            for (int n8 = 0; n8 < 8; ++n8)
                mma_f16(o[n8], ph[g], &vh[n8 >> 1][(n8 & 1) * 2]);
        }

        if (j < 14) {             // prefetch K(j+2) into other K buffer
            size_t nb = (size_t)(j + 2) * 64 * QKVC;
            cp_kv(sb + A_KB + (j & 1) * 9216, qk + nb + 64);
            CP_COMMIT();
        }
    }

    // ---- normalize + store single fp16 ----
    float inv0 = 1.f / l0, inv1 = 1.f / l1;
#pragma unroll
    for (int n8 = 0; n8 < 8; ++n8) {
        int d = n8 * 8 + ccol;
        uint32_t h0 = pack2(o[n8][0] * inv0, o[n8][1] * inv0);
        uint32_t h1 = pack2(o[n8][2] * inv1, o[n8][3] * inv1);
        size_t g0 = (size_t)(b * SS + i0 + w * 16 + crow) * CC + h * DK + d;
        size_t g1 = g0 + (size_t)8 * CC;
        *reinterpret_cast<uint32_t*>(g_ao_h + g0) = h0;
        *reinterpret_cast<uint32_t*>(g_ao_h + g1) = h1;
    }
}

// ---------------------------------------------------------------------------
extern "C" void kernel_launch(void* const* d_in, const int* in_sizes, int n_in,
                              void* d_out, int out_size) {
    const float* x = (const float*)d_in[0];
    const float* gn_w = (const float*)d_in[1];
    const float* gn_b = (const float*)d_in[2];
    const float* proj_w = (const float*)d_in[3];
    const float* proj_b = (const float*)d_in[4];
    const float* out_w = (const float*)d_in[5];
    const float* out_b = (const float*)d_in[6];
    float* out = (float*)d_out;

    __half *d_hh, *d_qh, *d_aoh, *d_pwh, *d_owh, *d_owl;
    cudaGetSymbolAddress((void**)&d_hh, g_h_h);
    cudaGetSymbolAddress((void**)&d_qh, g_qkv_h);
    cudaGetSymbolAddress((void**)&d_aoh, g_ao_h);
    cudaGetSymbolAddress((void**)&d_pwh, g_pw_h);
    cudaGetSymbolAddress((void**)&d_owh, g_ow_h);
    cudaGetSymbolAddress((void**)&d_owl, g_ow_l);

    const int SMEM0 = 3 * 15360;
    const int SMEM1 = 3 * 20480;
    cudaFuncSetAttribute(mma_gemm<0>, cudaFuncAttributeMaxDynamicSharedMemorySize, SMEM0);
    cudaFuncSetAttribute(mma_gemm<1>, cudaFuncAttributeMaxDynamicSharedMemorySize, SMEM1);
    cudaFuncSetAttribute(attn_mma, cudaFuncAttributeMaxDynamicSharedMemorySize, ATT_SMEM);

    const int n1 = QKVC * CC / 4, n2 = CC * CC / 4;
    cvt_w2<<<(n1 + n2 + 255) / 256, 256>>>(proj_w, d_pwh, n1,
                                           out_w, d_owh, d_owl, n2);
    gn_kernel<<<BB * NG, 256>>>(x, gn_w, gn_b);

    mma_gemm<0><<<dim3(QKVC / 64, BB * SS / 128), 256, SMEM0>>>(
        d_hh, d_pwh, nullptr, proj_b, nullptr, nullptr, d_qh, QKVC);

    attn_mma<<<dim3(SS / 128, BB * NH), 256, ATT_SMEM>>>();

    mma_gemm<1><<<dim3(CC / 64, BB * SS / 128), 256, SMEM1>>>(
        d_aoh, d_owh, d_owl, out_b, x, out, nullptr, CC);
}

// round 16
// speedup vs baseline: 6.3950x; 1.0119x over previous
#include <cuda_runtime.h>
#include <cuda_fp16.h>
#include <cstdint>

// Shapes: B=16, C=512, H=W=32 -> S=1024, 32 groups (16 ch/group), 8 heads, D=64.
#define BB 16
#define CC 512
#define SS 1024
#define NG 32
#define CPG 16
#define NH 8
#define DK 64
#define QKVC 1536

// fp16 storage (hi/lo split only where error does NOT dilute)
static __device__ __half g_h_h[BB * SS * CC];        // gn out: single fp16
static __device__ __half g_qkv_h[BB * SS * QKVC];    // qkv: single fp16 (q pre-scaled)
static __device__ __half g_ao_h[BB * SS * CC];       // ao: single fp16
static __device__ __half g_pw_h[QKVC * CC];          // proj_w: single fp16
static __device__ __half g_ow_h[CC * CC];            // out_w: hi/lo
static __device__ __half g_ow_l[CC * CC];

#define SCL 0.18033688011112042f  // 0.125 * log2(e), folded into q

// ============================================================================
// helpers
// ============================================================================
__device__ __forceinline__ uint32_t smem_u32(const void* p) {
    uint32_t a;
    asm("{ .reg .u64 t; cvta.to.shared.u64 t, %1; cvt.u32.u64 %0, t; }"
        : "=r"(a) : "l"(p));
    return a;
}

__device__ __forceinline__ void ldm_x4(uint32_t* r, uint32_t addr) {
    asm volatile("ldmatrix.sync.aligned.m8n8.x4.shared.b16 {%0,%1,%2,%3}, [%4];"
                 : "=r"(r[0]), "=r"(r[1]), "=r"(r[2]), "=r"(r[3]) : "r"(addr));
}
__device__ __forceinline__ void ldm_x4_t(uint32_t* r, uint32_t addr) {
    asm volatile("ldmatrix.sync.aligned.m8n8.x4.trans.shared.b16 {%0,%1,%2,%3}, [%4];"
                 : "=r"(r[0]), "=r"(r[1]), "=r"(r[2]), "=r"(r[3]) : "r"(addr));
}

__device__ __forceinline__ void mma_f16(float* c, const uint32_t* a, const uint32_t* b) {
    asm volatile(
        "mma.sync.aligned.m16n8k16.row.col.f32.f16.f16.f32 "
        "{%0,%1,%2,%3}, {%4,%5,%6,%7}, {%8,%9}, {%0,%1,%2,%3};"
        : "+f"(c[0]), "+f"(c[1]), "+f"(c[2]), "+f"(c[3])
        : "r"(a[0]), "r"(a[1]), "r"(a[2]), "r"(a[3]), "r"(b[0]), "r"(b[1]));
}

#define CP_A16(dst, src) \
    asm volatile("cp.async.cg.shared.global [%0], [%1], 16;" :: "r"(dst), "l"(src))
#define CP_COMMIT() asm volatile("cp.async.commit_group;" ::: "memory")
#define CP_WAIT0()  asm volatile("cp.async.wait_group 0;" ::: "memory")
#define CP_WAIT1()  asm volatile("cp.async.wait_group 1;" ::: "memory")

// fp32 pair -> packed fp16 hi + packed fp16 lo
__device__ __forceinline__ void split2(float a, float b, uint32_t& h, uint32_t& l) {
    __half2 hp = __floats2half2_rn(a, b);
    float2 hf = __half22float2(hp);
    __half2 lp = __floats2half2_rn(a - hf.x, b - hf.y);
    h = *reinterpret_cast<uint32_t*>(&hp);
    l = *reinterpret_cast<uint32_t*>(&lp);
}

__device__ __forceinline__ uint32_t pack2(float a, float b) {
    __half2 hp = __floats2half2_rn(a, b);
    return *reinterpret_cast<uint32_t*>(&hp);
}

__device__ __forceinline__ uint32_t packh2(__half a, __half b) {
    __half2 hp = __halves2half2(a, b);
    return *reinterpret_cast<uint32_t*>(&hp);
}

// 2x exp2 in one MUFU op, result packed fp16x2 (mma-ready)
__device__ __forceinline__ uint32_t exp2_h2(float a, float b) {
    __half2 hv = __floats2half2_rn(a, b);
    uint32_t r;
    asm("ex2.approx.f16x2 %0, %1;" : "=r"(r) : "r"(*reinterpret_cast<uint32_t*>(&hv)));
    return r;
}

// ---------------------------------------------------------------------------
// Kernel 0: one-time weight conversion: proj_w -> single fp16; out_w -> hi/lo
// ---------------------------------------------------------------------------
__global__ __launch_bounds__(256) void cvt_w2(
    const float* __restrict__ w1, __half* __restrict__ h1, int n1,
    const float* __restrict__ w2, __half* __restrict__ h2,
    __half* __restrict__ l2, int n2) {
    int i = blockIdx.x * 256 + threadIdx.x;
    if (i < n1) {
        float4 v = reinterpret_cast<const float4*>(w1)[i];
        uint2 hv = make_uint2(pack2(v.x, v.y), pack2(v.z, v.w));
        reinterpret_cast<uint2*>(h1)[i] = hv;
    } else if (i < n1 + n2) {
        i -= n1;
        float4 v = reinterpret_cast<const float4*>(w2)[i];
        uint2 hv, lv;
        split2(v.x, v.y, hv.x, lv.x);
        split2(v.z, v.w, hv.y, lv.y);
        reinterpret_cast<uint2*>(h2)[i] = hv;
        reinterpret_cast<uint2*>(l2)[i] = lv;
    }
}

// ---------------------------------------------------------------------------
// Kernel 1: GroupNorm, smem-transposed pass 2 (coalesced loads + 16B stores)
// ---------------------------------------------------------------------------
__global__ __launch_bounds__(256) void gn_kernel(const float* __restrict__ x,
                                                 const float* __restrict__ w,
                                                 const float* __restrict__ bgn) {
    const int b = blockIdx.x >> 5;
    const int g = blockIdx.x & 31;
    const float* xp = x + (size_t)(b * CC + g * CPG) * SS;
    const int t = threadIdx.x;

    float sum = 0.f, sq = 0.f;
    for (int i = t; i < CPG * SS; i += 256) {
        float v = xp[i];
        sum += v;
        sq = fmaf(v, v, sq);
    }
    __shared__ float s1[256], s2[256];
    s1[t] = sum; s2[t] = sq;
    __syncthreads();
    for (int o = 128; o > 0; o >>= 1) {
        if (t < o) { s1[t] += s1[t + o]; s2[t] += s2[t + o]; }
        __syncthreads();
    }
    __shared__ float mean_s, inv_s;
    if (t == 0) {
        const float n_inv = 1.f / (CPG * SS);
        float mean = s1[0] * n_inv;
        float var = s2[0] * n_inv - mean * mean;
        mean_s = mean;
        inv_s = rsqrtf(var + 1e-5f);
    }
    __syncthreads();

    __shared__ float swc[16], sbc[16];
    if (t < 16) {
        int c = g * CPG + t;
        float wc = w[c] * inv_s;
        swc[t] = wc;
        sbc[t] = bgn[c] - mean_s * wc;
    }
    __shared__ __half tile[16][264];
    __syncthreads();

    const int s2i = t >> 1, hb = t & 1;
    for (int chunk = 0; chunk < 4; ++chunk) {
#pragma unroll
        for (int k = 0; k < 16; ++k) {
            float v = xp[k * SS + chunk * 256 + t];
            tile[k][t] = __float2half_rn(fmaf(v, swc[k], sbc[k]));
        }
        __syncthreads();
#pragma unroll
        for (int rep = 0; rep < 2; ++rep) {
            int s = s2i + rep * 128;
            __half v0 = tile[hb * 8 + 0][s], v1 = tile[hb * 8 + 1][s];
            __half v2 = tile[hb * 8 + 2][s], v3 = tile[hb * 8 + 3][s];
            __half v4 = tile[hb * 8 + 4][s], v5 = tile[hb * 8 + 5][s];
            __half v6 = tile[hb * 8 + 6][s], v7 = tile[hb * 8 + 7][s];
            uint4 u;
            u.x = packh2(v0, v1); u.y = packh2(v2, v3);
            u.z = packh2(v4, v5); u.w = packh2(v6, v7);
            size_t off = (size_t)(b * SS + chunk * 256 + s) * CC + g * CPG + hb * 8;
            *reinterpret_cast<uint4*>(g_h_h + off) = u;
        }
        __syncthreads();
    }
}

// ---------------------------------------------------------------------------
// Kernel 2: mma GEMM, 128x64 CTA tile, 3-stage cp.async ring, 3 CTAs/SM.
// MODE 0 (qkv): pure fp16, 1 pass; epi +bias (+SCL on q), fp16 out.
// MODE 1 (out): A single x W hi/lo, 2 passes; epi +bias+residual, fp32 CM.
// ---------------------------------------------------------------------------
#define GP 40                 // fp16 smem pitch (80B rows)

template <int MODE>
__global__ __launch_bounds__(256, 3) void mma_gemm(
    const __half* __restrict__ Ah,
    const __half* __restrict__ Wh, const __half* __restrict__ Wl,
    const float* __restrict__ bias, const float* __restrict__ xres,
    float* __restrict__ outf, __half* __restrict__ oh, int Ntot) {
    constexpr int GBUF = (MODE == 0) ? 15360 : 20480;
    extern __shared__ __align__(16) char sm[];
    const uint32_t sb = smem_u32(sm);
    const int t = threadIdx.x, w = t >> 5, L = t & 31;
    const int n0 = blockIdx.x * 64;
    const int m0 = blockIdx.y * 128;
    const int wm = w >> 1, wn = w & 1;

    const int arow = L & 15, aseg = L >> 4;
    const int brow = ((L >> 4) << 3) + (L & 7), bcol = ((L >> 3) & 1) * 8;
    const int crow = L >> 2, ccol = (L & 3) * 2;

    float acc[2][4][4] = {};

    auto load_chunk = [&](int kc, int st) {
        const int k0 = kc * 32;
        const uint32_t base = sb + st * GBUF;
#pragma unroll
        for (int rep = 0; rep < 2; ++rep) {
            int c = t + rep * 256;
            int row = c >> 2, ch = c & 3;
            size_t so = (size_t)(m0 + row) * CC + k0 + ch * 8;
            CP_A16(base + row * 80 + ch * 16, Ah + so);
        }
        {
            int row = t >> 2, ch = t & 3;
            size_t so = (size_t)(n0 + row) * CC + k0 + ch * 8;
            CP_A16(base + 10240 + row * 80 + ch * 16, Wh + so);
            if (MODE == 1)
                CP_A16(base + 15360 + row * 80 + ch * 16, Wl + so);
        }
    };

    auto compute = [&](int st) {
        const uint32_t base = sb + st * GBUF;
#pragma unroll
        for (int ks = 0; ks < 2; ++ks) {
            uint32_t ah[2][4], bh[2][4], bl[2][4];
#pragma unroll
            for (int mt = 0; mt < 2; ++mt) {
                uint32_t off = (uint32_t)(((wm * 32 + mt * 16 + arow) * GP +
                                           ks * 16 + aseg * 8) * 2);
                ldm_x4(ah[mt], base + off);
            }
#pragma unroll
            for (int nt = 0; nt < 2; ++nt) {
                uint32_t off = (uint32_t)(((wn * 32 + nt * 16 + brow) * GP +
                                           ks * 16 + bcol) * 2);
                ldm_x4(bh[nt], base + 10240 + off);
                if (MODE == 1) ldm_x4(bl[nt], base + 15360 + off);
            }
#pragma unroll
            for (int mt = 0; mt < 2; ++mt)
#pragma unroll
                for (int n8 = 0; n8 < 4; ++n8)
                    mma_f16(acc[mt][n8], ah[mt], &bh[n8 >> 1][(n8 & 1) * 2]);
            if (MODE == 1) {
#pragma unroll
                for (int mt = 0; mt < 2; ++mt)
#pragma unroll
                    for (int n8 = 0; n8 < 4; ++n8)
                        mma_f16(acc[mt][n8], ah[mt], &bl[n8 >> 1][(n8 & 1) * 2]);
            }
        }
    };

    load_chunk(0, 0); CP_COMMIT();
    load_chunk(1, 1); CP_COMMIT();
    int cs = 0, ls = 2;
    for (int kc = 0; kc < 16; ++kc) {
        if (kc < 15) CP_WAIT1(); else CP_WAIT0();
        __syncthreads();
        compute(cs);
        if (kc < 14) { load_chunk(kc + 2, ls); CP_COMMIT(); }
        cs = (cs == 2) ? 0 : cs + 1;
        ls = (ls == 2) ? 0 : ls + 1;
    }
    __syncthreads();   // buffers free before stage aliasing

    float* stage = reinterpret_cast<float*>(sm);
    const int PITCH = (MODE == 0) ? 68 : 65;
#pragma unroll
    for (int mt = 0; mt < 2; ++mt)
#pragma unroll
        for (int n8 = 0; n8 < 4; ++n8) {
            int r = wm * 32 + mt * 16 + crow;
            int c = wn * 32 + n8 * 8 + ccol;
            stage[r * PITCH + c]           = acc[mt][n8][0];
            stage[r * PITCH + c + 1]       = acc[mt][n8][1];
            stage[(r + 8) * PITCH + c]     = acc[mt][n8][2];
            stage[(r + 8) * PITCH + c + 1] = acc[mt][n8][3];
        }
    __syncthreads();

    if (MODE == 0) {
        // q tiles (n0 % 192 == 0) get the folded softmax scale
        const float scale = (n0 % 192 == 0) ? SCL : 1.0f;
#pragma unroll
        for (int i = 0; i < 8; ++i) {
            int f = t + 256 * i;
            int row = f >> 4, c4 = f & 15;
            float4 v = *(const float4*)&stage[row * 68 + c4 * 4];
            float4 bb = *(const float4*)&bias[n0 + c4 * 4];
            uint2 hv = make_uint2(pack2((v.x + bb.x) * scale, (v.y + bb.y) * scale),
                                  pack2((v.z + bb.z) * scale, (v.w + bb.w) * scale));
            size_t go = (size_t)(m0 + row) * Ntot + n0 + c4 * 4;
            *reinterpret_cast<uint2*>(oh + go) = hv;
        }
    } else {
        const int b = m0 >> 10;
        const int s0 = m0 & 1023;
#pragma unroll
        for (int i = 0; i < 32; ++i) {
            int idx = i * 256 + t;
            int c = idx >> 7, srow = idx & 127;
            size_t gi = (size_t)(b * CC + n0 + c) * SS + s0 + srow;
            outf[gi] = stage[srow * 65 + c] + bias[n0 + c] + xres[gi];
        }
    }
}

// ---------------------------------------------------------------------------
// Kernel 3: flash attention, 128 queries/CTA, warp owns 16 full rows.
// SINGLE sync + SINGLE wait per j-tile: K(j)+V(j) committed as one group;
// prefetch (j+1) issued right after the top sync (buffer freed by that sync),
// overlapping the whole tile's compute.  Q frags hoisted; ex2.f16x2 softmax.
// ---------------------------------------------------------------------------
#define AP 72
#define A_Q  0                    // Q: 128 x 144B
#define A_KB 18432                // K stage i at A_KB + i*9216
#define A_VB 36864                // V stage i at A_VB + i*9216
#define ATT_SMEM 55296

__global__ __launch_bounds__(256, 2) void attn_mma() {
    extern __shared__ __align__(16) char sm[];
    const uint32_t sb = smem_u32(sm);

    const int i0 = blockIdx.x * 128;
    const int bh = blockIdx.y;
    const int b = bh >> 3, h = bh & 7;
    const int t = threadIdx.x, w = t >> 5, L = t & 31;

    const int arow = L & 15, aseg = L >> 4;
    const int brow = ((L >> 4) << 3) + (L & 7), bcol = ((L >> 3) & 1) * 8;
    const int crow = L >> 2, ccol = (L & 3) * 2;

    const __half* qk = g_qkv_h + (size_t)b * SS * QKVC + h * 192;

    // K(j)+V(j) as ONE group into buffer slot st
    auto cp_kv2 = [&](int j, int st) {
        const __half* srck = qk + (size_t)j * 64 * QKVC + 64;
        const __half* srcv = srck + 64;
        const uint32_t kb = sb + A_KB + st * 9216;
        const uint32_t vb = sb + A_VB + st * 9216;
#pragma unroll
        for (int rep = 0; rep < 2; ++rep) {
            int c = t + rep * 256;
            int row = c >> 3, ch = c & 7;
            size_t so = (size_t)row * QKVC + ch * 8;
            CP_A16(kb + row * 144 + ch * 16, srck + so);
            CP_A16(vb + row * 144 + ch * 16, srcv + so);
        }
    };

    // prologue: group 0 = Q + K(0) + V(0)
    {
        const __half* sq = qk + (size_t)i0 * QKVC;
#pragma unroll
        for (int rep = 0; rep < 4; ++rep) {
            int c = t + rep * 256;
            int row = c >> 3, ch = c & 7;
            CP_A16(sb + A_Q + row * 144 + ch * 16, sq + (size_t)row * QKVC + ch * 8);
        }
    }
    cp_kv2(0, 0);
    CP_COMMIT();

    CP_WAIT0();                   // Q + K(0) + V(0) landed
    __syncthreads();

    // hoist Q fragments (loop-invariant)
    uint32_t qf[4][4];
#pragma unroll
    for (int ks = 0; ks < 4; ++ks) {
        uint32_t aoff = (uint32_t)(((w * 16 + arow) * AP + ks * 16 + aseg * 8) * 2);
        ldm_x4(qf[ks], sb + A_Q + aoff);
    }

    float m0 = -1e30f, m1 = -1e30f, l0 = 0.f, l1 = 0.f;
    float o[8][4] = {};

    for (int j = 0; j < 16; ++j) {
        const uint32_t kbase = sb + A_KB + (j & 1) * 9216;
        const uint32_t vbase = sb + A_VB + (j & 1) * 9216;

        if (j > 0) {              // group j complete; buffers of tile j-1 free
            CP_WAIT0();
            __syncthreads();
        }
        if (j < 15) {             // prefetch (K,V)(j+1); overlaps whole tile
            cp_kv2(j + 1, (j + 1) & 1);
            CP_COMMIT();
        }

        // ---- S = Q K^T : 1 pass (Q frags in registers) ----
        float sc[8][4] = {};
#pragma unroll
        for (int ks = 0; ks < 4; ++ks) {
            uint32_t bh_[4][4];
#pragma unroll
            for (int nt = 0; nt < 4; ++nt) {
                uint32_t boff = (uint32_t)(((nt * 16 + brow) * AP +
                                            ks * 16 + bcol) * 2);
                ldm_x4(bh_[nt], kbase + boff);
            }
#pragma unroll
            for (int n8 = 0; n8 < 8; ++n8)
                mma_f16(sc[n8], qf[ks], &bh_[n8 >> 1][(n8 & 1) * 2]);
        }

        // ---- register softmax (base-2 domain) ----
        float mx0 = -1e30f, mx1 = -1e30f;
#pragma unroll
        for (int n8 = 0; n8 < 8; ++n8) {
            mx0 = fmaxf(mx0, fmaxf(sc[n8][0], sc[n8][1]));
            mx1 = fmaxf(mx1, fmaxf(sc[n8][2], sc[n8][3]));
        }
        mx0 = fmaxf(mx0, __shfl_xor_sync(0xffffffff, mx0, 1));
        mx0 = fmaxf(mx0, __shfl_xor_sync(0xffffffff, mx0, 2));
        mx1 = fmaxf(mx1, __shfl_xor_sync(0xffffffff, mx1, 1));
        mx1 = fmaxf(mx1, __shfl_xor_sync(0xffffffff, mx1, 2));

        float mn0 = fmaxf(m0, mx0), mn1 = fmaxf(m1, mx1);
        float a0 = exp2f(m0 - mn0), a1 = exp2f(m1 - mn1);
        m0 = mn0; m1 = mn1;

        // exp via ex2.approx.f16x2; l-sum from the SAME fp16-rounded values.
        uint32_t ph[4][4];
        float s0 = 0.f, s1 = 0.f;
#pragma unroll
        for (int g = 0; g < 4; ++g)
#pragma unroll
            for (int hf = 0; hf < 2; ++hf) {
                int tile = g * 2 + hf;
                uint32_t p0 = exp2_h2(sc[tile][0] - mn0, sc[tile][1] - mn0);
                uint32_t p1 = exp2_h2(sc[tile][2] - mn1, sc[tile][3] - mn1);
                ph[g][hf * 2]     = p0;
                ph[g][hf * 2 + 1] = p1;
                float2 f0 = __half22float2(*reinterpret_cast<__half2*>(&p0));
                float2 f1 = __half22float2(*reinterpret_cast<__half2*>(&p1));
                s0 += f0.x + f0.y;
                s1 += f1.x + f1.y;
            }
        s0 += __shfl_xor_sync(0xffffffff, s0, 1);
        s0 += __shfl_xor_sync(0xffffffff, s0, 2);
        s1 += __shfl_xor_sync(0xffffffff, s1, 1);
        s1 += __shfl_xor_sync(0xffffffff, s1, 2);
        l0 = fmaf(l0, a0, s0);
        l1 = fmaf(l1, a1, s1);

#pragma unroll
        for (int n8 = 0; n8 < 8; ++n8) {
            o[n8][0] *= a0; o[n8][1] *= a0;
            o[n8][2] *= a1; o[n8][3] *= a1;
        }

        // ---- O += P V : 1 pass (V already resident; no wait needed) ----
#pragma unroll
        for (int g = 0; g < 4; ++g) {
            int krow = g * 16 + ((L >> 3) & 1) * 8 + (L & 7);
            uint32_t vh[4][4];
#pragma unroll
            for (int nt = 0; nt < 4; ++nt) {
                int dcol = nt * 16 + (L >> 4) * 8;
                ldm_x4_t(vh[nt], vbase + (uint32_t)((krow * AP + dcol) * 2));
            }
#pragma unroll
            for (int n8 = 0; n8 < 8; ++n8)
                mma_f16(o[n8], ph[g], &vh[n8 >> 1][(n8 & 1) * 2]);
        }
    }

    // ---- normalize + store single fp16 ----
    float inv0 = 1.f / l0, inv1 = 1.f / l1;
#pragma unroll
    for (int n8 = 0; n8 < 8; ++n8) {
        int d = n8 * 8 + ccol;
        uint32_t h0 = pack2(o[n8][0] * inv0, o[n8][1] * inv0);
        uint32_t h1 = pack2(o[n8][2] * inv1, o[n8][3] * inv1);
        size_t g0 = (size_t)(b * SS + i0 + w * 16 + crow) * CC + h * DK + d;
        size_t g1 = g0 + (size_t)8 * CC;
        *reinterpret_cast<uint32_t*>(g_ao_h + g0) = h0;
        *reinterpret_cast<uint32_t*>(g_ao_h + g1) = h1;
    }
}

// ---------------------------------------------------------------------------
extern "C" void kernel_launch(void* const* d_in, const int* in_sizes, int n_in,
                              void* d_out, int out_size) {
    const float* x = (const float*)d_in[0];
    const float* gn_w = (const float*)d_in[1];
    const float* gn_b = (const float*)d_in[2];
    const float* proj_w = (const float*)d_in[3];
    const float* proj_b = (const float*)d_in[4];
    const float* out_w = (const float*)d_in[5];
    const float* out_b = (const float*)d_in[6];
    float* out = (float*)d_out;

    __half *d_hh, *d_qh, *d_aoh, *d_pwh, *d_owh, *d_owl;
    cudaGetSymbolAddress((void**)&d_hh, g_h_h);
    cudaGetSymbolAddress((void**)&d_qh, g_qkv_h);
    cudaGetSymbolAddress((void**)&d_aoh, g_ao_h);
    cudaGetSymbolAddress((void**)&d_pwh, g_pw_h);
    cudaGetSymbolAddress((void**)&d_owh, g_ow_h);
    cudaGetSymbolAddress((void**)&d_owl, g_ow_l);

    const int SMEM0 = 3 * 15360;
    const int SMEM1 = 3 * 20480;
    cudaFuncSetAttribute(mma_gemm<0>, cudaFuncAttributeMaxDynamicSharedMemorySize, SMEM0);
    cudaFuncSetAttribute(mma_gemm<1>, cudaFuncAttributeMaxDynamicSharedMemorySize, SMEM1);
    cudaFuncSetAttribute(attn_mma, cudaFuncAttributeMaxDynamicSharedMemorySize, ATT_SMEM);

    const int n1 = QKVC * CC / 4, n2 = CC * CC / 4;
    cvt_w2<<<(n1 + n2 + 255) / 256, 256>>>(proj_w, d_pwh, n1,
                                           out_w, d_owh, d_owl, n2);
    gn_kernel<<<BB * NG, 256>>>(x, gn_w, gn_b);

    mma_gemm<0><<<dim3(QKVC / 64, BB * SS / 128), 256, SMEM0>>>(
        d_hh, d_pwh, nullptr, proj_b, nullptr, nullptr, d_qh, QKVC);

    attn_mma<<<dim3(SS / 128, BB * NH), 256, ATT_SMEM>>>();

    mma_gemm<1><<<dim3(CC / 64, BB * SS / 128), 256, SMEM1>>>(
        d_aoh, d_owh, d_owl, out_b, x, out, nullptr, CC);
}

// round 17
// speedup vs baseline: 6.9942x; 1.0937x over previous
#include <cuda_runtime.h>
#include <cuda_fp16.h>
#include <cstdint>

// Shapes: B=16, C=512, H=W=32 -> S=1024, 32 groups (16 ch/group), 8 heads, D=64.
#define BB 16
#define CC 512
#define SS 1024
#define NG 32
#define CPG 16
#define NH 8
#define DK 64
#define QKVC 1536

// fp16 storage (all single-plane now; dilution model validated R10-R16)
static __device__ __half g_h_h[BB * SS * CC];        // gn out
static __device__ __half g_qkv_h[BB * SS * QKVC];    // qkv (q pre-scaled)
static __device__ __half g_ao_h[BB * SS * CC];       // attention out
static __device__ __half g_pw_h[QKVC * CC];          // proj_w
static __device__ __half g_ow_h[CC * CC];            // out_w

#define SCL 0.18033688011112042f  // 0.125 * log2(e), folded into q

// ============================================================================
// helpers
// ============================================================================
__device__ __forceinline__ uint32_t smem_u32(const void* p) {
    uint32_t a;
    asm("{ .reg .u64 t; cvta.to.shared.u64 t, %1; cvt.u32.u64 %0, t; }"
        : "=r"(a) : "l"(p));
    return a;
}

__device__ __forceinline__ void ldm_x4(uint32_t* r, uint32_t addr) {
    asm volatile("ldmatrix.sync.aligned.m8n8.x4.shared.b16 {%0,%1,%2,%3}, [%4];"
                 : "=r"(r[0]), "=r"(r[1]), "=r"(r[2]), "=r"(r[3]) : "r"(addr));
}
__device__ __forceinline__ void ldm_x4_t(uint32_t* r, uint32_t addr) {
    asm volatile("ldmatrix.sync.aligned.m8n8.x4.trans.shared.b16 {%0,%1,%2,%3}, [%4];"
                 : "=r"(r[0]), "=r"(r[1]), "=r"(r[2]), "=r"(r[3]) : "r"(addr));
}

// fp32-accumulator mma
__device__ __forceinline__ void mma_f16(float* c, const uint32_t* a, const uint32_t* b) {
    asm volatile(
        "mma.sync.aligned.m16n8k16.row.col.f32.f16.f16.f32 "
        "{%0,%1,%2,%3}, {%4,%5,%6,%7}, {%8,%9}, {%0,%1,%2,%3};"
        : "+f"(c[0]), "+f"(c[1]), "+f"(c[2]), "+f"(c[3])
        : "r"(a[0]), "r"(a[1]), "r"(a[2]), "r"(a[3]), "r"(b[0]), "r"(b[1]));
}

// fp16-accumulator mma (QK^T logits)
__device__ __forceinline__ void mma_f16h(uint32_t* c, const uint32_t* a,
                                         const uint32_t* b) {
    asm volatile(
        "mma.sync.aligned.m16n8k16.row.col.f16.f16.f16.f16 "
        "{%0,%1}, {%2,%3,%4,%5}, {%6,%7}, {%0,%1};"
        : "+r"(c[0]), "+r"(c[1])
        : "r"(a[0]), "r"(a[1]), "r"(a[2]), "r"(a[3]), "r"(b[0]), "r"(b[1]));
}

#define CP_A16(dst, src) \
    asm volatile("cp.async.cg.shared.global [%0], [%1], 16;" :: "r"(dst), "l"(src))
#define CP_COMMIT() asm volatile("cp.async.commit_group;" ::: "memory")
#define CP_WAIT0()  asm volatile("cp.async.wait_group 0;" ::: "memory")
#define CP_WAIT1()  asm volatile("cp.async.wait_group 1;" ::: "memory")

__device__ __forceinline__ uint32_t pack2(float a, float b) {
    __half2 hp = __floats2half2_rn(a, b);
    return *reinterpret_cast<uint32_t*>(&hp);
}

__device__ __forceinline__ uint32_t packh2(__half a, __half b) {
    __half2 hp = __halves2half2(a, b);
    return *reinterpret_cast<uint32_t*>(&hp);
}

// packed fp16x2 exp2 (one MUFU op)
__device__ __forceinline__ uint32_t ex2h2(uint32_t x) {
    uint32_t r;
    asm("ex2.approx.f16x2 %0, %1;" : "=r"(r) : "r"(x));
    return r;
}

// ---------------------------------------------------------------------------
// Kernel 0: one-time weight conversion (both weights single fp16)
// ---------------------------------------------------------------------------
__global__ __launch_bounds__(256) void cvt_w2(
    const float* __restrict__ w1, __half* __restrict__ h1, int n1,
    const float* __restrict__ w2, __half* __restrict__ h2, int n2) {
    int i = blockIdx.x * 256 + threadIdx.x;
    const float* w; __half* hi;
    if (i < n1) { w = w1; hi = h1; }
    else if (i < n1 + n2) { i -= n1; w = w2; hi = h2; }
    else return;
    float4 v = reinterpret_cast<const float4*>(w)[i];
    reinterpret_cast<uint2*>(hi)[i] =
        make_uint2(pack2(v.x, v.y), pack2(v.z, v.w));
}

// ---------------------------------------------------------------------------
// Kernel 1: GroupNorm, smem-transposed pass 2 (coalesced loads + 16B stores)
// ---------------------------------------------------------------------------
__global__ __launch_bounds__(256) void gn_kernel(const float* __restrict__ x,
                                                 const float* __restrict__ w,
                                                 const float* __restrict__ bgn) {
    const int b = blockIdx.x >> 5;
    const int g = blockIdx.x & 31;
    const float* xp = x + (size_t)(b * CC + g * CPG) * SS;
    const int t = threadIdx.x;

    float sum = 0.f, sq = 0.f;
    for (int i = t; i < CPG * SS; i += 256) {
        float v = xp[i];
        sum += v;
        sq = fmaf(v, v, sq);
    }
    __shared__ float s1[256], s2[256];
    s1[t] = sum; s2[t] = sq;
    __syncthreads();
    for (int o = 128; o > 0; o >>= 1) {
        if (t < o) { s1[t] += s1[t + o]; s2[t] += s2[t + o]; }
        __syncthreads();
    }
    __shared__ float mean_s, inv_s;
    if (t == 0) {
        const float n_inv = 1.f / (CPG * SS);
        float mean = s1[0] * n_inv;
        float var = s2[0] * n_inv - mean * mean;
        mean_s = mean;
        inv_s = rsqrtf(var + 1e-5f);
    }
    __syncthreads();

    __shared__ float swc[16], sbc[16];
    if (t < 16) {
        int c = g * CPG + t;
        float wc = w[c] * inv_s;
        swc[t] = wc;
        sbc[t] = bgn[c] - mean_s * wc;
    }
    __shared__ __half tile[16][264];
    __syncthreads();

    const int s2i = t >> 1, hb = t & 1;
    for (int chunk = 0; chunk < 4; ++chunk) {
#pragma unroll
        for (int k = 0; k < 16; ++k) {
            float v = xp[k * SS + chunk * 256 + t];
            tile[k][t] = __float2half_rn(fmaf(v, swc[k], sbc[k]));
        }
        __syncthreads();
#pragma unroll
        for (int rep = 0; rep < 2; ++rep) {
            int s = s2i + rep * 128;
            __half v0 = tile[hb * 8 + 0][s], v1 = tile[hb * 8 + 1][s];
            __half v2 = tile[hb * 8 + 2][s], v3 = tile[hb * 8 + 3][s];
            __half v4 = tile[hb * 8 + 4][s], v5 = tile[hb * 8 + 5][s];
            __half v6 = tile[hb * 8 + 6][s], v7 = tile[hb * 8 + 7][s];
            uint4 u;
            u.x = packh2(v0, v1); u.y = packh2(v2, v3);
            u.z = packh2(v4, v5); u.w = packh2(v6, v7);
            size_t off = (size_t)(b * SS + chunk * 256 + s) * CC + g * CPG + hb * 8;
            *reinterpret_cast<uint4*>(g_h_h + off) = u;
        }
        __syncthreads();
    }
}

// ---------------------------------------------------------------------------
// Kernel 2: pure-fp16 1-pass mma GEMM, 128x64 CTA tile, 3-stage ring, 3 CTA/SM.
// MODE 0 (qkv): epi +bias (+SCL on q tiles), fp16 out (row-major).
// MODE 1 (out): epi +bias+residual, fp32 channel-major out.
// ---------------------------------------------------------------------------
#define GP 40                 // fp16 smem pitch (80B rows)
#define GBUF 15360            // A 10240 | W 5120
#define GEMM_SMEM (3 * GBUF)

template <int MODE>
__global__ __launch_bounds__(256, 3) void mma_gemm(
    const __half* __restrict__ Ah, const __half* __restrict__ Wh,
    const float* __restrict__ bias, const float* __restrict__ xres,
    float* __restrict__ outf, __half* __restrict__ oh, int Ntot) {
    extern __shared__ __align__(16) char sm[];
    const uint32_t sb = smem_u32(sm);
    const int t = threadIdx.x, w = t >> 5, L = t & 31;
    const int n0 = blockIdx.x * 64;
    const int m0 = blockIdx.y * 128;
    const int wm = w >> 1, wn = w & 1;

    const int arow = L & 15, aseg = L >> 4;
    const int brow = ((L >> 4) << 3) + (L & 7), bcol = ((L >> 3) & 1) * 8;
    const int crow = L >> 2, ccol = (L & 3) * 2;

    float acc[2][4][4] = {};

    auto load_chunk = [&](int kc, int st) {
        const int k0 = kc * 32;
        const uint32_t base = sb + st * GBUF;
#pragma unroll
        for (int rep = 0; rep < 2; ++rep) {
            int c = t + rep * 256;
            int row = c >> 2, ch = c & 3;
            size_t so = (size_t)(m0 + row) * CC + k0 + ch * 8;
            CP_A16(base + row * 80 + ch * 16, Ah + so);
        }
        {
            int row = t >> 2, ch = t & 3;
            size_t so = (size_t)(n0 + row) * CC + k0 + ch * 8;
            CP_A16(base + 10240 + row * 80 + ch * 16, Wh + so);
        }
    };

    auto compute = [&](int st) {
        const uint32_t base = sb + st * GBUF;
#pragma unroll
        for (int ks = 0; ks < 2; ++ks) {
            uint32_t ah[2][4], bh[2][4];
#pragma unroll
            for (int mt = 0; mt < 2; ++mt) {
                uint32_t off = (uint32_t)(((wm * 32 + mt * 16 + arow) * GP +
                                           ks * 16 + aseg * 8) * 2);
                ldm_x4(ah[mt], base + off);
            }
#pragma unroll
            for (int nt = 0; nt < 2; ++nt) {
                uint32_t off = (uint32_t)(((wn * 32 + nt * 16 + brow) * GP +
                                           ks * 16 + bcol) * 2);
                ldm_x4(bh[nt], base + 10240 + off);
            }
#pragma unroll
            for (int mt = 0; mt < 2; ++mt)
#pragma unroll
                for (int n8 = 0; n8 < 4; ++n8)
                    mma_f16(acc[mt][n8], ah[mt], &bh[n8 >> 1][(n8 & 1) * 2]);
        }
    };

    load_chunk(0, 0); CP_COMMIT();
    load_chunk(1, 1); CP_COMMIT();
    int cs = 0, ls = 2;
    for (int kc = 0; kc < 16; ++kc) {
        if (kc < 15) CP_WAIT1(); else CP_WAIT0();
        __syncthreads();
        compute(cs);
        if (kc < 14) { load_chunk(kc + 2, ls); CP_COMMIT(); }
        cs = (cs == 2) ? 0 : cs + 1;
        ls = (ls == 2) ? 0 : ls + 1;
    }
    __syncthreads();   // buffers free before stage aliasing

    float* stage = reinterpret_cast<float*>(sm);
    const int PITCH = (MODE == 0) ? 68 : 65;
#pragma unroll
    for (int mt = 0; mt < 2; ++mt)
#pragma unroll
        for (int n8 = 0; n8 < 4; ++n8) {
            int r = wm * 32 + mt * 16 + crow;
            int c = wn * 32 + n8 * 8 + ccol;
            stage[r * PITCH + c]           = acc[mt][n8][0];
            stage[r * PITCH + c + 1]       = acc[mt][n8][1];
            stage[(r + 8) * PITCH + c]     = acc[mt][n8][2];
            stage[(r + 8) * PITCH + c + 1] = acc[mt][n8][3];
        }
    __syncthreads();

    if (MODE == 0) {
        // q tiles (n0 % 192 == 0) get the folded softmax scale
        const float scale = (n0 % 192 == 0) ? SCL : 1.0f;
#pragma unroll
        for (int i = 0; i < 8; ++i) {
            int f = t + 256 * i;
            int row = f >> 4, c4 = f & 15;
            float4 v = *(const float4*)&stage[row * 68 + c4 * 4];
            float4 bb = *(const float4*)&bias[n0 + c4 * 4];
            uint2 hv = make_uint2(pack2((v.x + bb.x) * scale, (v.y + bb.y) * scale),
                                  pack2((v.z + bb.z) * scale, (v.w + bb.w) * scale));
            size_t go = (size_t)(m0 + row) * Ntot + n0 + c4 * 4;
            *reinterpret_cast<uint2*>(oh + go) = hv;
        }
    } else {
        const int b = m0 >> 10;
        const int s0 = m0 & 1023;
#pragma unroll
        for (int i = 0; i < 32; ++i) {
            int idx = i * 256 + t;
            int c = idx >> 7, srow = idx & 127;
            size_t gi = (size_t)(b * CC + n0 + c) * SS + s0 + srow;
            outf[gi] = stage[srow * 65 + c] + bias[n0 + c] + xres[gi];
        }
    }
}

// ---------------------------------------------------------------------------
// Kernel 3: flash attention, 128 queries/CTA, warp owns 16 full rows.
// QK^T with fp16 accumulators (logits land as packed half2 in P-fragment
// layout); softmax = hmax2 tree + hsub2 + ex2.f16x2.  Row-sum l computed by
// an extra ones-column mma (fp32 acc, rescaled like O).  Single sync/wait
// per tile; K+V one cp.async group; Q frags hoisted.
// ---------------------------------------------------------------------------
#define AP 72
#define A_Q  0                    // Q: 128 x 144B
#define A_KB 18432                // K stage i at A_KB + i*9216
#define A_VB 36864                // V stage i at A_VB + i*9216
#define ATT_SMEM 55296

__global__ __launch_bounds__(256, 2) void attn_mma() {
    extern __shared__ __align__(16) char sm[];
    const uint32_t sb = smem_u32(sm);

    const int i0 = blockIdx.x * 128;
    const int bh = blockIdx.y;
    const int b = bh >> 3, h = bh & 7;
    const int t = threadIdx.x, w = t >> 5, L = t & 31;

    const int arow = L & 15, aseg = L >> 4;
    const int brow = ((L >> 4) << 3) + (L & 7), bcol = ((L >> 3) & 1) * 8;
    const int crow = L >> 2, ccol = (L & 3) * 2;

    const __half* qk = g_qkv_h + (size_t)b * SS * QKVC + h * 192;

    // K(j)+V(j) as ONE group into buffer slot st
    auto cp_kv2 = [&](int j, int st) {
        const __half* srck = qk + (size_t)j * 64 * QKVC + 64;
        const __half* srcv = srck + 64;
        const uint32_t kb = sb + A_KB + st * 9216;
        const uint32_t vb = sb + A_VB + st * 9216;
#pragma unroll
        for (int rep = 0; rep < 2; ++rep) {
            int c = t + rep * 256;
            int row = c >> 3, ch = c & 7;
            size_t so = (size_t)row * QKVC + ch * 8;
            CP_A16(kb + row * 144 + ch * 16, srck + so);
            CP_A16(vb + row * 144 + ch * 16, srcv + so);
        }
    };

    // prologue: group 0 = Q + K(0) + V(0)
    {
        const __half* sq = qk + (size_t)i0 * QKVC;
#pragma unroll
        for (int rep = 0; rep < 4; ++rep) {
            int c = t + rep * 256;
            int row = c >> 3, ch = c & 7;
            CP_A16(sb + A_Q + row * 144 + ch * 16, sq + (size_t)row * QKVC + ch * 8);
        }
    }
    cp_kv2(0, 0);
    CP_COMMIT();

    CP_WAIT0();
    __syncthreads();

    // hoist Q fragments (loop-invariant)
    uint32_t qf[4][4];
#pragma unroll
    for (int ks = 0; ks < 4; ++ks) {
        uint32_t aoff = (uint32_t)(((w * 16 + arow) * AP + ks * 16 + aseg * 8) * 2);
        ldm_x4(qf[ks], sb + A_Q + aoff);
    }

    const uint32_t ONES[2] = {0x3C003C00u, 0x3C003C00u};  // fp16 1.0 x4
    float m0 = -1e30f, m1 = -1e30f;
    float lacc[4] = {};           // l via ones-mma: [0]=row crow, [2]=row crow+8
    float o[8][4] = {};

    for (int j = 0; j < 16; ++j) {
        const uint32_t kbase = sb + A_KB + (j & 1) * 9216;
        const uint32_t vbase = sb + A_VB + (j & 1) * 9216;

        if (j > 0) {
            CP_WAIT0();
            __syncthreads();
        }
        if (j < 15) {             // prefetch (K,V)(j+1); overlaps whole tile
            cp_kv2(j + 1, (j + 1) & 1);
            CP_COMMIT();
        }

        // ---- S = Q K^T : fp16 accumulators ----
        uint32_t sc[8][2] = {};
#pragma unroll
        for (int ks = 0; ks < 4; ++ks) {
            uint32_t bh_[4][4];
#pragma unroll
            for (int nt = 0; nt < 4; ++nt) {
                uint32_t boff = (uint32_t)(((nt * 16 + brow) * AP +
                                            ks * 16 + bcol) * 2);
                ldm_x4(bh_[nt], kbase + boff);
            }
#pragma unroll
            for (int n8 = 0; n8 < 8; ++n8)
                mma_f16h(sc[n8], qf[ks], &bh_[n8 >> 1][(n8 & 1) * 2]);
        }

        // ---- softmax: hmax2 tree + hsub2 + ex2.f16x2 ----
        __half2 mh0 = *reinterpret_cast<__half2*>(&sc[0][0]);
        __half2 mh1 = *reinterpret_cast<__half2*>(&sc[0][1]);
#pragma unroll
        for (int n8 = 1; n8 < 8; ++n8) {
            mh0 = __hmax2(mh0, *reinterpret_cast<__half2*>(&sc[n8][0]));
            mh1 = __hmax2(mh1, *reinterpret_cast<__half2*>(&sc[n8][1]));
        }
        {
            uint32_t u0 = *reinterpret_cast<uint32_t*>(&mh0);
            uint32_t u1 = *reinterpret_cast<uint32_t*>(&mh1);
            u0 = __shfl_xor_sync(0xffffffff, u0, 1);
            u1 = __shfl_xor_sync(0xffffffff, u1, 1);
            mh0 = __hmax2(mh0, *reinterpret_cast<__half2*>(&u0));
            mh1 = __hmax2(mh1, *reinterpret_cast<__half2*>(&u1));
            u0 = *reinterpret_cast<uint32_t*>(&mh0);
            u1 = *reinterpret_cast<uint32_t*>(&mh1);
            u0 = __shfl_xor_sync(0xffffffff, u0, 2);
            u1 = __shfl_xor_sync(0xffffffff, u1, 2);
            mh0 = __hmax2(mh0, *reinterpret_cast<__half2*>(&u0));
            mh1 = __hmax2(mh1, *reinterpret_cast<__half2*>(&u1));
        }
        float mx0 = fmaxf(__low2float(mh0), __high2float(mh0));
        float mx1 = fmaxf(__low2float(mh1), __high2float(mh1));

        float mn0 = fmaxf(m0, mx0), mn1 = fmaxf(m1, mx1);
        float a0 = exp2f(m0 - mn0), a1 = exp2f(m1 - mn1);
        m0 = mn0; m1 = mn1;
        __half2 sub0 = __float2half2_rn(mn0);
        __half2 sub1 = __float2half2_rn(mn1);
        uint32_t su0 = *reinterpret_cast<uint32_t*>(&sub0);
        uint32_t su1 = *reinterpret_cast<uint32_t*>(&sub1);

        uint32_t ph[4][4];
#pragma unroll
        for (int g = 0; g < 4; ++g) {
#pragma unroll
            for (int hf = 0; hf < 2; ++hf) {
                int tile = g * 2 + hf;
                __half2 d0 = __hsub2(*reinterpret_cast<__half2*>(&sc[tile][0]),
                                     *reinterpret_cast<__half2*>(&su0));
                __half2 d1 = __hsub2(*reinterpret_cast<__half2*>(&sc[tile][1]),
                                     *reinterpret_cast<__half2*>(&su1));
                ph[g][hf * 2]     = ex2h2(*reinterpret_cast<uint32_t*>(&d0));
                ph[g][hf * 2 + 1] = ex2h2(*reinterpret_cast<uint32_t*>(&d1));
            }
        }

        // rescale O and l, then l += row-sum(P) via ones-mma
#pragma unroll
        for (int n8 = 0; n8 < 8; ++n8) {
            o[n8][0] *= a0; o[n8][1] *= a0;
            o[n8][2] *= a1; o[n8][3] *= a1;
        }
        lacc[0] *= a0; lacc[1] *= a0;
        lacc[2] *= a1; lacc[3] *= a1;
#pragma unroll
        for (int g = 0; g < 4; ++g)
            mma_f16(lacc, ph[g], ONES);

        // ---- O += P V : 1 pass (V already resident) ----
#pragma unroll
        for (int g = 0; g < 4; ++g) {
            int krow = g * 16 + ((L >> 3) & 1) * 8 + (L & 7);
            uint32_t vh[4][4];
#pragma unroll
            for (int nt = 0; nt < 4; ++nt) {
                int dcol = nt * 16 + (L >> 4) * 8;
                ldm_x4_t(vh[nt], vbase + (uint32_t)((krow * AP + dcol) * 2));
            }
#pragma unroll
            for (int n8 = 0; n8 < 8; ++n8)
                mma_f16(o[n8], ph[g], &vh[n8 >> 1][(n8 & 1) * 2]);
        }
    }

    // ---- normalize + store single fp16 ----
    float inv0 = 1.f / lacc[0], inv1 = 1.f / lacc[2];
#pragma unroll
    for (int n8 = 0; n8 < 8; ++n8) {
        int d = n8 * 8 + ccol;
        uint32_t h0 = pack2(o[n8][0] * inv0, o[n8][1] * inv0);
        uint32_t h1 = pack2(o[n8][2] * inv1, o[n8][3] * inv1);
        size_t g0 = (size_t)(b * SS + i0 + w * 16 + crow) * CC + h * DK + d;
        size_t g1 = g0 + (size_t)8 * CC;
        *reinterpret_cast<uint32_t*>(g_ao_h + g0) = h0;
        *reinterpret_cast<uint32_t*>(g_ao_h + g1) = h1;
    }
}

// ---------------------------------------------------------------------------
extern "C" void kernel_launch(void* const* d_in, const int* in_sizes, int n_in,
                              void* d_out, int out_size) {
    const float* x = (const float*)d_in[0];
    const float* gn_w = (const float*)d_in[1];
    const float* gn_b = (const float*)d_in[2];
    const float* proj_w = (const float*)d_in[3];
    const float* proj_b = (const float*)d_in[4];
    const float* out_w = (const float*)d_in[5];
    const float* out_b = (const float*)d_in[6];
    float* out = (float*)d_out;

    __half *d_hh, *d_qh, *d_aoh, *d_pwh, *d_owh;
    cudaGetSymbolAddress((void**)&d_hh, g_h_h);
    cudaGetSymbolAddress((void**)&d_qh, g_qkv_h);
    cudaGetSymbolAddress((void**)&d_aoh, g_ao_h);
    cudaGetSymbolAddress((void**)&d_pwh, g_pw_h);
    cudaGetSymbolAddress((void**)&d_owh, g_ow_h);

    cudaFuncSetAttribute(mma_gemm<0>, cudaFuncAttributeMaxDynamicSharedMemorySize, GEMM_SMEM);
    cudaFuncSetAttribute(mma_gemm<1>, cudaFuncAttributeMaxDynamicSharedMemorySize, GEMM_SMEM);
    cudaFuncSetAttribute(attn_mma, cudaFuncAttributeMaxDynamicSharedMemorySize, ATT_SMEM);

    const int n1 = QKVC * CC / 4, n2 = CC * CC / 4;
    cvt_w2<<<(n1 + n2 + 255) / 256, 256>>>(proj_w, d_pwh, n1, out_w, d_owh, n2);
    gn_kernel<<<BB * NG, 256>>>(x, gn_w, gn_b);

    mma_gemm<0><<<dim3(QKVC / 64, BB * SS / 128), 256, GEMM_SMEM>>>(
        d_hh, d_pwh, proj_b, nullptr, nullptr, d_qh, QKVC);

    attn_mma<<<dim3(SS / 128, BB * NH), 256, ATT_SMEM>>>();

    mma_gemm<1><<<dim3(CC / 64, BB * SS / 128), 256, GEMM_SMEM>>>(
        d_aoh, d_owh, out_b, x, out, nullptr, CC);
}